// round 8
// baseline (speedup 1.0000x reference)
#include <cuda_runtime.h>
#include <cuda_bf16.h>
#include <cuda_fp16.h>
#include <math.h>
#include <stdint.h>

#define N_NODES 50000
#define N_EDGES 250000
#define DIM     256
#define NRELS   400
#define HROW2   128     // h row: 128 half2 (256 vals) = 512 B
#define SROW2   130     // spec row: 129 complex bins as half2 + 1 pad = 520 B
#define LN_EPS  1e-5f

// ------------------------- scratch (device globals) --------------------------
__device__ float   g_h  [(size_t)N_NODES * DIM];     // fp32 h (residual path)
__device__ float   g_Z  [(size_t)N_NODES * DIM];     // gemm out + bias + resid
__device__ __nv_bfloat16 g_HChi[(size_t)N_NODES * DIM];  // HC split hi
__device__ __nv_bfloat16 g_HClo[(size_t)N_NODES * DIM];  // HC split lo
__device__ __nv_bfloat16 g_Whi [3 * DIM * DIM];          // Wn1,Wn2,Wr2 hi
__device__ __nv_bfloat16 g_Wlo [3 * DIM * DIM];          // Wn1,Wn2,Wr2 lo
__device__ __nv_bfloat16 g_R2hi[NRELS * DIM];            // rel2 hi
__device__ __nv_bfloat16 g_R2lo[NRELS * DIM];            // rel2 lo
__device__ __half2 g_hH [(size_t)N_NODES * HROW2];   // h as fp16
__device__ __half2 g_HSH[(size_t)N_NODES * SROW2];   // rfft(h) as fp16
__device__ __half2 g_rH [2][(size_t)NRELS * HROW2];  // rel as fp16 (per layer)
__device__ __half2 g_RSH[2][(size_t)NRELS * SROW2];  // rfft(rel) as fp16
__device__ float   g_tw [7 * 64 * 2];
__device__ float   g_wt [129 * 2];
__device__ float   g_wi [129 * 2];
__device__ float   g_w  [6];
__device__ int     g_deg[N_NODES];
__device__ int     g_off[N_NODES + 1];
__device__ int     g_pos[N_NODES];
__device__ int2    g_edges[N_EDGES];                 // (src, et) sorted by dst

// ------------------------- small helpers -------------------------------------
__device__ __forceinline__ float2 cmulf(float2 a, float2 b) {
    return make_float2(a.x * b.x - a.y * b.y, a.x * b.y + a.y * b.x);
}
__device__ __forceinline__ float4 spec4(float4 a, float4 b) {
    return make_float4(a.x * b.x + a.y * b.y,
                       a.y * b.x - a.x * b.y,
                       a.z * b.z + a.w * b.w,
                       a.w * b.z - a.z * b.w);
}
__device__ __forceinline__ float4 add4(float4 a, float4 b) {
    return make_float4(a.x + b.x, a.y + b.y, a.z + b.z, a.w + b.w);
}
__device__ __forceinline__ float4 h2f4(uint2 raw) {
    float2 lo = __half22float2(*reinterpret_cast<__half2*>(&raw.x));
    float2 hi = __half22float2(*reinterpret_cast<__half2*>(&raw.y));
    return make_float4(lo.x, lo.y, hi.x, hi.y);
}
// T += h * (w0*r + w1)
__device__ __forceinline__ float4 tacc4(float4 h, float4 r, float w0, float w1,
                                        float4 T) {
    T.x = fmaf(h.x, fmaf(w0, r.x, w1), T.x);
    T.y = fmaf(h.y, fmaf(w0, r.y, w1), T.y);
    T.z = fmaf(h.z, fmaf(w0, r.z, w1), T.z);
    T.w = fmaf(h.w, fmaf(w0, r.w, w1), T.w);
    return T;
}

// ------------------------- fused setup kernel --------------------------------
__global__ void setup_kernel(float* tw, float* wt, float* wi,
                             const float* __restrict__ cw1,
                             const float* __restrict__ cw2, float* w,
                             int* deg) {
    int i = blockIdx.x * blockDim.x + threadIdx.x;
    if (i < 7 * 64) {
        int s = i >> 6, j = i & 63;
        int l = 64 >> s;
        float2 v = make_float2(0.f, 0.f);
        if (j < l) {
            double a = (double)j / (double)l;
            v = make_float2((float)cospi(a), (float)sinpi(a));
        }
        reinterpret_cast<float2*>(tw)[i] = v;
    }
    if (i < 129) {
        double a = (double)i / 128.0;
        reinterpret_cast<float2*>(wt)[i] = make_float2((float)cospi(a), (float)(-sinpi(a)));
        reinterpret_cast<float2*>(wi)[i] = make_float2((float)cospi(a), (float)( sinpi(a)));
    }
    if (i == 0) {
        for (int L = 0; L < 2; L++) {
            const float* c = (L == 0) ? cw1 : cw2;
            float m = fmaxf(c[0], fmaxf(c[1], c[2]));
            float e0 = expf(c[0] - m), e1 = expf(c[1] - m), e2 = expf(c[2] - m);
            float s = e0 + e1 + e2;
            w[L * 3 + 0] = e0 / s; w[L * 3 + 1] = e1 / s; w[L * 3 + 2] = e2 / s;
        }
    }
    if (i < N_NODES) deg[i] = 0;
}

// ------------------------- fp32 -> bf16 hi/lo split (all tensors, 1 launch) --
__global__ void split_all_kernel(const float* __restrict__ Wn1,
                                 const float* __restrict__ Wn2,
                                 const float* __restrict__ Wr2,
                                 const float* __restrict__ rel2,
                                 __nv_bfloat16* __restrict__ Whi,
                                 __nv_bfloat16* __restrict__ Wlo,
                                 __nv_bfloat16* __restrict__ R2hi,
                                 __nv_bfloat16* __restrict__ R2lo) {
    const int W4 = DIM * DIM / 4;
    const int R4 = NRELS * DIM / 4;
    int i = blockIdx.x * blockDim.x + threadIdx.x;
    const float* src; __nv_bfloat16 *hi, *lo; int idx;
    if (i < W4)            { src = Wn1;  hi = Whi;                 lo = Wlo;                 idx = i; }
    else if (i < 2 * W4)   { src = Wn2;  hi = Whi + DIM * DIM;     lo = Wlo + DIM * DIM;     idx = i - W4; }
    else if (i < 3 * W4)   { src = Wr2;  hi = Whi + 2 * DIM * DIM; lo = Wlo + 2 * DIM * DIM; idx = i - 2 * W4; }
    else if (i < 3 * W4 + R4) { src = rel2; hi = R2hi;             lo = R2lo;                idx = i - 3 * W4; }
    else return;
    float4 v = reinterpret_cast<const float4*>(src)[idx];
    float f[4] = {v.x, v.y, v.z, v.w};
    __nv_bfloat16 h[4], l[4];
#pragma unroll
    for (int j = 0; j < 4; j++) {
        h[j] = __float2bfloat16(f[j]);
        l[j] = __float2bfloat16(f[j] - __bfloat162float(h[j]));
    }
    reinterpret_cast<uint2*>(hi)[idx] = *reinterpret_cast<uint2*>(h);
    reinterpret_cast<uint2*>(lo)[idx] = *reinterpret_cast<uint2*>(l);
}

// ------------------------- edge sorting (counting sort by dst) ---------------
__global__ void hist_kernel(const int* __restrict__ dst, int* deg) {
    int e = blockIdx.x * blockDim.x + threadIdx.x;
    if (e < N_EDGES) atomicAdd(&deg[dst[e]], 1);
}
__global__ __launch_bounds__(1024)
void scan_kernel(const int* __restrict__ deg, int* off, int* pos) {
    __shared__ int ps[1024];
    int t = threadIdx.x;
    const int CH = (N_NODES + 1023) / 1024;
    int b0 = t * CH, b1 = min(b0 + CH, N_NODES);
    int s = 0;
    for (int i = b0; i < b1; i++) s += deg[i];
    ps[t] = s;
    __syncthreads();
    for (int o = 1; o < 1024; o <<= 1) {
        int u = (t >= o) ? ps[t - o] : 0;
        __syncthreads();
        ps[t] += u;
        __syncthreads();
    }
    int run = ps[t] - s;
    for (int i = b0; i < b1; i++) {
        off[i] = run; pos[i] = run; run += deg[i];
    }
    if (t == 1023) off[N_NODES] = ps[1023];
}
__global__ void scatter_kernel(const int* __restrict__ src,
                               const int* __restrict__ dst,
                               const int* __restrict__ et,
                               int* pos, int2* edges) {
    int e = blockIdx.x * blockDim.x + threadIdx.x;
    if (e >= N_EDGES) return;
    int p = atomicAdd(&pos[dst[e]], 1);
    edges[p] = make_int2(src[e], et[e]);
}

// ------------------------- 128-pt Stockham FFT (64 threads/row) --------------
__device__ __forceinline__ void fft128(float2* b0, float2* b1, int t, float sgn,
                                       const float2* __restrict__ tw) {
    float2* src = b0;
    float2* dst = b1;
#pragma unroll
    for (int s = 0; s < 7; s++) {
        int m = 1 << s;
        int j = t >> s;
        float2 w = tw[(s << 6) + j];
        w.y *= sgn;
        float2 c0 = src[t];
        float2 c1 = src[t + 64];
        float2 sum = make_float2(c0.x + c1.x, c0.y + c1.y);
        float2 d   = make_float2(c0.x - c1.x, c0.y - c1.y);
        int idx = (t & (m - 1)) | ((t >> s) << (s + 1));
        dst[idx]     = sum;
        dst[idx + m] = cmulf(d, w);
        float2* tmp = src; src = dst; dst = tmp;
        __syncthreads();
    }
}

// forward untangle -> fp16 spectrum row
__device__ __forceinline__ void untangle_store_h(
    float2* Z, __half2* Srow, int t, const float2* __restrict__ wt) {
#pragma unroll
    for (int u = 0; u < 2; u++) {
        int k = t + 64 * u;
        float2 Zk = Z[k];
        float2 Zm = Z[(128 - k) & 127];
        float2 Ze = make_float2(0.5f * (Zk.x + Zm.x), 0.5f * (Zk.y - Zm.y));
        float2 d  = make_float2(Zk.x - Zm.x, Zk.y + Zm.y);
        float2 Zo = make_float2(0.5f * d.y, -0.5f * d.x);
        float2 W  = wt[k];
        float2 H  = make_float2(Ze.x + W.x * Zo.x - W.y * Zo.y,
                                Ze.y + W.x * Zo.y + W.y * Zo.x);
        Srow[k] = __float22half2_rn(H);
    }
    if (t == 0) {
        float2 Z0 = Z[0];
        Srow[128] = __float22half2_rn(make_float2(Z0.x - Z0.y, 0.f));
    }
}

// ------------------------- gather + forward rfft (fused) ---------------------
__global__ __launch_bounds__(256)
void gather_fft_kernel(const int* __restrict__ x, const float* __restrict__ emb,
                       float* __restrict__ h, __half2* __restrict__ hH,
                       __half2* __restrict__ SH,
                       const float2* __restrict__ tw, const float2* __restrict__ wt) {
    __shared__ float2 buf[4][2][128];
    int g = threadIdx.x >> 6, t = threadIdx.x & 63;
    int row = (blockIdx.x << 2) + g;
    float4 v = reinterpret_cast<const float4*>(emb + (size_t)x[row] * DIM)[t];
    reinterpret_cast<float4*>(h + (size_t)row * DIM)[t] = v;
    __half2 p0 = __float22half2_rn(make_float2(v.x, v.y));
    __half2 p1 = __float22half2_rn(make_float2(v.z, v.w));
    *reinterpret_cast<uint2*>(hH + (size_t)row * HROW2 + 2 * t) =
        make_uint2(*reinterpret_cast<uint32_t*>(&p0), *reinterpret_cast<uint32_t*>(&p1));
    buf[g][0][2 * t]     = make_float2(v.x, v.y);
    buf[g][0][2 * t + 1] = make_float2(v.z, v.w);
    __syncthreads();
    fft128(buf[g][0], buf[g][1], t, -1.f, tw);
    untangle_store_h(buf[g][1], SH + (size_t)row * SROW2, t, wt);
}

// ------------------------- rel table fft -> fp16 copies ----------------------
__global__ __launch_bounds__(256)
void rel_fft_kernel(const float* __restrict__ rel, __half2* __restrict__ rH,
                    __half2* __restrict__ RSH,
                    const float2* __restrict__ tw, const float2* __restrict__ wt) {
    __shared__ float2 buf[4][2][128];
    int g = threadIdx.x >> 6, t = threadIdx.x & 63;
    int row = (blockIdx.x << 2) + g;
    float4 v = reinterpret_cast<const float4*>(rel + (size_t)row * DIM)[t];
    __half2 p0 = __float22half2_rn(make_float2(v.x, v.y));
    __half2 p1 = __float22half2_rn(make_float2(v.z, v.w));
    *reinterpret_cast<uint2*>(rH + (size_t)row * HROW2 + 2 * t) =
        make_uint2(*reinterpret_cast<uint32_t*>(&p0), *reinterpret_cast<uint32_t*>(&p1));
    buf[g][0][2 * t]     = make_float2(v.x, v.y);
    buf[g][0][2 * t + 1] = make_float2(v.z, v.w);
    __syncthreads();
    fft128(buf[g][0], buf[g][1], t, -1.f, tw);
    untangle_store_h(buf[g][1], RSH + (size_t)row * SROW2, t, wt);
}

// --------------- aggregation + inverse rfft (shfl-broadcast edges, x4 MLP) ---
__global__ __launch_bounds__(256)
void agg_inv_kernel(const int2* __restrict__ edges, const int* __restrict__ off,
                    const __half2* __restrict__ hH,  const __half2* __restrict__ HSH,
                    const __half2* __restrict__ rH, const __half2* __restrict__ RSH,
                    const float* __restrict__ w, int wofs,
                    __nv_bfloat16* __restrict__ HChi,
                    __nv_bfloat16* __restrict__ HClo,
                    const float2* __restrict__ tw, const float2* __restrict__ wi) {
    __shared__ float2 buf[4][2][128];
    __shared__ float2 sA[4][132];
    int g = threadIdx.x >> 6, t = threadIdx.x & 63;
    int lane = t & 31;
    int v = (blockIdx.x << 2) + g;
    float w0 = w[wofs + 0], w1 = w[wofs + 1], w2 = w[wofs + 2];

    const uint2* hHu  = reinterpret_cast<const uint2*>(hH);
    const uint2* rHu  = reinterpret_cast<const uint2*>(rH);
    const uint2* HSHu = reinterpret_cast<const uint2*>(HSH);
    const uint2* RSHu = reinterpret_cast<const uint2*>(RSH);

    // self-loop (rel type 0)
    float4 hv0 = h2f4(hHu[(size_t)v * 64 + t]);
    float4 rv0 = h2f4(rHu[t]);
    float4 T  = tacc4(hv0, rv0, w0, w1, make_float4(0.f, 0.f, 0.f, 0.f));
    float4 Rs = rv0;
    float4 F  = spec4(h2f4(HSHu[(size_t)v * 65 + t]), h2f4(RSHu[t]));
    float2 Ft = make_float2(0.f, 0.f);
    if (t == 0) {
        float2 a = __half22float2(HSH[(size_t)v * SROW2 + 128]);
        float2 b = __half22float2(RSH[128]);
        Ft = make_float2(a.x * b.x + a.y * b.y, a.y * b.x - a.x * b.y);
    }

    int e0i = off[v], e1i = off[v + 1];
    for (int base = e0i; base < e1i; base += 32) {
        int n = min(32, e1i - base);
        // lane-parallel preload of up to 32 edge descriptors (1 latency wave)
        int2 edl = edges[base + (lane < n ? lane : 0)];
        int j = 0;
        for (; j + 4 <= n; j += 4) {
            int s0 = __shfl_sync(0xffffffffu, edl.x, j + 0);
            int y0 = __shfl_sync(0xffffffffu, edl.y, j + 0);
            int s1 = __shfl_sync(0xffffffffu, edl.x, j + 1);
            int y1 = __shfl_sync(0xffffffffu, edl.y, j + 1);
            int s2 = __shfl_sync(0xffffffffu, edl.x, j + 2);
            int y2 = __shfl_sync(0xffffffffu, edl.y, j + 2);
            int s3 = __shfl_sync(0xffffffffu, edl.x, j + 3);
            int y3 = __shfl_sync(0xffffffffu, edl.y, j + 3);
            // issue all 16 gathers before consuming (4-edge MLP)
            uint2 h0 = hHu [(size_t)s0 * 64 + t];
            uint2 r0 = rHu [(size_t)y0 * 64 + t];
            uint2 f0 = HSHu[(size_t)s0 * 65 + t];
            uint2 g0 = RSHu[(size_t)y0 * 65 + t];
            uint2 h1 = hHu [(size_t)s1 * 64 + t];
            uint2 r1 = rHu [(size_t)y1 * 64 + t];
            uint2 f1 = HSHu[(size_t)s1 * 65 + t];
            uint2 g1 = RSHu[(size_t)y1 * 65 + t];
            uint2 h2v = hHu [(size_t)s2 * 64 + t];
            uint2 r2v = rHu [(size_t)y2 * 64 + t];
            uint2 f2v = HSHu[(size_t)s2 * 65 + t];
            uint2 g2v = RSHu[(size_t)y2 * 65 + t];
            uint2 h3 = hHu [(size_t)s3 * 64 + t];
            uint2 r3 = rHu [(size_t)y3 * 64 + t];
            uint2 f3 = HSHu[(size_t)s3 * 65 + t];
            uint2 g3 = RSHu[(size_t)y3 * 65 + t];
            float4 rf0 = h2f4(r0), rf1 = h2f4(r1), rf2 = h2f4(r2v), rf3 = h2f4(r3);
            T = tacc4(h2f4(h0), rf0, w0, w1, T);  Rs = add4(Rs, rf0);
            F = add4(F, spec4(h2f4(f0), h2f4(g0)));
            T = tacc4(h2f4(h1), rf1, w0, w1, T);  Rs = add4(Rs, rf1);
            F = add4(F, spec4(h2f4(f1), h2f4(g1)));
            T = tacc4(h2f4(h2v), rf2, w0, w1, T); Rs = add4(Rs, rf2);
            F = add4(F, spec4(h2f4(f2v), h2f4(g2v)));
            T = tacc4(h2f4(h3), rf3, w0, w1, T);  Rs = add4(Rs, rf3);
            F = add4(F, spec4(h2f4(f3), h2f4(g3)));
            if (t == 0) {
                float2 a0 = __half22float2(HSH[(size_t)s0 * SROW2 + 128]);
                float2 b0 = __half22float2(RSH[(size_t)y0 * SROW2 + 128]);
                float2 a1 = __half22float2(HSH[(size_t)s1 * SROW2 + 128]);
                float2 b1 = __half22float2(RSH[(size_t)y1 * SROW2 + 128]);
                float2 a2 = __half22float2(HSH[(size_t)s2 * SROW2 + 128]);
                float2 b2 = __half22float2(RSH[(size_t)y2 * SROW2 + 128]);
                float2 a3 = __half22float2(HSH[(size_t)s3 * SROW2 + 128]);
                float2 b3 = __half22float2(RSH[(size_t)y3 * SROW2 + 128]);
                Ft.x += a0.x * b0.x + a0.y * b0.y + a1.x * b1.x + a1.y * b1.y
                      + a2.x * b2.x + a2.y * b2.y + a3.x * b3.x + a3.y * b3.y;
                Ft.y += a0.y * b0.x - a0.x * b0.y + a1.y * b1.x - a1.x * b1.y
                      + a2.y * b2.x - a2.x * b2.y + a3.y * b3.x - a3.x * b3.y;
            }
        }
        for (; j < n; j++) {
            int sx = __shfl_sync(0xffffffffu, edl.x, j);
            int yy = __shfl_sync(0xffffffffu, edl.y, j);
            uint2 hh = hHu [(size_t)sx * 64 + t];
            uint2 rr = rHu [(size_t)yy * 64 + t];
            uint2 ff = HSHu[(size_t)sx * 65 + t];
            uint2 gg = RSHu[(size_t)yy * 65 + t];
            float4 rf = h2f4(rr);
            T = tacc4(h2f4(hh), rf, w0, w1, T);
            Rs = add4(Rs, rf);
            F = add4(F, spec4(h2f4(ff), h2f4(gg)));
            if (t == 0) {
                float2 a = __half22float2(HSH[(size_t)sx * SROW2 + 128]);
                float2 b = __half22float2(RSH[(size_t)yy * SROW2 + 128]);
                Ft.x += a.x * b.x + a.y * b.y;
                Ft.y += a.y * b.x - a.x * b.y;
            }
        }
    }

    // stage spectrum (scaled by w2) into shared
    sA[g][2 * t]     = make_float2(w2 * F.x, w2 * F.y);
    sA[g][2 * t + 1] = make_float2(w2 * F.z, w2 * F.w);
    if (t == 0) sA[g][128] = make_float2(w2 * Ft.x, w2 * Ft.y);
    __syncthreads();

    // inverse untangle -> packed complex
#pragma unroll
    for (int u = 0; u < 2; u++) {
        int k = t + 64 * u;
        float2 Ak = sA[g][k], Am = sA[g][128 - k];
        float2 Ze = make_float2(0.5f * (Ak.x + Am.x), 0.5f * (Ak.y - Am.y));
        float2 hd = make_float2(0.5f * (Ak.x - Am.x), 0.5f * (Ak.y + Am.y));
        float2 Zo = cmulf(wi[k], hd);
        buf[g][0][k] = make_float2(Ze.x - Zo.y, Ze.y + Zo.x);
    }
    __syncthreads();
    fft128(buf[g][0], buf[g][1], t, +1.f, tw);
    float2 z0 = buf[g][1][2 * t], z1 = buf[g][1][2 * t + 1];
    const float inv = 1.f / 128.f;
    float o[4];
    o[0] = fmaf(w1, Rs.x, T.x) + z0.x * inv;
    o[1] = fmaf(w1, Rs.y, T.y) + z0.y * inv;
    o[2] = fmaf(w1, Rs.z, T.z) + z1.x * inv;
    o[3] = fmaf(w1, Rs.w, T.w) + z1.y * inv;
    __nv_bfloat16 hi[4], lo[4];
#pragma unroll
    for (int j = 0; j < 4; j++) {
        hi[j] = __float2bfloat16(o[j]);
        lo[j] = __float2bfloat16(o[j] - __bfloat162float(hi[j]));
    }
    reinterpret_cast<uint2*>(HChi + (size_t)v * DIM)[t] = *reinterpret_cast<uint2*>(hi);
    reinterpret_cast<uint2*>(HClo + (size_t)v * DIM)[t] = *reinterpret_cast<uint2*>(lo);
}

// --------- LN + ReLU (input Z already = gemm+bias+resid), optional fft -------
template<bool DO_FFT>
__global__ __launch_bounds__(256)
void epilogue_fft_kernel(const float* __restrict__ Z,
                         const float* __restrict__ gamma,
                         const float* __restrict__ beta,
                         float* __restrict__ h_out,
                         __half2* __restrict__ hH,
                         __half2* __restrict__ SH,
                         const float2* __restrict__ tw,
                         const float2* __restrict__ wt) {
    __shared__ float2 buf[4][2][128];
    __shared__ float sred[4][2];
    int g = threadIdx.x >> 6, t = threadIdx.x & 63;
    int wsub = t >> 5;
    int v = (blockIdx.x << 2) + g;

    float4 z = reinterpret_cast<const float4*>(Z + (size_t)v * DIM)[t];
    float s = z.x + z.y + z.z + z.w;
#pragma unroll
    for (int ofs = 16; ofs; ofs >>= 1) s += __shfl_xor_sync(0xffffffffu, s, ofs);
    if ((t & 31) == 0) sred[g][wsub] = s;
    __syncthreads();
    float mu = (sred[g][0] + sred[g][1]) * (1.f / DIM);
    __syncthreads();
    float4 zc = make_float4(z.x - mu, z.y - mu, z.z - mu, z.w - mu);
    float vv = zc.x * zc.x + zc.y * zc.y + zc.z * zc.z + zc.w * zc.w;
#pragma unroll
    for (int ofs = 16; ofs; ofs >>= 1) vv += __shfl_xor_sync(0xffffffffu, vv, ofs);
    if ((t & 31) == 0) sred[g][wsub] = vv;
    __syncthreads();
    float rstd = rsqrtf((sred[g][0] + sred[g][1]) * (1.f / DIM) + LN_EPS);
    float4 gm = reinterpret_cast<const float4*>(gamma)[t];
    float4 bt = reinterpret_cast<const float4*>(beta)[t];
    float4 y = make_float4(fmaxf(zc.x * rstd * gm.x + bt.x, 0.f),
                           fmaxf(zc.y * rstd * gm.y + bt.y, 0.f),
                           fmaxf(zc.z * rstd * gm.z + bt.z, 0.f),
                           fmaxf(zc.w * rstd * gm.w + bt.w, 0.f));
    reinterpret_cast<float4*>(h_out + (size_t)v * DIM)[t] = y;
    if (DO_FFT) {
        __half2 p0 = __float22half2_rn(make_float2(y.x, y.y));
        __half2 p1 = __float22half2_rn(make_float2(y.z, y.w));
        *reinterpret_cast<uint2*>(hH + (size_t)v * HROW2 + 2 * t) =
            make_uint2(*reinterpret_cast<uint32_t*>(&p0), *reinterpret_cast<uint32_t*>(&p1));
        buf[g][0][2 * t]     = make_float2(y.x, y.y);
        buf[g][0][2 * t + 1] = make_float2(y.z, y.w);
        __syncthreads();
        fft128(buf[g][0], buf[g][1], t, -1.f, tw);
        untangle_store_h(buf[g][1], SH + (size_t)v * SROW2, t, wt);
    }
}

// ------------------------- bf16x3 GEMM with pre-split operands ---------------
#define GBK 32
#define GPAD 8
#define GLDW (GBK + GPAD)

__device__ __forceinline__ void mma_bf16(float* d,
    uint32_t a0, uint32_t a1, uint32_t a2, uint32_t a3,
    uint32_t b0, uint32_t b1) {
    asm volatile(
        "mma.sync.aligned.m16n8k16.row.col.f32.bf16.bf16.f32 "
        "{%0,%1,%2,%3}, {%4,%5,%6,%7}, {%8,%9}, {%0,%1,%2,%3};"
        : "+f"(d[0]), "+f"(d[1]), "+f"(d[2]), "+f"(d[3])
        : "r"(a0), "r"(a1), "r"(a2), "r"(a3), "r"(b0), "r"(b1));
}

template<bool BIAS, bool RESID>
__global__ __launch_bounds__(256)
void bf16s_gemm(const __nv_bfloat16* __restrict__ Ahi,
                const __nv_bfloat16* __restrict__ Alo,
                const __nv_bfloat16* __restrict__ Bhi,
                const __nv_bfloat16* __restrict__ Blo,
                float* __restrict__ C, const float* __restrict__ bias,
                const float* __restrict__ Hres,
                int M, int N, int K) {
    __shared__ __align__(16) __nv_bfloat16 Ah[128 * GLDW];
    __shared__ __align__(16) __nv_bfloat16 Al[128 * GLDW];
    __shared__ __align__(16) __nv_bfloat16 Bh[128 * GLDW];
    __shared__ __align__(16) __nv_bfloat16 Bl[128 * GLDW];

    int tid = threadIdx.x;
    int lane = tid & 31, wid = tid >> 5;
    int wm = wid & 1, wn = wid >> 1;
    int r = lane >> 2, cq = lane & 3;
    int bm = blockIdx.y * 128, bn = blockIdx.x * 128;

    float acc[4][4][4];
#pragma unroll
    for (int a = 0; a < 4; a++)
#pragma unroll
        for (int b = 0; b < 4; b++)
#pragma unroll
            for (int c = 0; c < 4; c++) acc[a][b][c] = 0.f;

    int lrow[2], lcol[2];
#pragma unroll
    for (int j = 0; j < 2; j++) {
        int idx = tid + 256 * j;
        lrow[j] = idx >> 2; lcol[j] = (idx & 3) << 3;
    }

    uint4 rah[2], ral[2], rbh[2], rbl[2];
    const uint4 z4 = make_uint4(0, 0, 0, 0);

    auto load_tile = [&](int k0) {
#pragma unroll
        for (int j = 0; j < 2; j++) {
            size_t ao = (size_t)(bm + lrow[j]) * K + k0 + lcol[j];
            size_t bo = (size_t)(bn + lrow[j]) * K + k0 + lcol[j];
            bool av = (bm + lrow[j] < M), bv = (bn + lrow[j] < N);
            rah[j] = av ? *reinterpret_cast<const uint4*>(Ahi + ao) : z4;
            ral[j] = av ? *reinterpret_cast<const uint4*>(Alo + ao) : z4;
            rbh[j] = bv ? *reinterpret_cast<const uint4*>(Bhi + bo) : z4;
            rbl[j] = bv ? *reinterpret_cast<const uint4*>(Blo + bo) : z4;
        }
    };
    auto stage_tile = [&]() {
#pragma unroll
        for (int j = 0; j < 2; j++) {
            int so = lrow[j] * GLDW + lcol[j];
            *reinterpret_cast<uint4*>(&Ah[so]) = rah[j];
            *reinterpret_cast<uint4*>(&Al[so]) = ral[j];
            *reinterpret_cast<uint4*>(&Bh[so]) = rbh[j];
            *reinterpret_cast<uint4*>(&Bl[so]) = rbl[j];
        }
    };

    load_tile(0);
    for (int k0 = 0; k0 < K; k0 += GBK) {
        stage_tile();
        __syncthreads();
        if (k0 + GBK < K) load_tile(k0 + GBK);

#pragma unroll
        for (int ks = 0; ks < 2; ks++) {
            int kb = ks * 16 + cq * 2;
            uint32_t bhf[4][2], blf[4][2];
#pragma unroll
            for (int nf = 0; nf < 4; nf++) {
                int col = wn * 32 + nf * 8 + r;
                bhf[nf][0] = *reinterpret_cast<const uint32_t*>(&Bh[col * GLDW + kb]);
                bhf[nf][1] = *reinterpret_cast<const uint32_t*>(&Bh[col * GLDW + kb + 8]);
                blf[nf][0] = *reinterpret_cast<const uint32_t*>(&Bl[col * GLDW + kb]);
                blf[nf][1] = *reinterpret_cast<const uint32_t*>(&Bl[col * GLDW + kb + 8]);
            }
#pragma unroll
            for (int mf = 0; mf < 4; mf++) {
                int row = wm * 64 + mf * 16 + r;
                uint32_t a0 = *reinterpret_cast<const uint32_t*>(&Ah[row * GLDW + kb]);
                uint32_t a1 = *reinterpret_cast<const uint32_t*>(&Ah[(row + 8) * GLDW + kb]);
                uint32_t a2 = *reinterpret_cast<const uint32_t*>(&Ah[row * GLDW + kb + 8]);
                uint32_t a3 = *reinterpret_cast<const uint32_t*>(&Ah[(row + 8) * GLDW + kb + 8]);
                uint32_t l0 = *reinterpret_cast<const uint32_t*>(&Al[row * GLDW + kb]);
                uint32_t l1 = *reinterpret_cast<const uint32_t*>(&Al[(row + 8) * GLDW + kb]);
                uint32_t l2 = *reinterpret_cast<const uint32_t*>(&Al[row * GLDW + kb + 8]);
                uint32_t l3 = *reinterpret_cast<const uint32_t*>(&Al[(row + 8) * GLDW + kb + 8]);
#pragma unroll
                for (int nf = 0; nf < 4; nf++) {
                    mma_bf16(acc[mf][nf], a0, a1, a2, a3, bhf[nf][0], bhf[nf][1]);
                    mma_bf16(acc[mf][nf], a0, a1, a2, a3, blf[nf][0], blf[nf][1]);
                    mma_bf16(acc[mf][nf], l0, l1, l2, l3, bhf[nf][0], bhf[nf][1]);
                }
            }
        }
        __syncthreads();
    }

#pragma unroll
    for (int mf = 0; mf < 4; mf++) {
        int row0 = bm + wm * 64 + mf * 16 + r;
#pragma unroll
        for (int nf = 0; nf < 4; nf++) {
            int col = bn + wn * 32 + nf * 8 + cq * 2;
            float bx = 0.f, by = 0.f;
            if (BIAS) { bx = bias[col]; by = bias[col + 1]; }
            if (row0 < M) {
                float rx = bx, ry = by;
                if (RESID) {
                    float2 hv = *reinterpret_cast<const float2*>(
                        Hres + (size_t)row0 * N + col);
                    rx += hv.x; ry += hv.y;
                }
                *reinterpret_cast<float2*>(C + (size_t)row0 * N + col) =
                    make_float2(acc[mf][nf][0] + rx, acc[mf][nf][1] + ry);
            }
            if (row0 + 8 < M) {
                float rx = bx, ry = by;
                if (RESID) {
                    float2 hv = *reinterpret_cast<const float2*>(
                        Hres + (size_t)(row0 + 8) * N + col);
                    rx += hv.x; ry += hv.y;
                }
                *reinterpret_cast<float2*>(C + (size_t)(row0 + 8) * N + col) =
                    make_float2(acc[mf][nf][2] + rx, acc[mf][nf][3] + ry);
            }
        }
    }
}

// ------------------------- launch --------------------------------------------
extern "C" void kernel_launch(void* const* d_in, const int* in_sizes, int n_in,
                              void* d_out, int out_size) {
    (void)in_sizes; (void)n_in; (void)out_size;
    const int*   x    = (const int*)  d_in[0];
    const int*   eidx = (const int*)  d_in[1];
    const int*   et   = (const int*)  d_in[2];
    const float* emb  = (const float*)d_in[3];
    const float* rel1 = (const float*)d_in[4];
    const float* Wn1  = (const float*)d_in[7];
    const float* bn1  = (const float*)d_in[8];
    const float* cw1  = (const float*)d_in[9];
    const float* gm1  = (const float*)d_in[10];
    const float* bt1  = (const float*)d_in[11];
    const float* rel2 = (const float*)d_in[12];
    const float* Wr2  = (const float*)d_in[13];
    const float* br2  = (const float*)d_in[14];
    const float* Wn2  = (const float*)d_in[15];
    const float* bn2  = (const float*)d_in[16];
    const float* cw2  = (const float*)d_in[17];
    const float* gm2  = (const float*)d_in[18];
    const float* bt2  = (const float*)d_in[19];

    float* out_h    = (float*)d_out;
    float* out_rels = out_h + (size_t)N_NODES * DIM;
    const int* src = eidx;
    const int* dst = eidx + N_EDGES;

    float *pH, *pZ, *pTw, *pWt, *pWi, *pW;
    __nv_bfloat16 *pHChi, *pHClo, *pWhi, *pWlo, *pR2hi, *pR2lo;
    __half2 *pHH, *pHSH, *pRH, *pRSH;
    int *pDeg, *pOff, *pPos;
    int2* pEdges;
    cudaGetSymbolAddress((void**)&pH,    g_h);
    cudaGetSymbolAddress((void**)&pZ,    g_Z);
    cudaGetSymbolAddress((void**)&pHChi, g_HChi);
    cudaGetSymbolAddress((void**)&pHClo, g_HClo);
    cudaGetSymbolAddress((void**)&pWhi,  g_Whi);
    cudaGetSymbolAddress((void**)&pWlo,  g_Wlo);
    cudaGetSymbolAddress((void**)&pR2hi, g_R2hi);
    cudaGetSymbolAddress((void**)&pR2lo, g_R2lo);
    cudaGetSymbolAddress((void**)&pHH,   g_hH);
    cudaGetSymbolAddress((void**)&pHSH,  g_HSH);
    cudaGetSymbolAddress((void**)&pRH,   g_rH);
    cudaGetSymbolAddress((void**)&pRSH,  g_RSH);
    cudaGetSymbolAddress((void**)&pTw,   g_tw);
    cudaGetSymbolAddress((void**)&pWt,   g_wt);
    cudaGetSymbolAddress((void**)&pWi,   g_wi);
    cudaGetSymbolAddress((void**)&pW,    g_w);
    cudaGetSymbolAddress((void**)&pDeg,  g_deg);
    cudaGetSymbolAddress((void**)&pOff,  g_off);
    cudaGetSymbolAddress((void**)&pPos,  g_pos);
    cudaGetSymbolAddress((void**)&pEdges, g_edges);

    const float2* tw = (const float2*)pTw;
    const float2* wt = (const float2*)pWt;
    const float2* wi = (const float2*)pWi;
    __half2* pRH1  = pRH;
    __half2* pRH2  = pRH  + (size_t)NRELS * HROW2;
    __half2* pRSH1 = pRSH;
    __half2* pRSH2 = pRSH + (size_t)NRELS * SROW2;

    setup_kernel<<<(N_NODES + 255) / 256, 256>>>(pTw, pWt, pWi, cw1, cw2, pW, pDeg);
    hist_kernel<<<(N_EDGES + 255) / 256, 256>>>(dst, pDeg);
    scan_kernel<<<1, 1024>>>(pDeg, pOff, pPos);
    scatter_kernel<<<(N_EDGES + 255) / 256, 256>>>(src, dst, et, pPos, pEdges);

    const int SPLIT_N = 3 * (DIM * DIM / 4) + NRELS * DIM / 4;
    split_all_kernel<<<(SPLIT_N + 255) / 256, 256>>>(
        Wn1, Wn2, Wr2, rel2, pWhi, pWlo, pR2hi, pR2lo);

    rel_fft_kernel<<<NRELS / 4, 256>>>(rel1, pRH1, pRSH1, tw, wt);
    rel_fft_kernel<<<NRELS / 4, 256>>>(rel2, pRH2, pRSH2, tw, wt);

    gather_fft_kernel<<<N_NODES / 4, 256>>>(x, emb, pH, pHH, pHSH, tw, wt);

    for (int L = 0; L < 2; L++) {
        const float* bn = (L == 0) ? bn1 : bn2;
        const float* gm = (L == 0) ? gm1 : gm2;
        const float* bt = (L == 0) ? bt1 : bt2;
        __half2* rH  = (L == 0) ? pRH1  : pRH2;
        __half2* RSH = (L == 0) ? pRSH1 : pRSH2;
        const __nv_bfloat16* Whi = pWhi + (size_t)L * DIM * DIM;
        const __nv_bfloat16* Wlo = pWlo + (size_t)L * DIM * DIM;

        agg_inv_kernel<<<N_NODES / 4, 256>>>(pEdges, pOff, pHH, pHSH, rH, RSH,
                                             pW, 3 * L, pHChi, pHClo, tw, wi);
        bf16s_gemm<true, true><<<dim3(2, (N_NODES + 127) / 128), 256>>>(
            pHChi, pHClo, Whi, Wlo, pZ, bn, pH, N_NODES, DIM, DIM);
        if (L == 0) {
            epilogue_fft_kernel<true><<<N_NODES / 4, 256>>>(
                pZ, gm, bt, pH, pHH, pHSH, tw, wt);
        } else {
            epilogue_fft_kernel<false><<<N_NODES / 4, 256>>>(
                pZ, gm, bt, out_h, nullptr, nullptr, tw, wt);
        }
    }

    bf16s_gemm<true, false><<<dim3(2, (NRELS + 127) / 128), 256>>>(
        pR2hi, pR2lo, pWhi + 2 * DIM * DIM, pWlo + 2 * DIM * DIM,
        out_rels, br2, nullptr, NRELS, DIM, DIM);
}

// round 9
// speedup vs baseline: 1.0403x; 1.0403x over previous
#include <cuda_runtime.h>
#include <cuda_bf16.h>
#include <cuda_fp16.h>
#include <math.h>
#include <stdint.h>

#define N_NODES 50000
#define N_EDGES 250000
#define DIM     256
#define NRELS   400
#define HROW2   128     // h row: 128 half2 (256 vals) = 512 B
#define SROW2   130     // spec row: 129 complex bins as half2 + 1 pad = 520 B
#define LN_EPS  1e-5f
#define DBINS   64

// ------------------------- scratch (device globals) --------------------------
__device__ float   g_h  [(size_t)N_NODES * DIM];     // fp32 h (residual path)
__device__ float   g_Z  [(size_t)N_NODES * DIM];     // gemm out + bias + resid
__device__ __nv_bfloat16 g_HChi[(size_t)N_NODES * DIM];  // HC split hi
__device__ __nv_bfloat16 g_HClo[(size_t)N_NODES * DIM];  // HC split lo
__device__ __nv_bfloat16 g_Whi [3 * DIM * DIM];          // Wn1,Wn2,Wr2 hi
__device__ __nv_bfloat16 g_Wlo [3 * DIM * DIM];          // Wn1,Wn2,Wr2 lo
__device__ __nv_bfloat16 g_R2hi[NRELS * DIM];            // rel2 hi
__device__ __nv_bfloat16 g_R2lo[NRELS * DIM];            // rel2 lo
__device__ __half2 g_hH [(size_t)N_NODES * HROW2];   // h as fp16
__device__ __half2 g_HSH[(size_t)N_NODES * SROW2];   // rfft(h) as fp16
__device__ __half2 g_rH [2][(size_t)NRELS * HROW2];  // rel as fp16 (per layer)
__device__ __half2 g_RSH[2][(size_t)NRELS * SROW2];  // rfft(rel) as fp16
__device__ float   g_tw [7 * 64 * 2];
__device__ float   g_wt [129 * 2];
__device__ float   g_wi [129 * 2];
__device__ float   g_w  [6];
__device__ int     g_deg[N_NODES];
__device__ int     g_off[N_NODES + 1];
__device__ int     g_pos[N_NODES];
__device__ int     g_dh [DBINS];                     // degree-bin positions
__device__ int     g_perm[N_NODES];                  // nodes sorted by degree
__device__ int2    g_edges[N_EDGES];                 // (src, et) sorted by dst

// ------------------------- small helpers -------------------------------------
__device__ __forceinline__ float2 cmulf(float2 a, float2 b) {
    return make_float2(a.x * b.x - a.y * b.y, a.x * b.y + a.y * b.x);
}
__device__ __forceinline__ float4 spec4(float4 a, float4 b) {
    return make_float4(a.x * b.x + a.y * b.y,
                       a.y * b.x - a.x * b.y,
                       a.z * b.z + a.w * b.w,
                       a.w * b.z - a.z * b.w);
}
__device__ __forceinline__ float4 add4(float4 a, float4 b) {
    return make_float4(a.x + b.x, a.y + b.y, a.z + b.z, a.w + b.w);
}
__device__ __forceinline__ float4 h2f4(uint2 raw) {
    float2 lo = __half22float2(*reinterpret_cast<__half2*>(&raw.x));
    float2 hi = __half22float2(*reinterpret_cast<__half2*>(&raw.y));
    return make_float4(lo.x, lo.y, hi.x, hi.y);
}
// T += h * (w0*r + w1)
__device__ __forceinline__ float4 tacc4(float4 h, float4 r, float w0, float w1,
                                        float4 T) {
    T.x = fmaf(h.x, fmaf(w0, r.x, w1), T.x);
    T.y = fmaf(h.y, fmaf(w0, r.y, w1), T.y);
    T.z = fmaf(h.z, fmaf(w0, r.z, w1), T.z);
    T.w = fmaf(h.w, fmaf(w0, r.w, w1), T.w);
    return T;
}

// ------------------------- fused setup kernel --------------------------------
__global__ void setup_kernel(float* tw, float* wt, float* wi,
                             const float* __restrict__ cw1,
                             const float* __restrict__ cw2, float* w,
                             int* deg) {
    int i = blockIdx.x * blockDim.x + threadIdx.x;
    if (i < 7 * 64) {
        int s = i >> 6, j = i & 63;
        int l = 64 >> s;
        float2 v = make_float2(0.f, 0.f);
        if (j < l) {
            double a = (double)j / (double)l;
            v = make_float2((float)cospi(a), (float)sinpi(a));
        }
        reinterpret_cast<float2*>(tw)[i] = v;
    }
    if (i < 129) {
        double a = (double)i / 128.0;
        reinterpret_cast<float2*>(wt)[i] = make_float2((float)cospi(a), (float)(-sinpi(a)));
        reinterpret_cast<float2*>(wi)[i] = make_float2((float)cospi(a), (float)( sinpi(a)));
    }
    if (i == 0) {
        for (int L = 0; L < 2; L++) {
            const float* c = (L == 0) ? cw1 : cw2;
            float m = fmaxf(c[0], fmaxf(c[1], c[2]));
            float e0 = expf(c[0] - m), e1 = expf(c[1] - m), e2 = expf(c[2] - m);
            float s = e0 + e1 + e2;
            w[L * 3 + 0] = e0 / s; w[L * 3 + 1] = e1 / s; w[L * 3 + 2] = e2 / s;
        }
    }
    if (i < N_NODES) deg[i] = 0;
}

// ------------------------- fp32 -> bf16 hi/lo split (all tensors, 1 launch) --
__global__ void split_all_kernel(const float* __restrict__ Wn1,
                                 const float* __restrict__ Wn2,
                                 const float* __restrict__ Wr2,
                                 const float* __restrict__ rel2,
                                 __nv_bfloat16* __restrict__ Whi,
                                 __nv_bfloat16* __restrict__ Wlo,
                                 __nv_bfloat16* __restrict__ R2hi,
                                 __nv_bfloat16* __restrict__ R2lo) {
    const int W4 = DIM * DIM / 4;
    const int R4 = NRELS * DIM / 4;
    int i = blockIdx.x * blockDim.x + threadIdx.x;
    const float* src; __nv_bfloat16 *hi, *lo; int idx;
    if (i < W4)            { src = Wn1;  hi = Whi;                 lo = Wlo;                 idx = i; }
    else if (i < 2 * W4)   { src = Wn2;  hi = Whi + DIM * DIM;     lo = Wlo + DIM * DIM;     idx = i - W4; }
    else if (i < 3 * W4)   { src = Wr2;  hi = Whi + 2 * DIM * DIM; lo = Wlo + 2 * DIM * DIM; idx = i - 2 * W4; }
    else if (i < 3 * W4 + R4) { src = rel2; hi = R2hi;             lo = R2lo;                idx = i - 3 * W4; }
    else return;
    float4 v = reinterpret_cast<const float4*>(src)[idx];
    float f[4] = {v.x, v.y, v.z, v.w};
    __nv_bfloat16 h[4], l[4];
#pragma unroll
    for (int j = 0; j < 4; j++) {
        h[j] = __float2bfloat16(f[j]);
        l[j] = __float2bfloat16(f[j] - __bfloat162float(h[j]));
    }
    reinterpret_cast<uint2*>(hi)[idx] = *reinterpret_cast<uint2*>(h);
    reinterpret_cast<uint2*>(lo)[idx] = *reinterpret_cast<uint2*>(l);
}

// ------------------------- edge sorting (counting sort by dst) ---------------
__global__ void hist_kernel(const int* __restrict__ dst, int* deg) {
    int e = blockIdx.x * blockDim.x + threadIdx.x;
    if (e < N_EDGES) atomicAdd(&deg[dst[e]], 1);
}
// edge-offset scan + degree histogram/prefix (for degree-sorted perm)
__global__ __launch_bounds__(1024)
void scan_kernel(const int* __restrict__ deg, int* off, int* pos, int* dh) {
    __shared__ int ps[1024];
    __shared__ int dsh[DBINS];
    int t = threadIdx.x;
    if (t < DBINS) dsh[t] = 0;
    __syncthreads();
    const int CH = (N_NODES + 1023) / 1024;
    int b0 = t * CH, b1 = min(b0 + CH, N_NODES);
    int s = 0;
    for (int i = b0; i < b1; i++) {
        int d = deg[i];
        s += d;
        atomicAdd(&dsh[min(d, DBINS - 1)], 1);
    }
    ps[t] = s;
    __syncthreads();
    for (int o = 1; o < 1024; o <<= 1) {
        int u = (t >= o) ? ps[t - o] : 0;
        __syncthreads();
        ps[t] += u;
        __syncthreads();
    }
    int run = ps[t] - s;
    for (int i = b0; i < b1; i++) {
        off[i] = run; pos[i] = run; run += deg[i];
    }
    if (t == 1023) off[N_NODES] = ps[1023];
    if (t == 0) {             // exclusive prefix over degree bins
        int acc = 0;
        for (int b = 0; b < DBINS; b++) { int c = dsh[b]; dh[b] = acc; acc += c; }
    }
}
__global__ void scatter_kernel(const int* __restrict__ src,
                               const int* __restrict__ dst,
                               const int* __restrict__ et,
                               int* pos, int2* edges) {
    int e = blockIdx.x * blockDim.x + threadIdx.x;
    if (e >= N_EDGES) return;
    int p = atomicAdd(&pos[dst[e]], 1);
    edges[p] = make_int2(src[e], et[e]);
}
// node permutation: counting-sort nodes by degree (balanced agg blocks)
__global__ void perm_kernel(const int* __restrict__ deg, int* dh, int* perm) {
    int v = blockIdx.x * blockDim.x + threadIdx.x;
    if (v >= N_NODES) return;
    int p = atomicAdd(&dh[min(deg[v], DBINS - 1)], 1);
    perm[p] = v;
}

// ------------------------- 128-pt Stockham FFT (64 threads/row) --------------
__device__ __forceinline__ void fft128(float2* b0, float2* b1, int t, float sgn,
                                       const float2* __restrict__ tw) {
    float2* src = b0;
    float2* dst = b1;
#pragma unroll
    for (int s = 0; s < 7; s++) {
        int m = 1 << s;
        int j = t >> s;
        float2 w = tw[(s << 6) + j];
        w.y *= sgn;
        float2 c0 = src[t];
        float2 c1 = src[t + 64];
        float2 sum = make_float2(c0.x + c1.x, c0.y + c1.y);
        float2 d   = make_float2(c0.x - c1.x, c0.y - c1.y);
        int idx = (t & (m - 1)) | ((t >> s) << (s + 1));
        dst[idx]     = sum;
        dst[idx + m] = cmulf(d, w);
        float2* tmp = src; src = dst; dst = tmp;
        __syncthreads();
    }
}

// forward untangle -> fp16 spectrum row
__device__ __forceinline__ void untangle_store_h(
    float2* Z, __half2* Srow, int t, const float2* __restrict__ wt) {
#pragma unroll
    for (int u = 0; u < 2; u++) {
        int k = t + 64 * u;
        float2 Zk = Z[k];
        float2 Zm = Z[(128 - k) & 127];
        float2 Ze = make_float2(0.5f * (Zk.x + Zm.x), 0.5f * (Zk.y - Zm.y));
        float2 d  = make_float2(Zk.x - Zm.x, Zk.y + Zm.y);
        float2 Zo = make_float2(0.5f * d.y, -0.5f * d.x);
        float2 W  = wt[k];
        float2 H  = make_float2(Ze.x + W.x * Zo.x - W.y * Zo.y,
                                Ze.y + W.x * Zo.y + W.y * Zo.x);
        Srow[k] = __float22half2_rn(H);
    }
    if (t == 0) {
        float2 Z0 = Z[0];
        Srow[128] = __float22half2_rn(make_float2(Z0.x - Z0.y, 0.f));
    }
}

// ------------------------- gather + forward rfft (fused) ---------------------
__global__ __launch_bounds__(256)
void gather_fft_kernel(const int* __restrict__ x, const float* __restrict__ emb,
                       float* __restrict__ h, __half2* __restrict__ hH,
                       __half2* __restrict__ SH,
                       const float2* __restrict__ tw, const float2* __restrict__ wt) {
    __shared__ float2 buf[4][2][128];
    int g = threadIdx.x >> 6, t = threadIdx.x & 63;
    int row = (blockIdx.x << 2) + g;
    float4 v = reinterpret_cast<const float4*>(emb + (size_t)x[row] * DIM)[t];
    reinterpret_cast<float4*>(h + (size_t)row * DIM)[t] = v;
    __half2 p0 = __float22half2_rn(make_float2(v.x, v.y));
    __half2 p1 = __float22half2_rn(make_float2(v.z, v.w));
    *reinterpret_cast<uint2*>(hH + (size_t)row * HROW2 + 2 * t) =
        make_uint2(*reinterpret_cast<uint32_t*>(&p0), *reinterpret_cast<uint32_t*>(&p1));
    buf[g][0][2 * t]     = make_float2(v.x, v.y);
    buf[g][0][2 * t + 1] = make_float2(v.z, v.w);
    __syncthreads();
    fft128(buf[g][0], buf[g][1], t, -1.f, tw);
    untangle_store_h(buf[g][1], SH + (size_t)row * SROW2, t, wt);
}

// --------------- rel tables fft -> fp16 copies (both layers, 1 launch) -------
__global__ __launch_bounds__(256)
void rel_fft2_kernel(const float* __restrict__ rel1, const float* __restrict__ rel2,
                     __half2* __restrict__ rH1,  __half2* __restrict__ RSH1,
                     __half2* __restrict__ rH2,  __half2* __restrict__ RSH2,
                     const float2* __restrict__ tw, const float2* __restrict__ wt) {
    __shared__ float2 buf[4][2][128];
    int g = threadIdx.x >> 6, t = threadIdx.x & 63;
    int row = (blockIdx.x << 2) + g;
    const float* rel = (row < NRELS) ? rel1 : rel2;
    __half2* rH  = (row < NRELS) ? rH1  : rH2;
    __half2* RSH = (row < NRELS) ? RSH1 : RSH2;
    int r = (row < NRELS) ? row : row - NRELS;
    float4 v = reinterpret_cast<const float4*>(rel + (size_t)r * DIM)[t];
    __half2 p0 = __float22half2_rn(make_float2(v.x, v.y));
    __half2 p1 = __float22half2_rn(make_float2(v.z, v.w));
    *reinterpret_cast<uint2*>(rH + (size_t)r * HROW2 + 2 * t) =
        make_uint2(*reinterpret_cast<uint32_t*>(&p0), *reinterpret_cast<uint32_t*>(&p1));
    buf[g][0][2 * t]     = make_float2(v.x, v.y);
    buf[g][0][2 * t + 1] = make_float2(v.z, v.w);
    __syncthreads();
    fft128(buf[g][0], buf[g][1], t, -1.f, tw);
    untangle_store_h(buf[g][1], RSH + (size_t)r * SROW2, t, wt);
}

// --------------- aggregation + inverse rfft (degree-sorted nodes) ------------
__global__ __launch_bounds__(256)
void agg_inv_kernel(const int2* __restrict__ edges, const int* __restrict__ off,
                    const int* __restrict__ perm,
                    const __half2* __restrict__ hH,  const __half2* __restrict__ HSH,
                    const __half2* __restrict__ rH, const __half2* __restrict__ RSH,
                    const float* __restrict__ w, int wofs,
                    __nv_bfloat16* __restrict__ HChi,
                    __nv_bfloat16* __restrict__ HClo,
                    const float2* __restrict__ tw, const float2* __restrict__ wi) {
    __shared__ float2 buf[4][2][128];
    __shared__ float2 sA[4][132];
    int g = threadIdx.x >> 6, t = threadIdx.x & 63;
    int v = perm[(blockIdx.x << 2) + g];      // degree-sorted: block is balanced
    float w0 = w[wofs + 0], w1 = w[wofs + 1], w2 = w[wofs + 2];

    const uint2* hHu  = reinterpret_cast<const uint2*>(hH);
    const uint2* rHu  = reinterpret_cast<const uint2*>(rH);
    const uint2* HSHu = reinterpret_cast<const uint2*>(HSH);
    const uint2* RSHu = reinterpret_cast<const uint2*>(RSH);

    // self-loop (rel type 0)
    float4 hv0 = h2f4(hHu[(size_t)v * 64 + t]);
    float4 rv0 = h2f4(rHu[t]);
    float4 T  = tacc4(hv0, rv0, w0, w1, make_float4(0.f, 0.f, 0.f, 0.f));
    float4 Rs = rv0;
    float4 F  = spec4(h2f4(HSHu[(size_t)v * 65 + t]), h2f4(RSHu[t]));
    float2 Ft = make_float2(0.f, 0.f);
    if (t == 0) {
        float2 a = __half22float2(HSH[(size_t)v * SROW2 + 128]);
        float2 b = __half22float2(RSH[128]);
        Ft = make_float2(a.x * b.x + a.y * b.y, a.y * b.x - a.x * b.y);
    }

    int e = off[v], e1 = off[v + 1];
    for (; e + 1 < e1; e += 2) {
        int2 ea = edges[e];
        int2 eb = edges[e + 1];
        uint2 ha = hHu [(size_t)ea.x * 64 + t];
        uint2 ra = rHu [(size_t)ea.y * 64 + t];
        uint2 sa = HSHu[(size_t)ea.x * 65 + t];
        uint2 ta = RSHu[(size_t)ea.y * 65 + t];
        uint2 hb = hHu [(size_t)eb.x * 64 + t];
        uint2 rb = rHu [(size_t)eb.y * 64 + t];
        uint2 sb = HSHu[(size_t)eb.x * 65 + t];
        uint2 tb = RSHu[(size_t)eb.y * 65 + t];
        float4 rfa = h2f4(ra), rfb = h2f4(rb);
        T = tacc4(h2f4(ha), rfa, w0, w1, T);  Rs = add4(Rs, rfa);
        F = add4(F, spec4(h2f4(sa), h2f4(ta)));
        T = tacc4(h2f4(hb), rfb, w0, w1, T);  Rs = add4(Rs, rfb);
        F = add4(F, spec4(h2f4(sb), h2f4(tb)));
        if (t == 0) {
            float2 a0 = __half22float2(HSH[(size_t)ea.x * SROW2 + 128]);
            float2 b0 = __half22float2(RSH[(size_t)ea.y * SROW2 + 128]);
            float2 a1 = __half22float2(HSH[(size_t)eb.x * SROW2 + 128]);
            float2 b1 = __half22float2(RSH[(size_t)eb.y * SROW2 + 128]);
            Ft.x += a0.x * b0.x + a0.y * b0.y + a1.x * b1.x + a1.y * b1.y;
            Ft.y += a0.y * b0.x - a0.x * b0.y + a1.y * b1.x - a1.x * b1.y;
        }
    }
    if (e < e1) {
        int2 ed = edges[e];
        float4 rf = h2f4(rHu[(size_t)ed.y * 64 + t]);
        T = tacc4(h2f4(hHu[(size_t)ed.x * 64 + t]), rf, w0, w1, T);
        Rs = add4(Rs, rf);
        F = add4(F, spec4(h2f4(HSHu[(size_t)ed.x * 65 + t]),
                          h2f4(RSHu[(size_t)ed.y * 65 + t])));
        if (t == 0) {
            float2 a = __half22float2(HSH[(size_t)ed.x * SROW2 + 128]);
            float2 b = __half22float2(RSH[(size_t)ed.y * SROW2 + 128]);
            Ft.x += a.x * b.x + a.y * b.y;
            Ft.y += a.y * b.x - a.x * b.y;
        }
    }

    // stage spectrum (scaled by w2) into shared
    sA[g][2 * t]     = make_float2(w2 * F.x, w2 * F.y);
    sA[g][2 * t + 1] = make_float2(w2 * F.z, w2 * F.w);
    if (t == 0) sA[g][128] = make_float2(w2 * Ft.x, w2 * Ft.y);
    __syncthreads();

    // inverse untangle -> packed complex
#pragma unroll
    for (int u = 0; u < 2; u++) {
        int k = t + 64 * u;
        float2 Ak = sA[g][k], Am = sA[g][128 - k];
        float2 Ze = make_float2(0.5f * (Ak.x + Am.x), 0.5f * (Ak.y - Am.y));
        float2 hd = make_float2(0.5f * (Ak.x - Am.x), 0.5f * (Ak.y + Am.y));
        float2 Zo = cmulf(wi[k], hd);
        buf[g][0][k] = make_float2(Ze.x - Zo.y, Ze.y + Zo.x);
    }
    __syncthreads();
    fft128(buf[g][0], buf[g][1], t, +1.f, tw);
    float2 z0 = buf[g][1][2 * t], z1 = buf[g][1][2 * t + 1];
    const float inv = 1.f / 128.f;
    float o[4];
    o[0] = fmaf(w1, Rs.x, T.x) + z0.x * inv;
    o[1] = fmaf(w1, Rs.y, T.y) + z0.y * inv;
    o[2] = fmaf(w1, Rs.z, T.z) + z1.x * inv;
    o[3] = fmaf(w1, Rs.w, T.w) + z1.y * inv;
    __nv_bfloat16 hi[4], lo[4];
#pragma unroll
    for (int j = 0; j < 4; j++) {
        hi[j] = __float2bfloat16(o[j]);
        lo[j] = __float2bfloat16(o[j] - __bfloat162float(hi[j]));
    }
    reinterpret_cast<uint2*>(HChi + (size_t)v * DIM)[t] = *reinterpret_cast<uint2*>(hi);
    reinterpret_cast<uint2*>(HClo + (size_t)v * DIM)[t] = *reinterpret_cast<uint2*>(lo);
}

// --------- LN + ReLU (input Z already = gemm+bias+resid), optional fft -------
template<bool DO_FFT>
__global__ __launch_bounds__(256)
void epilogue_fft_kernel(const float* __restrict__ Z,
                         const float* __restrict__ gamma,
                         const float* __restrict__ beta,
                         float* __restrict__ h_out,
                         __half2* __restrict__ hH,
                         __half2* __restrict__ SH,
                         const float2* __restrict__ tw,
                         const float2* __restrict__ wt) {
    __shared__ float2 buf[4][2][128];
    __shared__ float sred[4][2];
    int g = threadIdx.x >> 6, t = threadIdx.x & 63;
    int wsub = t >> 5;
    int v = (blockIdx.x << 2) + g;

    float4 z = reinterpret_cast<const float4*>(Z + (size_t)v * DIM)[t];
    float s = z.x + z.y + z.z + z.w;
#pragma unroll
    for (int ofs = 16; ofs; ofs >>= 1) s += __shfl_xor_sync(0xffffffffu, s, ofs);
    if ((t & 31) == 0) sred[g][wsub] = s;
    __syncthreads();
    float mu = (sred[g][0] + sred[g][1]) * (1.f / DIM);
    __syncthreads();
    float4 zc = make_float4(z.x - mu, z.y - mu, z.z - mu, z.w - mu);
    float vv = zc.x * zc.x + zc.y * zc.y + zc.z * zc.z + zc.w * zc.w;
#pragma unroll
    for (int ofs = 16; ofs; ofs >>= 1) vv += __shfl_xor_sync(0xffffffffu, vv, ofs);
    if ((t & 31) == 0) sred[g][wsub] = vv;
    __syncthreads();
    float rstd = rsqrtf((sred[g][0] + sred[g][1]) * (1.f / DIM) + LN_EPS);
    float4 gm = reinterpret_cast<const float4*>(gamma)[t];
    float4 bt = reinterpret_cast<const float4*>(beta)[t];
    float4 y = make_float4(fmaxf(zc.x * rstd * gm.x + bt.x, 0.f),
                           fmaxf(zc.y * rstd * gm.y + bt.y, 0.f),
                           fmaxf(zc.z * rstd * gm.z + bt.z, 0.f),
                           fmaxf(zc.w * rstd * gm.w + bt.w, 0.f));
    reinterpret_cast<float4*>(h_out + (size_t)v * DIM)[t] = y;
    if (DO_FFT) {
        __half2 p0 = __float22half2_rn(make_float2(y.x, y.y));
        __half2 p1 = __float22half2_rn(make_float2(y.z, y.w));
        *reinterpret_cast<uint2*>(hH + (size_t)v * HROW2 + 2 * t) =
            make_uint2(*reinterpret_cast<uint32_t*>(&p0), *reinterpret_cast<uint32_t*>(&p1));
        buf[g][0][2 * t]     = make_float2(y.x, y.y);
        buf[g][0][2 * t + 1] = make_float2(y.z, y.w);
        __syncthreads();
        fft128(buf[g][0], buf[g][1], t, -1.f, tw);
        untangle_store_h(buf[g][1], SH + (size_t)v * SROW2, t, wt);
    }
}

// ------------------------- bf16x3 GEMM with pre-split operands ---------------
#define GBK 32
#define GPAD 8
#define GLDW (GBK + GPAD)

__device__ __forceinline__ void mma_bf16(float* d,
    uint32_t a0, uint32_t a1, uint32_t a2, uint32_t a3,
    uint32_t b0, uint32_t b1) {
    asm volatile(
        "mma.sync.aligned.m16n8k16.row.col.f32.bf16.bf16.f32 "
        "{%0,%1,%2,%3}, {%4,%5,%6,%7}, {%8,%9}, {%0,%1,%2,%3};"
        : "+f"(d[0]), "+f"(d[1]), "+f"(d[2]), "+f"(d[3])
        : "r"(a0), "r"(a1), "r"(a2), "r"(a3), "r"(b0), "r"(b1));
}

template<bool BIAS, bool RESID>
__global__ __launch_bounds__(256)
void bf16s_gemm(const __nv_bfloat16* __restrict__ Ahi,
                const __nv_bfloat16* __restrict__ Alo,
                const __nv_bfloat16* __restrict__ Bhi,
                const __nv_bfloat16* __restrict__ Blo,
                float* __restrict__ C, const float* __restrict__ bias,
                const float* __restrict__ Hres,
                int M, int N, int K) {
    __shared__ __align__(16) __nv_bfloat16 Ah[128 * GLDW];
    __shared__ __align__(16) __nv_bfloat16 Al[128 * GLDW];
    __shared__ __align__(16) __nv_bfloat16 Bh[128 * GLDW];
    __shared__ __align__(16) __nv_bfloat16 Bl[128 * GLDW];

    int tid = threadIdx.x;
    int lane = tid & 31, wid = tid >> 5;
    int wm = wid & 1, wn = wid >> 1;
    int r = lane >> 2, cq = lane & 3;
    int bm = blockIdx.y * 128, bn = blockIdx.x * 128;

    float acc[4][4][4];
#pragma unroll
    for (int a = 0; a < 4; a++)
#pragma unroll
        for (int b = 0; b < 4; b++)
#pragma unroll
            for (int c = 0; c < 4; c++) acc[a][b][c] = 0.f;

    int lrow[2], lcol[2];
#pragma unroll
    for (int j = 0; j < 2; j++) {
        int idx = tid + 256 * j;
        lrow[j] = idx >> 2; lcol[j] = (idx & 3) << 3;
    }

    uint4 rah[2], ral[2], rbh[2], rbl[2];
    const uint4 z4 = make_uint4(0, 0, 0, 0);

    auto load_tile = [&](int k0) {
#pragma unroll
        for (int j = 0; j < 2; j++) {
            size_t ao = (size_t)(bm + lrow[j]) * K + k0 + lcol[j];
            size_t bo = (size_t)(bn + lrow[j]) * K + k0 + lcol[j];
            bool av = (bm + lrow[j] < M), bv = (bn + lrow[j] < N);
            rah[j] = av ? *reinterpret_cast<const uint4*>(Ahi + ao) : z4;
            ral[j] = av ? *reinterpret_cast<const uint4*>(Alo + ao) : z4;
            rbh[j] = bv ? *reinterpret_cast<const uint4*>(Bhi + bo) : z4;
            rbl[j] = bv ? *reinterpret_cast<const uint4*>(Blo + bo) : z4;
        }
    };
    auto stage_tile = [&]() {
#pragma unroll
        for (int j = 0; j < 2; j++) {
            int so = lrow[j] * GLDW + lcol[j];
            *reinterpret_cast<uint4*>(&Ah[so]) = rah[j];
            *reinterpret_cast<uint4*>(&Al[so]) = ral[j];
            *reinterpret_cast<uint4*>(&Bh[so]) = rbh[j];
            *reinterpret_cast<uint4*>(&Bl[so]) = rbl[j];
        }
    };

    load_tile(0);
    for (int k0 = 0; k0 < K; k0 += GBK) {
        stage_tile();
        __syncthreads();
        if (k0 + GBK < K) load_tile(k0 + GBK);

#pragma unroll
        for (int ks = 0; ks < 2; ks++) {
            int kb = ks * 16 + cq * 2;
            uint32_t bhf[4][2], blf[4][2];
#pragma unroll
            for (int nf = 0; nf < 4; nf++) {
                int col = wn * 32 + nf * 8 + r;
                bhf[nf][0] = *reinterpret_cast<const uint32_t*>(&Bh[col * GLDW + kb]);
                bhf[nf][1] = *reinterpret_cast<const uint32_t*>(&Bh[col * GLDW + kb + 8]);
                blf[nf][0] = *reinterpret_cast<const uint32_t*>(&Bl[col * GLDW + kb]);
                blf[nf][1] = *reinterpret_cast<const uint32_t*>(&Bl[col * GLDW + kb + 8]);
            }
#pragma unroll
            for (int mf = 0; mf < 4; mf++) {
                int row = wm * 64 + mf * 16 + r;
                uint32_t a0 = *reinterpret_cast<const uint32_t*>(&Ah[row * GLDW + kb]);
                uint32_t a1 = *reinterpret_cast<const uint32_t*>(&Ah[(row + 8) * GLDW + kb]);
                uint32_t a2 = *reinterpret_cast<const uint32_t*>(&Ah[row * GLDW + kb + 8]);
                uint32_t a3 = *reinterpret_cast<const uint32_t*>(&Ah[(row + 8) * GLDW + kb + 8]);
                uint32_t l0 = *reinterpret_cast<const uint32_t*>(&Al[row * GLDW + kb]);
                uint32_t l1 = *reinterpret_cast<const uint32_t*>(&Al[(row + 8) * GLDW + kb]);
                uint32_t l2 = *reinterpret_cast<const uint32_t*>(&Al[row * GLDW + kb + 8]);
                uint32_t l3 = *reinterpret_cast<const uint32_t*>(&Al[(row + 8) * GLDW + kb + 8]);
#pragma unroll
                for (int nf = 0; nf < 4; nf++) {
                    mma_bf16(acc[mf][nf], a0, a1, a2, a3, bhf[nf][0], bhf[nf][1]);
                    mma_bf16(acc[mf][nf], a0, a1, a2, a3, blf[nf][0], blf[nf][1]);
                    mma_bf16(acc[mf][nf], l0, l1, l2, l3, bhf[nf][0], bhf[nf][1]);
                }
            }
        }
        __syncthreads();
    }

#pragma unroll
    for (int mf = 0; mf < 4; mf++) {
        int row0 = bm + wm * 64 + mf * 16 + r;
#pragma unroll
        for (int nf = 0; nf < 4; nf++) {
            int col = bn + wn * 32 + nf * 8 + cq * 2;
            float bx = 0.f, by = 0.f;
            if (BIAS) { bx = bias[col]; by = bias[col + 1]; }
            if (row0 < M) {
                float rx = bx, ry = by;
                if (RESID) {
                    float2 hv = *reinterpret_cast<const float2*>(
                        Hres + (size_t)row0 * N + col);
                    rx += hv.x; ry += hv.y;
                }
                *reinterpret_cast<float2*>(C + (size_t)row0 * N + col) =
                    make_float2(acc[mf][nf][0] + rx, acc[mf][nf][1] + ry);
            }
            if (row0 + 8 < M) {
                float rx = bx, ry = by;
                if (RESID) {
                    float2 hv = *reinterpret_cast<const float2*>(
                        Hres + (size_t)(row0 + 8) * N + col);
                    rx += hv.x; ry += hv.y;
                }
                *reinterpret_cast<float2*>(C + (size_t)(row0 + 8) * N + col) =
                    make_float2(acc[mf][nf][2] + rx, acc[mf][nf][3] + ry);
            }
        }
    }
}

// ------------------------- launch --------------------------------------------
extern "C" void kernel_launch(void* const* d_in, const int* in_sizes, int n_in,
                              void* d_out, int out_size) {
    (void)in_sizes; (void)n_in; (void)out_size;
    const int*   x    = (const int*)  d_in[0];
    const int*   eidx = (const int*)  d_in[1];
    const int*   et   = (const int*)  d_in[2];
    const float* emb  = (const float*)d_in[3];
    const float* rel1 = (const float*)d_in[4];
    const float* Wn1  = (const float*)d_in[7];
    const float* bn1  = (const float*)d_in[8];
    const float* cw1  = (const float*)d_in[9];
    const float* gm1  = (const float*)d_in[10];
    const float* bt1  = (const float*)d_in[11];
    const float* rel2 = (const float*)d_in[12];
    const float* Wr2  = (const float*)d_in[13];
    const float* br2  = (const float*)d_in[14];
    const float* Wn2  = (const float*)d_in[15];
    const float* bn2  = (const float*)d_in[16];
    const float* cw2  = (const float*)d_in[17];
    const float* gm2  = (const float*)d_in[18];
    const float* bt2  = (const float*)d_in[19];

    float* out_h    = (float*)d_out;
    float* out_rels = out_h + (size_t)N_NODES * DIM;
    const int* src = eidx;
    const int* dst = eidx + N_EDGES;

    float *pH, *pZ, *pTw, *pWt, *pWi, *pW;
    __nv_bfloat16 *pHChi, *pHClo, *pWhi, *pWlo, *pR2hi, *pR2lo;
    __half2 *pHH, *pHSH, *pRH, *pRSH;
    int *pDeg, *pOff, *pPos, *pDh, *pPerm;
    int2* pEdges;
    cudaGetSymbolAddress((void**)&pH,    g_h);
    cudaGetSymbolAddress((void**)&pZ,    g_Z);
    cudaGetSymbolAddress((void**)&pHChi, g_HChi);
    cudaGetSymbolAddress((void**)&pHClo, g_HClo);
    cudaGetSymbolAddress((void**)&pWhi,  g_Whi);
    cudaGetSymbolAddress((void**)&pWlo,  g_Wlo);
    cudaGetSymbolAddress((void**)&pR2hi, g_R2hi);
    cudaGetSymbolAddress((void**)&pR2lo, g_R2lo);
    cudaGetSymbolAddress((void**)&pHH,   g_hH);
    cudaGetSymbolAddress((void**)&pHSH,  g_HSH);
    cudaGetSymbolAddress((void**)&pRH,   g_rH);
    cudaGetSymbolAddress((void**)&pRSH,  g_RSH);
    cudaGetSymbolAddress((void**)&pTw,   g_tw);
    cudaGetSymbolAddress((void**)&pWt,   g_wt);
    cudaGetSymbolAddress((void**)&pWi,   g_wi);
    cudaGetSymbolAddress((void**)&pW,    g_w);
    cudaGetSymbolAddress((void**)&pDeg,  g_deg);
    cudaGetSymbolAddress((void**)&pOff,  g_off);
    cudaGetSymbolAddress((void**)&pPos,  g_pos);
    cudaGetSymbolAddress((void**)&pDh,   g_dh);
    cudaGetSymbolAddress((void**)&pPerm, g_perm);
    cudaGetSymbolAddress((void**)&pEdges, g_edges);

    const float2* tw = (const float2*)pTw;
    const float2* wt = (const float2*)pWt;
    const float2* wi = (const float2*)pWi;
    __half2* pRH1  = pRH;
    __half2* pRH2  = pRH  + (size_t)NRELS * HROW2;
    __half2* pRSH1 = pRSH;
    __half2* pRSH2 = pRSH + (size_t)NRELS * SROW2;

    setup_kernel<<<(N_NODES + 255) / 256, 256>>>(pTw, pWt, pWi, cw1, cw2, pW, pDeg);
    hist_kernel<<<(N_EDGES + 255) / 256, 256>>>(dst, pDeg);
    scan_kernel<<<1, 1024>>>(pDeg, pOff, pPos, pDh);
    scatter_kernel<<<(N_EDGES + 255) / 256, 256>>>(src, dst, et, pPos, pEdges);
    perm_kernel<<<(N_NODES + 255) / 256, 256>>>(pDeg, pDh, pPerm);

    const int SPLIT_N = 3 * (DIM * DIM / 4) + NRELS * DIM / 4;
    split_all_kernel<<<(SPLIT_N + 255) / 256, 256>>>(
        Wn1, Wn2, Wr2, rel2, pWhi, pWlo, pR2hi, pR2lo);

    rel_fft2_kernel<<<2 * NRELS / 4, 256>>>(rel1, rel2, pRH1, pRSH1, pRH2, pRSH2,
                                            tw, wt);

    gather_fft_kernel<<<N_NODES / 4, 256>>>(x, emb, pH, pHH, pHSH, tw, wt);

    for (int L = 0; L < 2; L++) {
        const float* bn = (L == 0) ? bn1 : bn2;
        const float* gm = (L == 0) ? gm1 : gm2;
        const float* bt = (L == 0) ? bt1 : bt2;
        __half2* rH  = (L == 0) ? pRH1  : pRH2;
        __half2* RSH = (L == 0) ? pRSH1 : pRSH2;
        const __nv_bfloat16* Whi = pWhi + (size_t)L * DIM * DIM;
        const __nv_bfloat16* Wlo = pWlo + (size_t)L * DIM * DIM;

        agg_inv_kernel<<<N_NODES / 4, 256>>>(pEdges, pOff, pPerm, pHH, pHSH,
                                             rH, RSH, pW, 3 * L, pHChi, pHClo,
                                             tw, wi);
        bf16s_gemm<true, true><<<dim3(2, (N_NODES + 127) / 128), 256>>>(
            pHChi, pHClo, Whi, Wlo, pZ, bn, pH, N_NODES, DIM, DIM);
        if (L == 0) {
            epilogue_fft_kernel<true><<<N_NODES / 4, 256>>>(
                pZ, gm, bt, pH, pHH, pHSH, tw, wt);
        } else {
            epilogue_fft_kernel<false><<<N_NODES / 4, 256>>>(
                pZ, gm, bt, out_h, nullptr, nullptr, tw, wt);
        }
    }

    bf16s_gemm<true, false><<<dim3(2, (NRELS + 127) / 128), 256>>>(
        pR2hi, pR2lo, pWhi + 2 * DIM * DIM, pWlo + 2 * DIM * DIM,
        out_rels, br2, nullptr, NRELS, DIM, DIM);
}

// round 10
// speedup vs baseline: 1.0949x; 1.0524x over previous
#include <cuda_runtime.h>
#include <cuda_bf16.h>
#include <cuda_fp16.h>
#include <math.h>
#include <stdint.h>

#define N_NODES 50000
#define N_EDGES 250000
#define DIM     256
#define NRELS   400
#define HROW2   128     // h row: 128 half2 (256 vals) = 512 B
#define SROW2   130     // spec row: 129 complex bins as half2 + 1 pad = 520 B
#define LN_EPS  1e-5f
#define DBINS   64

// ------------------------- scratch (device globals) --------------------------
__device__ float   g_h  [(size_t)N_NODES * DIM];     // fp32 h (residual path)
__device__ float   g_Z  [(size_t)N_NODES * DIM];     // gemm out + bias + resid
__device__ __nv_bfloat16 g_HChi[(size_t)N_NODES * DIM];  // HC split hi
__device__ __nv_bfloat16 g_HClo[(size_t)N_NODES * DIM];  // HC split lo
__device__ __nv_bfloat16 g_Whi [3 * DIM * DIM];          // Wn1,Wn2,Wr2 hi
__device__ __nv_bfloat16 g_Wlo [3 * DIM * DIM];          // Wn1,Wn2,Wr2 lo
__device__ __nv_bfloat16 g_R2hi[NRELS * DIM];            // rel2 hi
__device__ __nv_bfloat16 g_R2lo[NRELS * DIM];            // rel2 lo
__device__ __half2 g_hH [(size_t)N_NODES * HROW2];   // h as fp16
__device__ __half2 g_HSH[(size_t)N_NODES * SROW2];   // rfft(h) as fp16
__device__ __half2 g_rH [2][(size_t)NRELS * HROW2];  // rel as fp16 (per layer)
__device__ __half2 g_RSH[2][(size_t)NRELS * SROW2];  // rfft(rel) as fp16
__device__ float   g_tw [7 * 64 * 2];
__device__ float   g_wt [129 * 2];
__device__ float   g_wi [129 * 2];
__device__ float   g_w  [6];
__device__ int     g_deg[N_NODES];
__device__ int     g_off[N_NODES + 1];
__device__ int     g_pos[N_NODES];
__device__ int     g_dh [DBINS];                     // degree-bin positions
__device__ int     g_perm[N_NODES];                  // nodes sorted by degree
__device__ int2    g_edges[N_EDGES];                 // (src, et) sorted by dst

// ------------------------- small helpers -------------------------------------
__device__ __forceinline__ float2 cmulf(float2 a, float2 b) {
    return make_float2(a.x * b.x - a.y * b.y, a.x * b.y + a.y * b.x);
}
__device__ __forceinline__ float4 spec4(float4 a, float4 b) {
    return make_float4(a.x * b.x + a.y * b.y,
                       a.y * b.x - a.x * b.y,
                       a.z * b.z + a.w * b.w,
                       a.w * b.z - a.z * b.w);
}
__device__ __forceinline__ float4 add4(float4 a, float4 b) {
    return make_float4(a.x + b.x, a.y + b.y, a.z + b.z, a.w + b.w);
}
__device__ __forceinline__ float4 h2f4(uint2 raw) {
    float2 lo = __half22float2(*reinterpret_cast<__half2*>(&raw.x));
    float2 hi = __half22float2(*reinterpret_cast<__half2*>(&raw.y));
    return make_float4(lo.x, lo.y, hi.x, hi.y);
}
// T += h * (w0*r + w1)
__device__ __forceinline__ float4 tacc4(float4 h, float4 r, float w0, float w1,
                                        float4 T) {
    T.x = fmaf(h.x, fmaf(w0, r.x, w1), T.x);
    T.y = fmaf(h.y, fmaf(w0, r.y, w1), T.y);
    T.z = fmaf(h.z, fmaf(w0, r.z, w1), T.z);
    T.w = fmaf(h.w, fmaf(w0, r.w, w1), T.w);
    return T;
}

// ------------------------- fused setup kernel --------------------------------
__global__ void setup_kernel(float* tw, float* wt, float* wi,
                             const float* __restrict__ cw1,
                             const float* __restrict__ cw2, float* w,
                             int* deg) {
    int i = blockIdx.x * blockDim.x + threadIdx.x;
    if (i < 7 * 64) {
        int s = i >> 6, j = i & 63;
        int l = 64 >> s;
        float2 v = make_float2(0.f, 0.f);
        if (j < l) {
            double a = (double)j / (double)l;
            v = make_float2((float)cospi(a), (float)sinpi(a));
        }
        reinterpret_cast<float2*>(tw)[i] = v;
    }
    if (i < 129) {
        double a = (double)i / 128.0;
        reinterpret_cast<float2*>(wt)[i] = make_float2((float)cospi(a), (float)(-sinpi(a)));
        reinterpret_cast<float2*>(wi)[i] = make_float2((float)cospi(a), (float)( sinpi(a)));
    }
    if (i == 0) {
        for (int L = 0; L < 2; L++) {
            const float* c = (L == 0) ? cw1 : cw2;
            float m = fmaxf(c[0], fmaxf(c[1], c[2]));
            float e0 = expf(c[0] - m), e1 = expf(c[1] - m), e2 = expf(c[2] - m);
            float s = e0 + e1 + e2;
            w[L * 3 + 0] = e0 / s; w[L * 3 + 1] = e1 / s; w[L * 3 + 2] = e2 / s;
        }
    }
    if (i < N_NODES) deg[i] = 0;
}

// ------------------------- fp32 -> bf16 hi/lo split (all tensors, 1 launch) --
__global__ void split_all_kernel(const float* __restrict__ Wn1,
                                 const float* __restrict__ Wn2,
                                 const float* __restrict__ Wr2,
                                 const float* __restrict__ rel2,
                                 __nv_bfloat16* __restrict__ Whi,
                                 __nv_bfloat16* __restrict__ Wlo,
                                 __nv_bfloat16* __restrict__ R2hi,
                                 __nv_bfloat16* __restrict__ R2lo) {
    const int W4 = DIM * DIM / 4;
    const int R4 = NRELS * DIM / 4;
    int i = blockIdx.x * blockDim.x + threadIdx.x;
    const float* src; __nv_bfloat16 *hi, *lo; int idx;
    if (i < W4)            { src = Wn1;  hi = Whi;                 lo = Wlo;                 idx = i; }
    else if (i < 2 * W4)   { src = Wn2;  hi = Whi + DIM * DIM;     lo = Wlo + DIM * DIM;     idx = i - W4; }
    else if (i < 3 * W4)   { src = Wr2;  hi = Whi + 2 * DIM * DIM; lo = Wlo + 2 * DIM * DIM; idx = i - 2 * W4; }
    else if (i < 3 * W4 + R4) { src = rel2; hi = R2hi;             lo = R2lo;                idx = i - 3 * W4; }
    else return;
    float4 v = reinterpret_cast<const float4*>(src)[idx];
    float f[4] = {v.x, v.y, v.z, v.w};
    __nv_bfloat16 h[4], l[4];
#pragma unroll
    for (int j = 0; j < 4; j++) {
        h[j] = __float2bfloat16(f[j]);
        l[j] = __float2bfloat16(f[j] - __bfloat162float(h[j]));
    }
    reinterpret_cast<uint2*>(hi)[idx] = *reinterpret_cast<uint2*>(h);
    reinterpret_cast<uint2*>(lo)[idx] = *reinterpret_cast<uint2*>(l);
}

// ------------------------- edge sorting (counting sort by dst) ---------------
__global__ void hist_kernel(const int* __restrict__ dst, int* deg) {
    int e = blockIdx.x * blockDim.x + threadIdx.x;
    if (e < N_EDGES) atomicAdd(&deg[dst[e]], 1);
}
// edge-offset scan + degree histogram/prefix (for degree-sorted perm)
__global__ __launch_bounds__(1024)
void scan_kernel(const int* __restrict__ deg, int* off, int* pos, int* dh) {
    __shared__ int ps[1024];
    __shared__ int dsh[DBINS];
    int t = threadIdx.x;
    if (t < DBINS) dsh[t] = 0;
    __syncthreads();
    const int CH = (N_NODES + 1023) / 1024;
    int b0 = t * CH, b1 = min(b0 + CH, N_NODES);
    int s = 0;
    for (int i = b0; i < b1; i++) {
        int d = deg[i];
        s += d;
        atomicAdd(&dsh[min(d, DBINS - 1)], 1);
    }
    ps[t] = s;
    __syncthreads();
    for (int o = 1; o < 1024; o <<= 1) {
        int u = (t >= o) ? ps[t - o] : 0;
        __syncthreads();
        ps[t] += u;
        __syncthreads();
    }
    int run = ps[t] - s;
    for (int i = b0; i < b1; i++) {
        off[i] = run; pos[i] = run; run += deg[i];
    }
    if (t == 1023) off[N_NODES] = ps[1023];
    if (t == 0) {
        int acc = 0;
        for (int b = 0; b < DBINS; b++) { int c = dsh[b]; dh[b] = acc; acc += c; }
    }
}
// fused: edge scatter + degree-sorted node permutation
__global__ void scatter_perm_kernel(const int* __restrict__ src,
                                    const int* __restrict__ dst,
                                    const int* __restrict__ et,
                                    const int* __restrict__ deg,
                                    int* pos, int* dh,
                                    int2* edges, int* perm) {
    int e = blockIdx.x * blockDim.x + threadIdx.x;
    if (e < N_EDGES) {
        int p = atomicAdd(&pos[dst[e]], 1);
        edges[p] = make_int2(src[e], et[e]);
    }
    if (e < N_NODES) {
        int p = atomicAdd(&dh[min(deg[e], DBINS - 1)], 1);
        perm[p] = e;
    }
}

// ------------------------- 128-pt Stockham FFT (64 threads/row) --------------
__device__ __forceinline__ void fft128(float2* b0, float2* b1, int t, float sgn,
                                       const float2* __restrict__ tw) {
    float2* src = b0;
    float2* dst = b1;
#pragma unroll
    for (int s = 0; s < 7; s++) {
        int m = 1 << s;
        int j = t >> s;
        float2 w = tw[(s << 6) + j];
        w.y *= sgn;
        float2 c0 = src[t];
        float2 c1 = src[t + 64];
        float2 sum = make_float2(c0.x + c1.x, c0.y + c1.y);
        float2 d   = make_float2(c0.x - c1.x, c0.y - c1.y);
        int idx = (t & (m - 1)) | ((t >> s) << (s + 1));
        dst[idx]     = sum;
        dst[idx + m] = cmulf(d, w);
        float2* tmp = src; src = dst; dst = tmp;
        __syncthreads();
    }
}

// forward untangle -> fp16 spectrum row
__device__ __forceinline__ void untangle_store_h(
    float2* Z, __half2* Srow, int t, const float2* __restrict__ wt) {
#pragma unroll
    for (int u = 0; u < 2; u++) {
        int k = t + 64 * u;
        float2 Zk = Z[k];
        float2 Zm = Z[(128 - k) & 127];
        float2 Ze = make_float2(0.5f * (Zk.x + Zm.x), 0.5f * (Zk.y - Zm.y));
        float2 d  = make_float2(Zk.x - Zm.x, Zk.y + Zm.y);
        float2 Zo = make_float2(0.5f * d.y, -0.5f * d.x);
        float2 W  = wt[k];
        float2 H  = make_float2(Ze.x + W.x * Zo.x - W.y * Zo.y,
                                Ze.y + W.x * Zo.y + W.y * Zo.x);
        Srow[k] = __float22half2_rn(H);
    }
    if (t == 0) {
        float2 Z0 = Z[0];
        Srow[128] = __float22half2_rn(make_float2(Z0.x - Z0.y, 0.f));
    }
}

// ------------------------- gather + forward rfft (fused) ---------------------
__global__ __launch_bounds__(256)
void gather_fft_kernel(const int* __restrict__ x, const float* __restrict__ emb,
                       float* __restrict__ h, __half2* __restrict__ hH,
                       __half2* __restrict__ SH,
                       const float2* __restrict__ tw, const float2* __restrict__ wt) {
    __shared__ float2 buf[4][2][128];
    int g = threadIdx.x >> 6, t = threadIdx.x & 63;
    int row = (blockIdx.x << 2) + g;
    float4 v = reinterpret_cast<const float4*>(emb + (size_t)x[row] * DIM)[t];
    reinterpret_cast<float4*>(h + (size_t)row * DIM)[t] = v;
    __half2 p0 = __float22half2_rn(make_float2(v.x, v.y));
    __half2 p1 = __float22half2_rn(make_float2(v.z, v.w));
    *reinterpret_cast<uint2*>(hH + (size_t)row * HROW2 + 2 * t) =
        make_uint2(*reinterpret_cast<uint32_t*>(&p0), *reinterpret_cast<uint32_t*>(&p1));
    buf[g][0][2 * t]     = make_float2(v.x, v.y);
    buf[g][0][2 * t + 1] = make_float2(v.z, v.w);
    __syncthreads();
    fft128(buf[g][0], buf[g][1], t, -1.f, tw);
    untangle_store_h(buf[g][1], SH + (size_t)row * SROW2, t, wt);
}

// --------------- rel tables fft -> fp16 copies (both layers, 1 launch) -------
__global__ __launch_bounds__(256)
void rel_fft2_kernel(const float* __restrict__ rel1, const float* __restrict__ rel2,
                     __half2* __restrict__ rH1,  __half2* __restrict__ RSH1,
                     __half2* __restrict__ rH2,  __half2* __restrict__ RSH2,
                     const float2* __restrict__ tw, const float2* __restrict__ wt) {
    __shared__ float2 buf[4][2][128];
    int g = threadIdx.x >> 6, t = threadIdx.x & 63;
    int row = (blockIdx.x << 2) + g;
    const float* rel = (row < NRELS) ? rel1 : rel2;
    __half2* rH  = (row < NRELS) ? rH1  : rH2;
    __half2* RSH = (row < NRELS) ? RSH1 : RSH2;
    int r = (row < NRELS) ? row : row - NRELS;
    float4 v = reinterpret_cast<const float4*>(rel + (size_t)r * DIM)[t];
    __half2 p0 = __float22half2_rn(make_float2(v.x, v.y));
    __half2 p1 = __float22half2_rn(make_float2(v.z, v.w));
    *reinterpret_cast<uint2*>(rH + (size_t)r * HROW2 + 2 * t) =
        make_uint2(*reinterpret_cast<uint32_t*>(&p0), *reinterpret_cast<uint32_t*>(&p1));
    buf[g][0][2 * t]     = make_float2(v.x, v.y);
    buf[g][0][2 * t + 1] = make_float2(v.z, v.w);
    __syncthreads();
    fft128(buf[g][0], buf[g][1], t, -1.f, tw);
    untangle_store_h(buf[g][1], RSH + (size_t)r * SROW2, t, wt);
}

// --------------- aggregation + inverse rfft (occupancy-tuned) ----------------
// __launch_bounds__(256, 4): cap registers at 64 -> 4 blocks/SM (2x occupancy).
// Spectrum staging aliases the FFT ping-pong buffer (sA == buf[g][1]).
__global__ __launch_bounds__(256, 4)
void agg_inv_kernel(const int2* __restrict__ edges, const int* __restrict__ off,
                    const int* __restrict__ perm,
                    const __half2* __restrict__ hH,  const __half2* __restrict__ HSH,
                    const __half2* __restrict__ rH, const __half2* __restrict__ RSH,
                    const float* __restrict__ w, int wofs,
                    __nv_bfloat16* __restrict__ HChi,
                    __nv_bfloat16* __restrict__ HClo,
                    const float2* __restrict__ tw, const float2* __restrict__ wi) {
    __shared__ float2 buf[4][2][132];   // buf[g][1][0..128] doubles as sA
    int g = threadIdx.x >> 6, t = threadIdx.x & 63;
    int v = perm[(blockIdx.x << 2) + g];
    float w0 = w[wofs + 0], w1 = w[wofs + 1], w2 = w[wofs + 2];

    const uint2* hHu  = reinterpret_cast<const uint2*>(hH);
    const uint2* rHu  = reinterpret_cast<const uint2*>(rH);
    const uint2* HSHu = reinterpret_cast<const uint2*>(HSH);
    const uint2* RSHu = reinterpret_cast<const uint2*>(RSH);

    // self-loop (rel type 0)
    float4 hv0 = h2f4(hHu[(size_t)v * 64 + t]);
    float4 rv0 = h2f4(rHu[t]);
    float4 T  = tacc4(hv0, rv0, w0, w1, make_float4(0.f, 0.f, 0.f, 0.f));
    float4 Rs = rv0;
    float4 F  = spec4(h2f4(HSHu[(size_t)v * 65 + t]), h2f4(RSHu[t]));
    float2 Ft = make_float2(0.f, 0.f);
    if (t == 0) {
        float2 a = __half22float2(HSH[(size_t)v * SROW2 + 128]);
        float2 b = __half22float2(RSH[128]);
        Ft = make_float2(a.x * b.x + a.y * b.y, a.y * b.x - a.x * b.y);
    }

    int e = off[v], e1 = off[v + 1];
    for (; e + 1 < e1; e += 2) {
        int2 ea = edges[e];
        int2 eb = edges[e + 1];
        uint2 ha = hHu [(size_t)ea.x * 64 + t];
        uint2 ra = rHu [(size_t)ea.y * 64 + t];
        uint2 sa = HSHu[(size_t)ea.x * 65 + t];
        uint2 ta = RSHu[(size_t)ea.y * 65 + t];
        uint2 hb = hHu [(size_t)eb.x * 64 + t];
        uint2 rb = rHu [(size_t)eb.y * 64 + t];
        uint2 sb = HSHu[(size_t)eb.x * 65 + t];
        uint2 tb = RSHu[(size_t)eb.y * 65 + t];
        float4 rfa = h2f4(ra), rfb = h2f4(rb);
        T = tacc4(h2f4(ha), rfa, w0, w1, T);  Rs = add4(Rs, rfa);
        F = add4(F, spec4(h2f4(sa), h2f4(ta)));
        T = tacc4(h2f4(hb), rfb, w0, w1, T);  Rs = add4(Rs, rfb);
        F = add4(F, spec4(h2f4(sb), h2f4(tb)));
        if (t == 0) {
            float2 a0 = __half22float2(HSH[(size_t)ea.x * SROW2 + 128]);
            float2 b0 = __half22float2(RSH[(size_t)ea.y * SROW2 + 128]);
            float2 a1 = __half22float2(HSH[(size_t)eb.x * SROW2 + 128]);
            float2 b1 = __half22float2(RSH[(size_t)eb.y * SROW2 + 128]);
            Ft.x += a0.x * b0.x + a0.y * b0.y + a1.x * b1.x + a1.y * b1.y;
            Ft.y += a0.y * b0.x - a0.x * b0.y + a1.y * b1.x - a1.x * b1.y;
        }
    }
    if (e < e1) {
        int2 ed = edges[e];
        float4 rf = h2f4(rHu[(size_t)ed.y * 64 + t]);
        T = tacc4(h2f4(hHu[(size_t)ed.x * 64 + t]), rf, w0, w1, T);
        Rs = add4(Rs, rf);
        F = add4(F, spec4(h2f4(HSHu[(size_t)ed.x * 65 + t]),
                          h2f4(RSHu[(size_t)ed.y * 65 + t])));
        if (t == 0) {
            float2 a = __half22float2(HSH[(size_t)ed.x * SROW2 + 128]);
            float2 b = __half22float2(RSH[(size_t)ed.y * SROW2 + 128]);
            Ft.x += a.x * b.x + a.y * b.y;
            Ft.y += a.y * b.x - a.x * b.y;
        }
    }

    // stage spectrum (scaled by w2) into the aliased buffer
    float2* sA = buf[g][1];
    sA[2 * t]     = make_float2(w2 * F.x, w2 * F.y);
    sA[2 * t + 1] = make_float2(w2 * F.z, w2 * F.w);
    if (t == 0) sA[128] = make_float2(w2 * Ft.x, w2 * Ft.y);
    __syncthreads();

    // inverse untangle -> packed complex into buf[g][0]
#pragma unroll
    for (int u = 0; u < 2; u++) {
        int k = t + 64 * u;
        float2 Ak = sA[k], Am = sA[128 - k];
        float2 Ze = make_float2(0.5f * (Ak.x + Am.x), 0.5f * (Ak.y - Am.y));
        float2 hd = make_float2(0.5f * (Ak.x - Am.x), 0.5f * (Ak.y + Am.y));
        float2 Zo = cmulf(wi[k], hd);
        buf[g][0][k] = make_float2(Ze.x - Zo.y, Ze.y + Zo.x);
    }
    __syncthreads();
    fft128(buf[g][0], buf[g][1], t, +1.f, tw);
    float2 z0 = buf[g][1][2 * t], z1 = buf[g][1][2 * t + 1];
    const float inv = 1.f / 128.f;
    float o[4];
    o[0] = fmaf(w1, Rs.x, T.x) + z0.x * inv;
    o[1] = fmaf(w1, Rs.y, T.y) + z0.y * inv;
    o[2] = fmaf(w1, Rs.z, T.z) + z1.x * inv;
    o[3] = fmaf(w1, Rs.w, T.w) + z1.y * inv;
    __nv_bfloat16 hi[4], lo[4];
#pragma unroll
    for (int j = 0; j < 4; j++) {
        hi[j] = __float2bfloat16(o[j]);
        lo[j] = __float2bfloat16(o[j] - __bfloat162float(hi[j]));
    }
    reinterpret_cast<uint2*>(HChi + (size_t)v * DIM)[t] = *reinterpret_cast<uint2*>(hi);
    reinterpret_cast<uint2*>(HClo + (size_t)v * DIM)[t] = *reinterpret_cast<uint2*>(lo);
}

// --------- LN + ReLU (input Z already = gemm+bias+resid), optional fft -------
template<bool DO_FFT>
__global__ __launch_bounds__(256)
void epilogue_fft_kernel(const float* __restrict__ Z,
                         const float* __restrict__ gamma,
                         const float* __restrict__ beta,
                         float* __restrict__ h_out,
                         __half2* __restrict__ hH,
                         __half2* __restrict__ SH,
                         const float2* __restrict__ tw,
                         const float2* __restrict__ wt) {
    __shared__ float2 buf[4][2][128];
    __shared__ float sred[4][2];
    int g = threadIdx.x >> 6, t = threadIdx.x & 63;
    int wsub = t >> 5;
    int v = (blockIdx.x << 2) + g;

    float4 z = reinterpret_cast<const float4*>(Z + (size_t)v * DIM)[t];
    float s = z.x + z.y + z.z + z.w;
#pragma unroll
    for (int ofs = 16; ofs; ofs >>= 1) s += __shfl_xor_sync(0xffffffffu, s, ofs);
    if ((t & 31) == 0) sred[g][wsub] = s;
    __syncthreads();
    float mu = (sred[g][0] + sred[g][1]) * (1.f / DIM);
    __syncthreads();
    float4 zc = make_float4(z.x - mu, z.y - mu, z.z - mu, z.w - mu);
    float vv = zc.x * zc.x + zc.y * zc.y + zc.z * zc.z + zc.w * zc.w;
#pragma unroll
    for (int ofs = 16; ofs; ofs >>= 1) vv += __shfl_xor_sync(0xffffffffu, vv, ofs);
    if ((t & 31) == 0) sred[g][wsub] = vv;
    __syncthreads();
    float rstd = rsqrtf((sred[g][0] + sred[g][1]) * (1.f / DIM) + LN_EPS);
    float4 gm = reinterpret_cast<const float4*>(gamma)[t];
    float4 bt = reinterpret_cast<const float4*>(beta)[t];
    float4 y = make_float4(fmaxf(zc.x * rstd * gm.x + bt.x, 0.f),
                           fmaxf(zc.y * rstd * gm.y + bt.y, 0.f),
                           fmaxf(zc.z * rstd * gm.z + bt.z, 0.f),
                           fmaxf(zc.w * rstd * gm.w + bt.w, 0.f));
    reinterpret_cast<float4*>(h_out + (size_t)v * DIM)[t] = y;
    if (DO_FFT) {
        __half2 p0 = __float22half2_rn(make_float2(y.x, y.y));
        __half2 p1 = __float22half2_rn(make_float2(y.z, y.w));
        *reinterpret_cast<uint2*>(hH + (size_t)v * HROW2 + 2 * t) =
            make_uint2(*reinterpret_cast<uint32_t*>(&p0), *reinterpret_cast<uint32_t*>(&p1));
        buf[g][0][2 * t]     = make_float2(y.x, y.y);
        buf[g][0][2 * t + 1] = make_float2(y.z, y.w);
        __syncthreads();
        fft128(buf[g][0], buf[g][1], t, -1.f, tw);
        untangle_store_h(buf[g][1], SH + (size_t)v * SROW2, t, wt);
    }
}

// ------------------------- bf16x3 GEMM with pre-split operands ---------------
#define GBK 32
#define GPAD 8
#define GLDW (GBK + GPAD)

__device__ __forceinline__ void mma_bf16(float* d,
    uint32_t a0, uint32_t a1, uint32_t a2, uint32_t a3,
    uint32_t b0, uint32_t b1) {
    asm volatile(
        "mma.sync.aligned.m16n8k16.row.col.f32.bf16.bf16.f32 "
        "{%0,%1,%2,%3}, {%4,%5,%6,%7}, {%8,%9}, {%0,%1,%2,%3};"
        : "+f"(d[0]), "+f"(d[1]), "+f"(d[2]), "+f"(d[3])
        : "r"(a0), "r"(a1), "r"(a2), "r"(a3), "r"(b0), "r"(b1));
}

template<bool BIAS, bool RESID>
__global__ __launch_bounds__(256)
void bf16s_gemm(const __nv_bfloat16* __restrict__ Ahi,
                const __nv_bfloat16* __restrict__ Alo,
                const __nv_bfloat16* __restrict__ Bhi,
                const __nv_bfloat16* __restrict__ Blo,
                float* __restrict__ C, const float* __restrict__ bias,
                const float* __restrict__ Hres,
                int M, int N, int K) {
    __shared__ __align__(16) __nv_bfloat16 Ah[128 * GLDW];
    __shared__ __align__(16) __nv_bfloat16 Al[128 * GLDW];
    __shared__ __align__(16) __nv_bfloat16 Bh[128 * GLDW];
    __shared__ __align__(16) __nv_bfloat16 Bl[128 * GLDW];

    int tid = threadIdx.x;
    int lane = tid & 31, wid = tid >> 5;
    int wm = wid & 1, wn = wid >> 1;
    int r = lane >> 2, cq = lane & 3;
    int bm = blockIdx.y * 128, bn = blockIdx.x * 128;

    float acc[4][4][4];
#pragma unroll
    for (int a = 0; a < 4; a++)
#pragma unroll
        for (int b = 0; b < 4; b++)
#pragma unroll
            for (int c = 0; c < 4; c++) acc[a][b][c] = 0.f;

    int lrow[2], lcol[2];
#pragma unroll
    for (int j = 0; j < 2; j++) {
        int idx = tid + 256 * j;
        lrow[j] = idx >> 2; lcol[j] = (idx & 3) << 3;
    }

    uint4 rah[2], ral[2], rbh[2], rbl[2];
    const uint4 z4 = make_uint4(0, 0, 0, 0);

    auto load_tile = [&](int k0) {
#pragma unroll
        for (int j = 0; j < 2; j++) {
            size_t ao = (size_t)(bm + lrow[j]) * K + k0 + lcol[j];
            size_t bo = (size_t)(bn + lrow[j]) * K + k0 + lcol[j];
            bool av = (bm + lrow[j] < M), bv = (bn + lrow[j] < N);
            rah[j] = av ? *reinterpret_cast<const uint4*>(Ahi + ao) : z4;
            ral[j] = av ? *reinterpret_cast<const uint4*>(Alo + ao) : z4;
            rbh[j] = bv ? *reinterpret_cast<const uint4*>(Bhi + bo) : z4;
            rbl[j] = bv ? *reinterpret_cast<const uint4*>(Blo + bo) : z4;
        }
    };
    auto stage_tile = [&]() {
#pragma unroll
        for (int j = 0; j < 2; j++) {
            int so = lrow[j] * GLDW + lcol[j];
            *reinterpret_cast<uint4*>(&Ah[so]) = rah[j];
            *reinterpret_cast<uint4*>(&Al[so]) = ral[j];
            *reinterpret_cast<uint4*>(&Bh[so]) = rbh[j];
            *reinterpret_cast<uint4*>(&Bl[so]) = rbl[j];
        }
    };

    load_tile(0);
    for (int k0 = 0; k0 < K; k0 += GBK) {
        stage_tile();
        __syncthreads();
        if (k0 + GBK < K) load_tile(k0 + GBK);

#pragma unroll
        for (int ks = 0; ks < 2; ks++) {
            int kb = ks * 16 + cq * 2;
            uint32_t bhf[4][2], blf[4][2];
#pragma unroll
            for (int nf = 0; nf < 4; nf++) {
                int col = wn * 32 + nf * 8 + r;
                bhf[nf][0] = *reinterpret_cast<const uint32_t*>(&Bh[col * GLDW + kb]);
                bhf[nf][1] = *reinterpret_cast<const uint32_t*>(&Bh[col * GLDW + kb + 8]);
                blf[nf][0] = *reinterpret_cast<const uint32_t*>(&Bl[col * GLDW + kb]);
                blf[nf][1] = *reinterpret_cast<const uint32_t*>(&Bl[col * GLDW + kb + 8]);
            }
#pragma unroll
            for (int mf = 0; mf < 4; mf++) {
                int row = wm * 64 + mf * 16 + r;
                uint32_t a0 = *reinterpret_cast<const uint32_t*>(&Ah[row * GLDW + kb]);
                uint32_t a1 = *reinterpret_cast<const uint32_t*>(&Ah[(row + 8) * GLDW + kb]);
                uint32_t a2 = *reinterpret_cast<const uint32_t*>(&Ah[row * GLDW + kb + 8]);
                uint32_t a3 = *reinterpret_cast<const uint32_t*>(&Ah[(row + 8) * GLDW + kb + 8]);
                uint32_t l0 = *reinterpret_cast<const uint32_t*>(&Al[row * GLDW + kb]);
                uint32_t l1 = *reinterpret_cast<const uint32_t*>(&Al[(row + 8) * GLDW + kb]);
                uint32_t l2 = *reinterpret_cast<const uint32_t*>(&Al[row * GLDW + kb + 8]);
                uint32_t l3 = *reinterpret_cast<const uint32_t*>(&Al[(row + 8) * GLDW + kb + 8]);
#pragma unroll
                for (int nf = 0; nf < 4; nf++) {
                    mma_bf16(acc[mf][nf], a0, a1, a2, a3, bhf[nf][0], bhf[nf][1]);
                    mma_bf16(acc[mf][nf], a0, a1, a2, a3, blf[nf][0], blf[nf][1]);
                    mma_bf16(acc[mf][nf], l0, l1, l2, l3, bhf[nf][0], bhf[nf][1]);
                }
            }
        }
        __syncthreads();
    }

#pragma unroll
    for (int mf = 0; mf < 4; mf++) {
        int row0 = bm + wm * 64 + mf * 16 + r;
#pragma unroll
        for (int nf = 0; nf < 4; nf++) {
            int col = bn + wn * 32 + nf * 8 + cq * 2;
            float bx = 0.f, by = 0.f;
            if (BIAS) { bx = bias[col]; by = bias[col + 1]; }
            if (row0 < M) {
                float rx = bx, ry = by;
                if (RESID) {
                    float2 hv = *reinterpret_cast<const float2*>(
                        Hres + (size_t)row0 * N + col);
                    rx += hv.x; ry += hv.y;
                }
                *reinterpret_cast<float2*>(C + (size_t)row0 * N + col) =
                    make_float2(acc[mf][nf][0] + rx, acc[mf][nf][1] + ry);
            }
            if (row0 + 8 < M) {
                float rx = bx, ry = by;
                if (RESID) {
                    float2 hv = *reinterpret_cast<const float2*>(
                        Hres + (size_t)(row0 + 8) * N + col);
                    rx += hv.x; ry += hv.y;
                }
                *reinterpret_cast<float2*>(C + (size_t)(row0 + 8) * N + col) =
                    make_float2(acc[mf][nf][2] + rx, acc[mf][nf][3] + ry);
            }
        }
    }
}

// ------------------------- launch --------------------------------------------
extern "C" void kernel_launch(void* const* d_in, const int* in_sizes, int n_in,
                              void* d_out, int out_size) {
    (void)in_sizes; (void)n_in; (void)out_size;
    const int*   x    = (const int*)  d_in[0];
    const int*   eidx = (const int*)  d_in[1];
    const int*   et   = (const int*)  d_in[2];
    const float* emb  = (const float*)d_in[3];
    const float* rel1 = (const float*)d_in[4];
    const float* Wn1  = (const float*)d_in[7];
    const float* bn1  = (const float*)d_in[8];
    const float* cw1  = (const float*)d_in[9];
    const float* gm1  = (const float*)d_in[10];
    const float* bt1  = (const float*)d_in[11];
    const float* rel2 = (const float*)d_in[12];
    const float* Wr2  = (const float*)d_in[13];
    const float* br2  = (const float*)d_in[14];
    const float* Wn2  = (const float*)d_in[15];
    const float* bn2  = (const float*)d_in[16];
    const float* cw2  = (const float*)d_in[17];
    const float* gm2  = (const float*)d_in[18];
    const float* bt2  = (const float*)d_in[19];

    float* out_h    = (float*)d_out;
    float* out_rels = out_h + (size_t)N_NODES * DIM;
    const int* src = eidx;
    const int* dst = eidx + N_EDGES;

    float *pH, *pZ, *pTw, *pWt, *pWi, *pW;
    __nv_bfloat16 *pHChi, *pHClo, *pWhi, *pWlo, *pR2hi, *pR2lo;
    __half2 *pHH, *pHSH, *pRH, *pRSH;
    int *pDeg, *pOff, *pPos, *pDh, *pPerm;
    int2* pEdges;
    cudaGetSymbolAddress((void**)&pH,    g_h);
    cudaGetSymbolAddress((void**)&pZ,    g_Z);
    cudaGetSymbolAddress((void**)&pHChi, g_HChi);
    cudaGetSymbolAddress((void**)&pHClo, g_HClo);
    cudaGetSymbolAddress((void**)&pWhi,  g_Whi);
    cudaGetSymbolAddress((void**)&pWlo,  g_Wlo);
    cudaGetSymbolAddress((void**)&pR2hi, g_R2hi);
    cudaGetSymbolAddress((void**)&pR2lo, g_R2lo);
    cudaGetSymbolAddress((void**)&pHH,   g_hH);
    cudaGetSymbolAddress((void**)&pHSH,  g_HSH);
    cudaGetSymbolAddress((void**)&pRH,   g_rH);
    cudaGetSymbolAddress((void**)&pRSH,  g_RSH);
    cudaGetSymbolAddress((void**)&pTw,   g_tw);
    cudaGetSymbolAddress((void**)&pWt,   g_wt);
    cudaGetSymbolAddress((void**)&pWi,   g_wi);
    cudaGetSymbolAddress((void**)&pW,    g_w);
    cudaGetSymbolAddress((void**)&pDeg,  g_deg);
    cudaGetSymbolAddress((void**)&pOff,  g_off);
    cudaGetSymbolAddress((void**)&pPos,  g_pos);
    cudaGetSymbolAddress((void**)&pDh,   g_dh);
    cudaGetSymbolAddress((void**)&pPerm, g_perm);
    cudaGetSymbolAddress((void**)&pEdges, g_edges);

    const float2* tw = (const float2*)pTw;
    const float2* wt = (const float2*)pWt;
    const float2* wi = (const float2*)pWi;
    __half2* pRH1  = pRH;
    __half2* pRH2  = pRH  + (size_t)NRELS * HROW2;
    __half2* pRSH1 = pRSH;
    __half2* pRSH2 = pRSH + (size_t)NRELS * SROW2;

    setup_kernel<<<(N_NODES + 255) / 256, 256>>>(pTw, pWt, pWi, cw1, cw2, pW, pDeg);
    hist_kernel<<<(N_EDGES + 255) / 256, 256>>>(dst, pDeg);
    scan_kernel<<<1, 1024>>>(pDeg, pOff, pPos, pDh);
    scatter_perm_kernel<<<(N_EDGES + 255) / 256, 256>>>(src, dst, et, pDeg,
                                                        pPos, pDh, pEdges, pPerm);

    const int SPLIT_N = 3 * (DIM * DIM / 4) + NRELS * DIM / 4;
    split_all_kernel<<<(SPLIT_N + 255) / 256, 256>>>(
        Wn1, Wn2, Wr2, rel2, pWhi, pWlo, pR2hi, pR2lo);

    rel_fft2_kernel<<<2 * NRELS / 4, 256>>>(rel1, rel2, pRH1, pRSH1, pRH2, pRSH2,
                                            tw, wt);

    gather_fft_kernel<<<N_NODES / 4, 256>>>(x, emb, pH, pHH, pHSH, tw, wt);

    for (int L = 0; L < 2; L++) {
        const float* bn = (L == 0) ? bn1 : bn2;
        const float* gm = (L == 0) ? gm1 : gm2;
        const float* bt = (L == 0) ? bt1 : bt2;
        __half2* rH  = (L == 0) ? pRH1  : pRH2;
        __half2* RSH = (L == 0) ? pRSH1 : pRSH2;
        const __nv_bfloat16* Whi = pWhi + (size_t)L * DIM * DIM;
        const __nv_bfloat16* Wlo = pWlo + (size_t)L * DIM * DIM;

        agg_inv_kernel<<<N_NODES / 4, 256>>>(pEdges, pOff, pPerm, pHH, pHSH,
                                             rH, RSH, pW, 3 * L, pHChi, pHClo,
                                             tw, wi);
        bf16s_gemm<true, true><<<dim3(2, (N_NODES + 127) / 128), 256>>>(
            pHChi, pHClo, Whi, Wlo, pZ, bn, pH, N_NODES, DIM, DIM);
        if (L == 0) {
            epilogue_fft_kernel<true><<<N_NODES / 4, 256>>>(
                pZ, gm, bt, pH, pHH, pHSH, tw, wt);
        } else {
            epilogue_fft_kernel<false><<<N_NODES / 4, 256>>>(
                pZ, gm, bt, out_h, nullptr, nullptr, tw, wt);
        }
    }

    bf16s_gemm<true, false><<<dim3(2, (NRELS + 127) / 128), 256>>>(
        pR2hi, pR2lo, pWhi + 2 * DIM * DIM, pWlo + 2 * DIM * DIM,
        out_rels, br2, nullptr, NRELS, DIM, DIM);
}

// round 11
// speedup vs baseline: 1.1213x; 1.0242x over previous
#include <cuda_runtime.h>
#include <cuda_bf16.h>
#include <cuda_fp16.h>
#include <math.h>
#include <stdint.h>

#define N_NODES 50000
#define N_EDGES 250000
#define DIM     256
#define NRELS   400
#define HROW2   128     // h row: 128 half2 (256 vals) = 512 B
#define SROW2   132     // spec row: 129 bins as half2 + 3 pad = 528 B (16B-aligned)
#define SROW4   33      // spec row in uint4
#define LN_EPS  1e-5f
#define DBINS   64

// ------------------------- scratch (device globals) --------------------------
__device__ float   g_h  [(size_t)N_NODES * DIM];
__device__ float   g_Z  [(size_t)N_NODES * DIM];
__device__ __nv_bfloat16 g_HChi[(size_t)N_NODES * DIM];
__device__ __nv_bfloat16 g_HClo[(size_t)N_NODES * DIM];
__device__ __nv_bfloat16 g_Whi [3 * DIM * DIM];
__device__ __nv_bfloat16 g_Wlo [3 * DIM * DIM];
__device__ __nv_bfloat16 g_R2hi[NRELS * DIM];
__device__ __nv_bfloat16 g_R2lo[NRELS * DIM];
__device__ __half2 g_hH [(size_t)N_NODES * HROW2];
__device__ __half2 g_HSH[(size_t)N_NODES * SROW2];
__device__ __half2 g_rH [2][(size_t)NRELS * HROW2];
__device__ __half2 g_RSH[2][(size_t)NRELS * SROW2];
__device__ float   g_tw [7 * 64 * 2];
__device__ float   g_wt [129 * 2];
__device__ float   g_wi [129 * 2];
__device__ float   g_w  [6];
__device__ int     g_deg[N_NODES];
__device__ int     g_off[N_NODES + 1];
__device__ int     g_pos[N_NODES];
__device__ int     g_dh [DBINS];
__device__ int     g_perm[N_NODES];
__device__ int2    g_edges[N_EDGES];

// ------------------------- small helpers -------------------------------------
__device__ __forceinline__ float2 cmulf(float2 a, float2 b) {
    return make_float2(a.x * b.x - a.y * b.y, a.x * b.y + a.y * b.x);
}
// 8 halves (uint4) -> 8 floats
__device__ __forceinline__ void cvt8(uint4 u, float* f) {
    __half2* p = reinterpret_cast<__half2*>(&u);
#pragma unroll
    for (int i = 0; i < 4; i++) {
        float2 x = __half22float2(p[i]);
        f[2 * i] = x.x; f[2 * i + 1] = x.y;
    }
}

// ------------------------- fused setup kernel --------------------------------
__global__ void setup_kernel(float* tw, float* wt, float* wi,
                             const float* __restrict__ cw1,
                             const float* __restrict__ cw2, float* w,
                             int* deg) {
    int i = blockIdx.x * blockDim.x + threadIdx.x;
    if (i < 7 * 64) {
        int s = i >> 6, j = i & 63;
        int l = 64 >> s;
        float2 v = make_float2(0.f, 0.f);
        if (j < l) {
            double a = (double)j / (double)l;
            v = make_float2((float)cospi(a), (float)sinpi(a));
        }
        reinterpret_cast<float2*>(tw)[i] = v;
    }
    if (i < 129) {
        double a = (double)i / 128.0;
        reinterpret_cast<float2*>(wt)[i] = make_float2((float)cospi(a), (float)(-sinpi(a)));
        reinterpret_cast<float2*>(wi)[i] = make_float2((float)cospi(a), (float)( sinpi(a)));
    }
    if (i == 0) {
        for (int L = 0; L < 2; L++) {
            const float* c = (L == 0) ? cw1 : cw2;
            float m = fmaxf(c[0], fmaxf(c[1], c[2]));
            float e0 = expf(c[0] - m), e1 = expf(c[1] - m), e2 = expf(c[2] - m);
            float s = e0 + e1 + e2;
            w[L * 3 + 0] = e0 / s; w[L * 3 + 1] = e1 / s; w[L * 3 + 2] = e2 / s;
        }
    }
    if (i < N_NODES) deg[i] = 0;
}

// ------------------------- fp32 -> bf16 hi/lo split --------------------------
__global__ void split_all_kernel(const float* __restrict__ Wn1,
                                 const float* __restrict__ Wn2,
                                 const float* __restrict__ Wr2,
                                 const float* __restrict__ rel2,
                                 __nv_bfloat16* __restrict__ Whi,
                                 __nv_bfloat16* __restrict__ Wlo,
                                 __nv_bfloat16* __restrict__ R2hi,
                                 __nv_bfloat16* __restrict__ R2lo) {
    const int W4 = DIM * DIM / 4;
    const int R4 = NRELS * DIM / 4;
    int i = blockIdx.x * blockDim.x + threadIdx.x;
    const float* src; __nv_bfloat16 *hi, *lo; int idx;
    if (i < W4)            { src = Wn1;  hi = Whi;                 lo = Wlo;                 idx = i; }
    else if (i < 2 * W4)   { src = Wn2;  hi = Whi + DIM * DIM;     lo = Wlo + DIM * DIM;     idx = i - W4; }
    else if (i < 3 * W4)   { src = Wr2;  hi = Whi + 2 * DIM * DIM; lo = Wlo + 2 * DIM * DIM; idx = i - 2 * W4; }
    else if (i < 3 * W4 + R4) { src = rel2; hi = R2hi;             lo = R2lo;                idx = i - 3 * W4; }
    else return;
    float4 v = reinterpret_cast<const float4*>(src)[idx];
    float f[4] = {v.x, v.y, v.z, v.w};
    __nv_bfloat16 h[4], l[4];
#pragma unroll
    for (int j = 0; j < 4; j++) {
        h[j] = __float2bfloat16(f[j]);
        l[j] = __float2bfloat16(f[j] - __bfloat162float(h[j]));
    }
    reinterpret_cast<uint2*>(hi)[idx] = *reinterpret_cast<uint2*>(h);
    reinterpret_cast<uint2*>(lo)[idx] = *reinterpret_cast<uint2*>(l);
}

// ------------------------- edge sorting --------------------------------------
__global__ void hist_kernel(const int* __restrict__ dst, int* deg) {
    int e = blockIdx.x * blockDim.x + threadIdx.x;
    if (e < N_EDGES) atomicAdd(&deg[dst[e]], 1);
}
__global__ __launch_bounds__(1024)
void scan_kernel(const int* __restrict__ deg, int* off, int* pos, int* dh) {
    __shared__ int ps[1024];
    __shared__ int dsh[DBINS];
    int t = threadIdx.x;
    if (t < DBINS) dsh[t] = 0;
    __syncthreads();
    const int CH = (N_NODES + 1023) / 1024;
    int b0 = t * CH, b1 = min(b0 + CH, N_NODES);
    int s = 0;
    for (int i = b0; i < b1; i++) {
        int d = deg[i];
        s += d;
        atomicAdd(&dsh[min(d, DBINS - 1)], 1);
    }
    ps[t] = s;
    __syncthreads();
    for (int o = 1; o < 1024; o <<= 1) {
        int u = (t >= o) ? ps[t - o] : 0;
        __syncthreads();
        ps[t] += u;
        __syncthreads();
    }
    int run = ps[t] - s;
    for (int i = b0; i < b1; i++) {
        off[i] = run; pos[i] = run; run += deg[i];
    }
    if (t == 1023) off[N_NODES] = ps[1023];
    if (t == 0) {
        int acc = 0;
        for (int b = 0; b < DBINS; b++) { int c = dsh[b]; dh[b] = acc; acc += c; }
    }
}
__global__ void scatter_perm_kernel(const int* __restrict__ src,
                                    const int* __restrict__ dst,
                                    const int* __restrict__ et,
                                    const int* __restrict__ deg,
                                    int* pos, int* dh,
                                    int2* edges, int* perm) {
    int e = blockIdx.x * blockDim.x + threadIdx.x;
    if (e < N_EDGES) {
        int p = atomicAdd(&pos[dst[e]], 1);
        edges[p] = make_int2(src[e], et[e]);
    }
    if (e < N_NODES) {
        int p = atomicAdd(&dh[min(deg[e], DBINS - 1)], 1);
        perm[p] = e;
    }
}

// ------------------------- 128-pt Stockham FFT (64 threads/row) --------------
__device__ __forceinline__ void fft128(float2* b0, float2* b1, int t, float sgn,
                                       const float2* __restrict__ tw) {
    float2* src = b0;
    float2* dst = b1;
#pragma unroll
    for (int s = 0; s < 7; s++) {
        int m = 1 << s;
        int j = t >> s;
        float2 w = tw[(s << 6) + j];
        w.y *= sgn;
        float2 c0 = src[t];
        float2 c1 = src[t + 64];
        float2 sum = make_float2(c0.x + c1.x, c0.y + c1.y);
        float2 d   = make_float2(c0.x - c1.x, c0.y - c1.y);
        int idx = (t & (m - 1)) | ((t >> s) << (s + 1));
        dst[idx]     = sum;
        dst[idx + m] = cmulf(d, w);
        float2* tmp = src; src = dst; dst = tmp;
        __syncthreads();
    }
}

// forward untangle -> fp16 spectrum row
__device__ __forceinline__ void untangle_store_h(
    float2* Z, __half2* Srow, int t, const float2* __restrict__ wt) {
#pragma unroll
    for (int u = 0; u < 2; u++) {
        int k = t + 64 * u;
        float2 Zk = Z[k];
        float2 Zm = Z[(128 - k) & 127];
        float2 Ze = make_float2(0.5f * (Zk.x + Zm.x), 0.5f * (Zk.y - Zm.y));
        float2 d  = make_float2(Zk.x - Zm.x, Zk.y + Zm.y);
        float2 Zo = make_float2(0.5f * d.y, -0.5f * d.x);
        float2 W  = wt[k];
        float2 H  = make_float2(Ze.x + W.x * Zo.x - W.y * Zo.y,
                                Ze.y + W.x * Zo.y + W.y * Zo.x);
        Srow[k] = __float22half2_rn(H);
    }
    if (t == 0) {
        float2 Z0 = Z[0];
        Srow[128] = __float22half2_rn(make_float2(Z0.x - Z0.y, 0.f));
    }
}

// ------------------------- gather + forward rfft (fused) ---------------------
__global__ __launch_bounds__(256)
void gather_fft_kernel(const int* __restrict__ x, const float* __restrict__ emb,
                       float* __restrict__ h, __half2* __restrict__ hH,
                       __half2* __restrict__ SH,
                       const float2* __restrict__ tw, const float2* __restrict__ wt) {
    __shared__ float2 buf[4][2][128];
    int g = threadIdx.x >> 6, t = threadIdx.x & 63;
    int row = (blockIdx.x << 2) + g;
    float4 v = reinterpret_cast<const float4*>(emb + (size_t)x[row] * DIM)[t];
    reinterpret_cast<float4*>(h + (size_t)row * DIM)[t] = v;
    __half2 p0 = __float22half2_rn(make_float2(v.x, v.y));
    __half2 p1 = __float22half2_rn(make_float2(v.z, v.w));
    *reinterpret_cast<uint2*>(hH + (size_t)row * HROW2 + 2 * t) =
        make_uint2(*reinterpret_cast<uint32_t*>(&p0), *reinterpret_cast<uint32_t*>(&p1));
    buf[g][0][2 * t]     = make_float2(v.x, v.y);
    buf[g][0][2 * t + 1] = make_float2(v.z, v.w);
    __syncthreads();
    fft128(buf[g][0], buf[g][1], t, -1.f, tw);
    untangle_store_h(buf[g][1], SH + (size_t)row * SROW2, t, wt);
}

// --------------- rel tables fft -> fp16 copies (both layers) -----------------
__global__ __launch_bounds__(256)
void rel_fft2_kernel(const float* __restrict__ rel1, const float* __restrict__ rel2,
                     __half2* __restrict__ rH1,  __half2* __restrict__ RSH1,
                     __half2* __restrict__ rH2,  __half2* __restrict__ RSH2,
                     const float2* __restrict__ tw, const float2* __restrict__ wt) {
    __shared__ float2 buf[4][2][128];
    int g = threadIdx.x >> 6, t = threadIdx.x & 63;
    int row = (blockIdx.x << 2) + g;
    const float* rel = (row < NRELS) ? rel1 : rel2;
    __half2* rH  = (row < NRELS) ? rH1  : rH2;
    __half2* RSH = (row < NRELS) ? RSH1 : RSH2;
    int r = (row < NRELS) ? row : row - NRELS;
    float4 v = reinterpret_cast<const float4*>(rel + (size_t)r * DIM)[t];
    __half2 p0 = __float22half2_rn(make_float2(v.x, v.y));
    __half2 p1 = __float22half2_rn(make_float2(v.z, v.w));
    *reinterpret_cast<uint2*>(rH + (size_t)r * HROW2 + 2 * t) =
        make_uint2(*reinterpret_cast<uint32_t*>(&p0), *reinterpret_cast<uint32_t*>(&p1));
    buf[g][0][2 * t]     = make_float2(v.x, v.y);
    buf[g][0][2 * t + 1] = make_float2(v.z, v.w);
    __syncthreads();
    fft128(buf[g][0], buf[g][1], t, -1.f, tw);
    untangle_store_h(buf[g][1], RSH + (size_t)r * SROW2, t, wt);
}

// --------------- aggregation + inverse rfft (WARP per node) ------------------
// 8 nodes per 256-thread block, one warp each. Lane t owns time cols 8t..8t+7
// (one uint4 of the fp16 row) and spectral bins 4t..4t+3 (one uint4).
// Inverse FFT runs with 32 threads + __syncwarp only -> no block convoy.
__global__ __launch_bounds__(256, 3)
void agg_inv_kernel(const int2* __restrict__ edges, const int* __restrict__ off,
                    const int* __restrict__ perm,
                    const __half2* __restrict__ hH,  const __half2* __restrict__ HSH,
                    const __half2* __restrict__ rH, const __half2* __restrict__ RSH,
                    const float* __restrict__ w, int wofs,
                    __nv_bfloat16* __restrict__ HChi,
                    __nv_bfloat16* __restrict__ HClo,
                    const float2* __restrict__ tw, const float2* __restrict__ wi) {
    __shared__ float2 buf[8][2][132];
    int wl = threadIdx.x >> 5, t = threadIdx.x & 31;
    int v = perm[(blockIdx.x << 3) + wl];
    float w0 = w[wofs + 0], w1 = w[wofs + 1], w2 = w[wofs + 2];

    const uint4* hH4 = reinterpret_cast<const uint4*>(hH);
    const uint4* rH4 = reinterpret_cast<const uint4*>(rH);
    const uint4* HS4 = reinterpret_cast<const uint4*>(HSH);
    const uint4* RS4 = reinterpret_cast<const uint4*>(RSH);

    float T[8], Rs[8], F[8];
    float hv[8], rv[8], av[8], bv[8];

    // self-loop (rel type 0)
    cvt8(hH4[(size_t)v * 32 + t], hv);
    cvt8(rH4[t], rv);
#pragma unroll
    for (int i = 0; i < 8; i++) {
        Rs[i] = rv[i];
        T[i]  = hv[i] * fmaf(w0, rv[i], w1);
    }
    cvt8(HS4[(size_t)v * SROW4 + t], av);
    cvt8(RS4[t], bv);
#pragma unroll
    for (int i = 0; i < 4; i++) {
        F[2 * i]     = av[2 * i] * bv[2 * i] + av[2 * i + 1] * bv[2 * i + 1];
        F[2 * i + 1] = av[2 * i + 1] * bv[2 * i] - av[2 * i] * bv[2 * i + 1];
    }
    float2 Ft = make_float2(0.f, 0.f);
    if (t == 0) {
        float2 a = __half22float2(HSH[(size_t)v * SROW2 + 128]);
        float2 b = __half22float2(RSH[128]);
        Ft = make_float2(a.x * b.x + a.y * b.y, a.y * b.x - a.x * b.y);
    }

    int e = off[v], e1 = off[v + 1];
    for (; e + 1 < e1; e += 2) {
        int2 ea = edges[e];
        int2 eb = edges[e + 1];
        uint4 ha = hH4[(size_t)ea.x * 32 + t];
        uint4 ra = rH4[(size_t)ea.y * 32 + t];
        uint4 sa = HS4[(size_t)ea.x * SROW4 + t];
        uint4 ta = RS4[(size_t)ea.y * SROW4 + t];
        uint4 hb = hH4[(size_t)eb.x * 32 + t];
        uint4 rb = rH4[(size_t)eb.y * 32 + t];
        uint4 sb = HS4[(size_t)eb.x * SROW4 + t];
        uint4 tb = RS4[(size_t)eb.y * SROW4 + t];
        cvt8(ha, hv); cvt8(ra, rv);
#pragma unroll
        for (int i = 0; i < 8; i++) {
            Rs[i] += rv[i];
            T[i] = fmaf(hv[i], fmaf(w0, rv[i], w1), T[i]);
        }
        cvt8(sa, av); cvt8(ta, bv);
#pragma unroll
        for (int i = 0; i < 4; i++) {
            F[2 * i]     += av[2 * i] * bv[2 * i] + av[2 * i + 1] * bv[2 * i + 1];
            F[2 * i + 1] += av[2 * i + 1] * bv[2 * i] - av[2 * i] * bv[2 * i + 1];
        }
        cvt8(hb, hv); cvt8(rb, rv);
#pragma unroll
        for (int i = 0; i < 8; i++) {
            Rs[i] += rv[i];
            T[i] = fmaf(hv[i], fmaf(w0, rv[i], w1), T[i]);
        }
        cvt8(sb, av); cvt8(tb, bv);
#pragma unroll
        for (int i = 0; i < 4; i++) {
            F[2 * i]     += av[2 * i] * bv[2 * i] + av[2 * i + 1] * bv[2 * i + 1];
            F[2 * i + 1] += av[2 * i + 1] * bv[2 * i] - av[2 * i] * bv[2 * i + 1];
        }
        if (t == 0) {
            float2 a0 = __half22float2(HSH[(size_t)ea.x * SROW2 + 128]);
            float2 b0 = __half22float2(RSH[(size_t)ea.y * SROW2 + 128]);
            float2 a1 = __half22float2(HSH[(size_t)eb.x * SROW2 + 128]);
            float2 b1 = __half22float2(RSH[(size_t)eb.y * SROW2 + 128]);
            Ft.x += a0.x * b0.x + a0.y * b0.y + a1.x * b1.x + a1.y * b1.y;
            Ft.y += a0.y * b0.x - a0.x * b0.y + a1.y * b1.x - a1.x * b1.y;
        }
    }
    if (e < e1) {
        int2 ed = edges[e];
        uint4 ha = hH4[(size_t)ed.x * 32 + t];
        uint4 ra = rH4[(size_t)ed.y * 32 + t];
        uint4 sa = HS4[(size_t)ed.x * SROW4 + t];
        uint4 ta = RS4[(size_t)ed.y * SROW4 + t];
        cvt8(ha, hv); cvt8(ra, rv);
#pragma unroll
        for (int i = 0; i < 8; i++) {
            Rs[i] += rv[i];
            T[i] = fmaf(hv[i], fmaf(w0, rv[i], w1), T[i]);
        }
        cvt8(sa, av); cvt8(ta, bv);
#pragma unroll
        for (int i = 0; i < 4; i++) {
            F[2 * i]     += av[2 * i] * bv[2 * i] + av[2 * i + 1] * bv[2 * i + 1];
            F[2 * i + 1] += av[2 * i + 1] * bv[2 * i] - av[2 * i] * bv[2 * i + 1];
        }
        if (t == 0) {
            float2 a = __half22float2(HSH[(size_t)ed.x * SROW2 + 128]);
            float2 b = __half22float2(RSH[(size_t)ed.y * SROW2 + 128]);
            Ft.x += a.x * b.x + a.y * b.y;
            Ft.y += a.y * b.x - a.x * b.y;
        }
    }

    // stage spectrum (scaled by w2) into per-warp smem
    float2* sA = buf[wl][1];
#pragma unroll
    for (int i = 0; i < 4; i++)
        sA[4 * t + i] = make_float2(w2 * F[2 * i], w2 * F[2 * i + 1]);
    if (t == 0) sA[128] = make_float2(w2 * Ft.x, w2 * Ft.y);
    __syncwarp();

    // inverse untangle -> packed complex in buf[wl][0]
    float2* pk = buf[wl][0];
#pragma unroll
    for (int u = 0; u < 4; u++) {
        int k = t + 32 * u;
        float2 Ak = sA[k], Am = sA[128 - k];
        float2 Ze = make_float2(0.5f * (Ak.x + Am.x), 0.5f * (Ak.y - Am.y));
        float2 hd = make_float2(0.5f * (Ak.x - Am.x), 0.5f * (Ak.y + Am.y));
        float2 Zo = cmulf(wi[k], hd);
        pk[k] = make_float2(Ze.x - Zo.y, Ze.y + Zo.x);
    }
    __syncwarp();

    // 128-pt inverse Stockham FFT, 32 threads (2 butterflies/thread/stage)
    float2* src = buf[wl][0];
    float2* dst = buf[wl][1];
#pragma unroll
    for (int s = 0; s < 7; s++) {
        int m = 1 << s;
#pragma unroll
        for (int u = 0; u < 2; u++) {
            int tt = t + 32 * u;
            float2 wv = tw[(s << 6) + (tt >> s)];   // sgn = +1 (inverse)
            float2 c0 = src[tt];
            float2 c1 = src[tt + 64];
            float2 sum = make_float2(c0.x + c1.x, c0.y + c1.y);
            float2 d   = make_float2(c0.x - c1.x, c0.y - c1.y);
            int idx = (tt & (m - 1)) | ((tt >> s) << (s + 1));
            dst[idx]     = sum;
            dst[idx + m] = cmulf(d, wv);
        }
        float2* tmp = src; src = dst; dst = tmp;
        __syncwarp();
    }
    // result is in src after final swap

    const float inv = 1.f / 128.f;
    float o[8];
#pragma unroll
    for (int i = 0; i < 4; i++) {
        float2 z = src[4 * t + i];
        o[2 * i]     = fmaf(w1, Rs[2 * i],     T[2 * i])     + z.x * inv;
        o[2 * i + 1] = fmaf(w1, Rs[2 * i + 1], T[2 * i + 1]) + z.y * inv;
    }
    __nv_bfloat16 hi8[8], lo8[8];
#pragma unroll
    for (int j = 0; j < 8; j++) {
        hi8[j] = __float2bfloat16(o[j]);
        lo8[j] = __float2bfloat16(o[j] - __bfloat162float(hi8[j]));
    }
    reinterpret_cast<uint4*>(HChi + (size_t)v * DIM)[t] = *reinterpret_cast<uint4*>(hi8);
    reinterpret_cast<uint4*>(HClo + (size_t)v * DIM)[t] = *reinterpret_cast<uint4*>(lo8);
}

// --------- LN + ReLU (input Z already = gemm+bias+resid), optional fft -------
template<bool DO_FFT>
__global__ __launch_bounds__(256)
void epilogue_fft_kernel(const float* __restrict__ Z,
                         const float* __restrict__ gamma,
                         const float* __restrict__ beta,
                         float* __restrict__ h_out,
                         __half2* __restrict__ hH,
                         __half2* __restrict__ SH,
                         const float2* __restrict__ tw,
                         const float2* __restrict__ wt) {
    __shared__ float2 buf[4][2][128];
    __shared__ float sred[4][2];
    int g = threadIdx.x >> 6, t = threadIdx.x & 63;
    int wsub = t >> 5;
    int v = (blockIdx.x << 2) + g;

    float4 z = reinterpret_cast<const float4*>(Z + (size_t)v * DIM)[t];
    float s = z.x + z.y + z.z + z.w;
#pragma unroll
    for (int ofs = 16; ofs; ofs >>= 1) s += __shfl_xor_sync(0xffffffffu, s, ofs);
    if ((t & 31) == 0) sred[g][wsub] = s;
    __syncthreads();
    float mu = (sred[g][0] + sred[g][1]) * (1.f / DIM);
    __syncthreads();
    float4 zc = make_float4(z.x - mu, z.y - mu, z.z - mu, z.w - mu);
    float vv = zc.x * zc.x + zc.y * zc.y + zc.z * zc.z + zc.w * zc.w;
#pragma unroll
    for (int ofs = 16; ofs; ofs >>= 1) vv += __shfl_xor_sync(0xffffffffu, vv, ofs);
    if ((t & 31) == 0) sred[g][wsub] = vv;
    __syncthreads();
    float rstd = rsqrtf((sred[g][0] + sred[g][1]) * (1.f / DIM) + LN_EPS);
    float4 gm = reinterpret_cast<const float4*>(gamma)[t];
    float4 bt = reinterpret_cast<const float4*>(beta)[t];
    float4 y = make_float4(fmaxf(zc.x * rstd * gm.x + bt.x, 0.f),
                           fmaxf(zc.y * rstd * gm.y + bt.y, 0.f),
                           fmaxf(zc.z * rstd * gm.z + bt.z, 0.f),
                           fmaxf(zc.w * rstd * gm.w + bt.w, 0.f));
    reinterpret_cast<float4*>(h_out + (size_t)v * DIM)[t] = y;
    if (DO_FFT) {
        __half2 p0 = __float22half2_rn(make_float2(y.x, y.y));
        __half2 p1 = __float22half2_rn(make_float2(y.z, y.w));
        *reinterpret_cast<uint2*>(hH + (size_t)v * HROW2 + 2 * t) =
            make_uint2(*reinterpret_cast<uint32_t*>(&p0), *reinterpret_cast<uint32_t*>(&p1));
        buf[g][0][2 * t]     = make_float2(y.x, y.y);
        buf[g][0][2 * t + 1] = make_float2(y.z, y.w);
        __syncthreads();
        fft128(buf[g][0], buf[g][1], t, -1.f, tw);
        untangle_store_h(buf[g][1], SH + (size_t)v * SROW2, t, wt);
    }
}

// ------------------------- bf16x3 GEMM with pre-split operands ---------------
#define GBK 32
#define GPAD 8
#define GLDW (GBK + GPAD)

__device__ __forceinline__ void mma_bf16(float* d,
    uint32_t a0, uint32_t a1, uint32_t a2, uint32_t a3,
    uint32_t b0, uint32_t b1) {
    asm volatile(
        "mma.sync.aligned.m16n8k16.row.col.f32.bf16.bf16.f32 "
        "{%0,%1,%2,%3}, {%4,%5,%6,%7}, {%8,%9}, {%0,%1,%2,%3};"
        : "+f"(d[0]), "+f"(d[1]), "+f"(d[2]), "+f"(d[3])
        : "r"(a0), "r"(a1), "r"(a2), "r"(a3), "r"(b0), "r"(b1));
}

template<bool BIAS, bool RESID>
__global__ __launch_bounds__(256)
void bf16s_gemm(const __nv_bfloat16* __restrict__ Ahi,
                const __nv_bfloat16* __restrict__ Alo,
                const __nv_bfloat16* __restrict__ Bhi,
                const __nv_bfloat16* __restrict__ Blo,
                float* __restrict__ C, const float* __restrict__ bias,
                const float* __restrict__ Hres,
                int M, int N, int K) {
    __shared__ __align__(16) __nv_bfloat16 Ah[128 * GLDW];
    __shared__ __align__(16) __nv_bfloat16 Al[128 * GLDW];
    __shared__ __align__(16) __nv_bfloat16 Bh[128 * GLDW];
    __shared__ __align__(16) __nv_bfloat16 Bl[128 * GLDW];

    int tid = threadIdx.x;
    int lane = tid & 31, wid = tid >> 5;
    int wm = wid & 1, wn = wid >> 1;
    int r = lane >> 2, cq = lane & 3;
    int bm = blockIdx.y * 128, bn = blockIdx.x * 128;

    float acc[4][4][4];
#pragma unroll
    for (int a = 0; a < 4; a++)
#pragma unroll
        for (int b = 0; b < 4; b++)
#pragma unroll
            for (int c = 0; c < 4; c++) acc[a][b][c] = 0.f;

    int lrow[2], lcol[2];
#pragma unroll
    for (int j = 0; j < 2; j++) {
        int idx = tid + 256 * j;
        lrow[j] = idx >> 2; lcol[j] = (idx & 3) << 3;
    }

    uint4 rah[2], ral[2], rbh[2], rbl[2];
    const uint4 z4 = make_uint4(0, 0, 0, 0);

    auto load_tile = [&](int k0) {
#pragma unroll
        for (int j = 0; j < 2; j++) {
            size_t ao = (size_t)(bm + lrow[j]) * K + k0 + lcol[j];
            size_t bo = (size_t)(bn + lrow[j]) * K + k0 + lcol[j];
            bool av = (bm + lrow[j] < M), bv = (bn + lrow[j] < N);
            rah[j] = av ? *reinterpret_cast<const uint4*>(Ahi + ao) : z4;
            ral[j] = av ? *reinterpret_cast<const uint4*>(Alo + ao) : z4;
            rbh[j] = bv ? *reinterpret_cast<const uint4*>(Bhi + bo) : z4;
            rbl[j] = bv ? *reinterpret_cast<const uint4*>(Blo + bo) : z4;
        }
    };
    auto stage_tile = [&]() {
#pragma unroll
        for (int j = 0; j < 2; j++) {
            int so = lrow[j] * GLDW + lcol[j];
            *reinterpret_cast<uint4*>(&Ah[so]) = rah[j];
            *reinterpret_cast<uint4*>(&Al[so]) = ral[j];
            *reinterpret_cast<uint4*>(&Bh[so]) = rbh[j];
            *reinterpret_cast<uint4*>(&Bl[so]) = rbl[j];
        }
    };

    load_tile(0);
    for (int k0 = 0; k0 < K; k0 += GBK) {
        stage_tile();
        __syncthreads();
        if (k0 + GBK < K) load_tile(k0 + GBK);

#pragma unroll
        for (int ks = 0; ks < 2; ks++) {
            int kb = ks * 16 + cq * 2;
            uint32_t bhf[4][2], blf[4][2];
#pragma unroll
            for (int nf = 0; nf < 4; nf++) {
                int col = wn * 32 + nf * 8 + r;
                bhf[nf][0] = *reinterpret_cast<const uint32_t*>(&Bh[col * GLDW + kb]);
                bhf[nf][1] = *reinterpret_cast<const uint32_t*>(&Bh[col * GLDW + kb + 8]);
                blf[nf][0] = *reinterpret_cast<const uint32_t*>(&Bl[col * GLDW + kb]);
                blf[nf][1] = *reinterpret_cast<const uint32_t*>(&Bl[col * GLDW + kb + 8]);
            }
#pragma unroll
            for (int mf = 0; mf < 4; mf++) {
                int row = wm * 64 + mf * 16 + r;
                uint32_t a0 = *reinterpret_cast<const uint32_t*>(&Ah[row * GLDW + kb]);
                uint32_t a1 = *reinterpret_cast<const uint32_t*>(&Ah[(row + 8) * GLDW + kb]);
                uint32_t a2 = *reinterpret_cast<const uint32_t*>(&Ah[row * GLDW + kb + 8]);
                uint32_t a3 = *reinterpret_cast<const uint32_t*>(&Ah[(row + 8) * GLDW + kb + 8]);
                uint32_t l0 = *reinterpret_cast<const uint32_t*>(&Al[row * GLDW + kb]);
                uint32_t l1 = *reinterpret_cast<const uint32_t*>(&Al[(row + 8) * GLDW + kb]);
                uint32_t l2 = *reinterpret_cast<const uint32_t*>(&Al[row * GLDW + kb + 8]);
                uint32_t l3 = *reinterpret_cast<const uint32_t*>(&Al[(row + 8) * GLDW + kb + 8]);
#pragma unroll
                for (int nf = 0; nf < 4; nf++) {
                    mma_bf16(acc[mf][nf], a0, a1, a2, a3, bhf[nf][0], bhf[nf][1]);
                    mma_bf16(acc[mf][nf], a0, a1, a2, a3, blf[nf][0], blf[nf][1]);
                    mma_bf16(acc[mf][nf], l0, l1, l2, l3, bhf[nf][0], bhf[nf][1]);
                }
            }
        }
        __syncthreads();
    }

#pragma unroll
    for (int mf = 0; mf < 4; mf++) {
        int row0 = bm + wm * 64 + mf * 16 + r;
#pragma unroll
        for (int nf = 0; nf < 4; nf++) {
            int col = bn + wn * 32 + nf * 8 + cq * 2;
            float bx = 0.f, by = 0.f;
            if (BIAS) { bx = bias[col]; by = bias[col + 1]; }
            if (row0 < M) {
                float rx = bx, ry = by;
                if (RESID) {
                    float2 hv = *reinterpret_cast<const float2*>(
                        Hres + (size_t)row0 * N + col);
                    rx += hv.x; ry += hv.y;
                }
                *reinterpret_cast<float2*>(C + (size_t)row0 * N + col) =
                    make_float2(acc[mf][nf][0] + rx, acc[mf][nf][1] + ry);
            }
            if (row0 + 8 < M) {
                float rx = bx, ry = by;
                if (RESID) {
                    float2 hv = *reinterpret_cast<const float2*>(
                        Hres + (size_t)(row0 + 8) * N + col);
                    rx += hv.x; ry += hv.y;
                }
                *reinterpret_cast<float2*>(C + (size_t)(row0 + 8) * N + col) =
                    make_float2(acc[mf][nf][2] + rx, acc[mf][nf][3] + ry);
            }
        }
    }
}

// ------------------------- launch --------------------------------------------
extern "C" void kernel_launch(void* const* d_in, const int* in_sizes, int n_in,
                              void* d_out, int out_size) {
    (void)in_sizes; (void)n_in; (void)out_size;
    const int*   x    = (const int*)  d_in[0];
    const int*   eidx = (const int*)  d_in[1];
    const int*   et   = (const int*)  d_in[2];
    const float* emb  = (const float*)d_in[3];
    const float* rel1 = (const float*)d_in[4];
    const float* Wn1  = (const float*)d_in[7];
    const float* bn1  = (const float*)d_in[8];
    const float* cw1  = (const float*)d_in[9];
    const float* gm1  = (const float*)d_in[10];
    const float* bt1  = (const float*)d_in[11];
    const float* rel2 = (const float*)d_in[12];
    const float* Wr2  = (const float*)d_in[13];
    const float* br2  = (const float*)d_in[14];
    const float* Wn2  = (const float*)d_in[15];
    const float* bn2  = (const float*)d_in[16];
    const float* cw2  = (const float*)d_in[17];
    const float* gm2  = (const float*)d_in[18];
    const float* bt2  = (const float*)d_in[19];

    float* out_h    = (float*)d_out;
    float* out_rels = out_h + (size_t)N_NODES * DIM;
    const int* src = eidx;
    const int* dst = eidx + N_EDGES;

    float *pH, *pZ, *pTw, *pWt, *pWi, *pW;
    __nv_bfloat16 *pHChi, *pHClo, *pWhi, *pWlo, *pR2hi, *pR2lo;
    __half2 *pHH, *pHSH, *pRH, *pRSH;
    int *pDeg, *pOff, *pPos, *pDh, *pPerm;
    int2* pEdges;
    cudaGetSymbolAddress((void**)&pH,    g_h);
    cudaGetSymbolAddress((void**)&pZ,    g_Z);
    cudaGetSymbolAddress((void**)&pHChi, g_HChi);
    cudaGetSymbolAddress((void**)&pHClo, g_HClo);
    cudaGetSymbolAddress((void**)&pWhi,  g_Whi);
    cudaGetSymbolAddress((void**)&pWlo,  g_Wlo);
    cudaGetSymbolAddress((void**)&pR2hi, g_R2hi);
    cudaGetSymbolAddress((void**)&pR2lo, g_R2lo);
    cudaGetSymbolAddress((void**)&pHH,   g_hH);
    cudaGetSymbolAddress((void**)&pHSH,  g_HSH);
    cudaGetSymbolAddress((void**)&pRH,   g_rH);
    cudaGetSymbolAddress((void**)&pRSH,  g_RSH);
    cudaGetSymbolAddress((void**)&pTw,   g_tw);
    cudaGetSymbolAddress((void**)&pWt,   g_wt);
    cudaGetSymbolAddress((void**)&pWi,   g_wi);
    cudaGetSymbolAddress((void**)&pW,    g_w);
    cudaGetSymbolAddress((void**)&pDeg,  g_deg);
    cudaGetSymbolAddress((void**)&pOff,  g_off);
    cudaGetSymbolAddress((void**)&pPos,  g_pos);
    cudaGetSymbolAddress((void**)&pDh,   g_dh);
    cudaGetSymbolAddress((void**)&pPerm, g_perm);
    cudaGetSymbolAddress((void**)&pEdges, g_edges);

    const float2* tw = (const float2*)pTw;
    const float2* wt = (const float2*)pWt;
    const float2* wi = (const float2*)pWi;
    __half2* pRH1  = pRH;
    __half2* pRH2  = pRH  + (size_t)NRELS * HROW2;
    __half2* pRSH1 = pRSH;
    __half2* pRSH2 = pRSH + (size_t)NRELS * SROW2;

    setup_kernel<<<(N_NODES + 255) / 256, 256>>>(pTw, pWt, pWi, cw1, cw2, pW, pDeg);
    hist_kernel<<<(N_EDGES + 255) / 256, 256>>>(dst, pDeg);
    scan_kernel<<<1, 1024>>>(pDeg, pOff, pPos, pDh);
    scatter_perm_kernel<<<(N_EDGES + 255) / 256, 256>>>(src, dst, et, pDeg,
                                                        pPos, pDh, pEdges, pPerm);

    const int SPLIT_N = 3 * (DIM * DIM / 4) + NRELS * DIM / 4;
    split_all_kernel<<<(SPLIT_N + 255) / 256, 256>>>(
        Wn1, Wn2, Wr2, rel2, pWhi, pWlo, pR2hi, pR2lo);

    rel_fft2_kernel<<<2 * NRELS / 4, 256>>>(rel1, rel2, pRH1, pRSH1, pRH2, pRSH2,
                                            tw, wt);

    gather_fft_kernel<<<N_NODES / 4, 256>>>(x, emb, pH, pHH, pHSH, tw, wt);

    for (int L = 0; L < 2; L++) {
        const float* bn = (L == 0) ? bn1 : bn2;
        const float* gm = (L == 0) ? gm1 : gm2;
        const float* bt = (L == 0) ? bt1 : bt2;
        __half2* rH  = (L == 0) ? pRH1  : pRH2;
        __half2* RSH = (L == 0) ? pRSH1 : pRSH2;
        const __nv_bfloat16* Whi = pWhi + (size_t)L * DIM * DIM;
        const __nv_bfloat16* Wlo = pWlo + (size_t)L * DIM * DIM;

        agg_inv_kernel<<<N_NODES / 8, 256>>>(pEdges, pOff, pPerm, pHH, pHSH,
                                             rH, RSH, pW, 3 * L, pHChi, pHClo,
                                             tw, wi);
        bf16s_gemm<true, true><<<dim3(2, (N_NODES + 127) / 128), 256>>>(
            pHChi, pHClo, Whi, Wlo, pZ, bn, pH, N_NODES, DIM, DIM);
        if (L == 0) {
            epilogue_fft_kernel<true><<<N_NODES / 4, 256>>>(
                pZ, gm, bt, pH, pHH, pHSH, tw, wt);
        } else {
            epilogue_fft_kernel<false><<<N_NODES / 4, 256>>>(
                pZ, gm, bt, out_h, nullptr, nullptr, tw, wt);
        }
    }

    bf16s_gemm<true, false><<<dim3(2, (NRELS + 127) / 128), 256>>>(
        pR2hi, pR2lo, pWhi + 2 * DIM * DIM, pWlo + 2 * DIM * DIM,
        out_rels, br2, nullptr, NRELS, DIM, DIM);
}

// round 14
// speedup vs baseline: 1.1505x; 1.0260x over previous
#include <cuda_runtime.h>
#include <cuda_bf16.h>
#include <cuda_fp16.h>
#include <math.h>
#include <stdint.h>

#define N_NODES 50000
#define N_EDGES 250000
#define DIM     256
#define NRELS   400
#define HROW2   128     // h row: 128 half2 (256 vals) = 512 B
#define SROW2   132     // spec row: 129 bins as half2 + 3 pad = 528 B (16B-aligned)
#define SROW4   33      // spec row in uint4
#define LN_EPS  1e-5f
#define DBINS   64

// ------------------------- scratch (device globals) --------------------------
__device__ float   g_h  [(size_t)N_NODES * DIM];
__device__ float   g_Z  [(size_t)N_NODES * DIM];
__device__ __nv_bfloat16 g_HChi[(size_t)N_NODES * DIM];
__device__ __nv_bfloat16 g_HClo[(size_t)N_NODES * DIM];
__device__ __nv_bfloat16 g_Whi [3 * DIM * DIM];
__device__ __nv_bfloat16 g_Wlo [3 * DIM * DIM];
__device__ __nv_bfloat16 g_R2hi[NRELS * DIM];
__device__ __nv_bfloat16 g_R2lo[NRELS * DIM];
__device__ __half2 g_hH [(size_t)N_NODES * HROW2];
__device__ __half2 g_HSH[(size_t)N_NODES * SROW2];
__device__ __half2 g_rH [2][(size_t)NRELS * HROW2];
__device__ __half2 g_RSH[2][(size_t)NRELS * SROW2];
__device__ float   g_tw [7 * 64 * 2];
__device__ float   g_wt [129 * 2];
__device__ float   g_wi [129 * 2];
__device__ float   g_w  [6];
__device__ int     g_deg[N_NODES];
__device__ int     g_off[N_NODES + 1];
__device__ int     g_pos[N_NODES];
__device__ int     g_dh [DBINS];
__device__ int     g_perm[N_NODES];
__device__ int2    g_edges[N_EDGES];

// ------------------------- small helpers -------------------------------------
__device__ __forceinline__ float2 cmulf(float2 a, float2 b) {
    return make_float2(a.x * b.x - a.y * b.y, a.x * b.y + a.y * b.x);
}
__device__ __forceinline__ void cvt8(uint4 u, float* f) {
    __half2* p = reinterpret_cast<__half2*>(&u);
#pragma unroll
    for (int i = 0; i < 4; i++) {
        float2 x = __half22float2(p[i]);
        f[2 * i] = x.x; f[2 * i + 1] = x.y;
    }
}

// ------------------------- fused setup kernel --------------------------------
__global__ void setup_kernel(float* tw, float* wt, float* wi,
                             const float* __restrict__ cw1,
                             const float* __restrict__ cw2, float* w,
                             int* deg) {
    int i = blockIdx.x * blockDim.x + threadIdx.x;
    if (i < 7 * 64) {
        int s = i >> 6, j = i & 63;
        int l = 64 >> s;
        float2 v = make_float2(0.f, 0.f);
        if (j < l) {
            double a = (double)j / (double)l;
            v = make_float2((float)cospi(a), (float)sinpi(a));
        }
        reinterpret_cast<float2*>(tw)[i] = v;
    }
    if (i < 129) {
        double a = (double)i / 128.0;
        reinterpret_cast<float2*>(wt)[i] = make_float2((float)cospi(a), (float)(-sinpi(a)));
        reinterpret_cast<float2*>(wi)[i] = make_float2((float)cospi(a), (float)( sinpi(a)));
    }
    if (i == 0) {
        for (int L = 0; L < 2; L++) {
            const float* c = (L == 0) ? cw1 : cw2;
            float m = fmaxf(c[0], fmaxf(c[1], c[2]));
            float e0 = expf(c[0] - m), e1 = expf(c[1] - m), e2 = expf(c[2] - m);
            float s = e0 + e1 + e2;
            w[L * 3 + 0] = e0 / s; w[L * 3 + 1] = e1 / s; w[L * 3 + 2] = e2 / s;
        }
    }
    if (i < N_NODES) deg[i] = 0;
}

// ------------------------- fp32 -> bf16 hi/lo split --------------------------
__global__ void split_all_kernel(const float* __restrict__ Wn1,
                                 const float* __restrict__ Wn2,
                                 const float* __restrict__ Wr2,
                                 const float* __restrict__ rel2,
                                 __nv_bfloat16* __restrict__ Whi,
                                 __nv_bfloat16* __restrict__ Wlo,
                                 __nv_bfloat16* __restrict__ R2hi,
                                 __nv_bfloat16* __restrict__ R2lo) {
    const int W4 = DIM * DIM / 4;
    const int R4 = NRELS * DIM / 4;
    int i = blockIdx.x * blockDim.x + threadIdx.x;
    const float* src; __nv_bfloat16 *hi, *lo; int idx;
    if (i < W4)            { src = Wn1;  hi = Whi;                 lo = Wlo;                 idx = i; }
    else if (i < 2 * W4)   { src = Wn2;  hi = Whi + DIM * DIM;     lo = Wlo + DIM * DIM;     idx = i - W4; }
    else if (i < 3 * W4)   { src = Wr2;  hi = Whi + 2 * DIM * DIM; lo = Wlo + 2 * DIM * DIM; idx = i - 2 * W4; }
    else if (i < 3 * W4 + R4) { src = rel2; hi = R2hi;             lo = R2lo;                idx = i - 3 * W4; }
    else return;
    float4 v = reinterpret_cast<const float4*>(src)[idx];
    float f[4] = {v.x, v.y, v.z, v.w};
    __nv_bfloat16 h[4], l[4];
#pragma unroll
    for (int j = 0; j < 4; j++) {
        h[j] = __float2bfloat16(f[j]);
        l[j] = __float2bfloat16(f[j] - __bfloat162float(h[j]));
    }
    reinterpret_cast<uint2*>(hi)[idx] = *reinterpret_cast<uint2*>(h);
    reinterpret_cast<uint2*>(lo)[idx] = *reinterpret_cast<uint2*>(l);
}

// ------------------------- edge sorting --------------------------------------
__global__ void hist_kernel(const int* __restrict__ dst, int* deg) {
    int e = blockIdx.x * blockDim.x + threadIdx.x;
    if (e < N_EDGES) atomicAdd(&deg[dst[e]], 1);
}
__global__ __launch_bounds__(1024)
void scan_kernel(const int* __restrict__ deg, int* off, int* pos, int* dh) {
    __shared__ int ps[1024];
    __shared__ int dsh[DBINS];
    int t = threadIdx.x;
    if (t < DBINS) dsh[t] = 0;
    __syncthreads();
    const int CH = (N_NODES + 1023) / 1024;
    int b0 = t * CH, b1 = min(b0 + CH, N_NODES);
    int s = 0;
    for (int i = b0; i < b1; i++) {
        int d = deg[i];
        s += d;
        atomicAdd(&dsh[min(d, DBINS - 1)], 1);
    }
    ps[t] = s;
    __syncthreads();
    for (int o = 1; o < 1024; o <<= 1) {
        int u = (t >= o) ? ps[t - o] : 0;
        __syncthreads();
        ps[t] += u;
        __syncthreads();
    }
    int run = ps[t] - s;
    for (int i = b0; i < b1; i++) {
        off[i] = run; pos[i] = run; run += deg[i];
    }
    if (t == 1023) off[N_NODES] = ps[1023];
    if (t == 0) {
        int acc = 0;
        for (int b = 0; b < DBINS; b++) { int c = dsh[b]; dh[b] = acc; acc += c; }
    }
}
__global__ void scatter_perm_kernel(const int* __restrict__ src,
                                    const int* __restrict__ dst,
                                    const int* __restrict__ et,
                                    const int* __restrict__ deg,
                                    int* pos, int* dh,
                                    int2* edges, int* perm) {
    int e = blockIdx.x * blockDim.x + threadIdx.x;
    if (e < N_EDGES) {
        int p = atomicAdd(&pos[dst[e]], 1);
        edges[p] = make_int2(src[e], et[e]);
    }
    if (e < N_NODES) {
        int p = atomicAdd(&dh[min(deg[e], DBINS - 1)], 1);
        perm[p] = e;
    }
}

// ------------------------- 128-pt Stockham FFT (64 threads/row) --------------
__device__ __forceinline__ void fft128(float2* b0, float2* b1, int t, float sgn,
                                       const float2* __restrict__ tw) {
    float2* src = b0;
    float2* dst = b1;
#pragma unroll
    for (int s = 0; s < 7; s++) {
        int m = 1 << s;
        int j = t >> s;
        float2 w = tw[(s << 6) + j];
        w.y *= sgn;
        float2 c0 = src[t];
        float2 c1 = src[t + 64];
        float2 sum = make_float2(c0.x + c1.x, c0.y + c1.y);
        float2 d   = make_float2(c0.x - c1.x, c0.y - c1.y);
        int idx = (t & (m - 1)) | ((t >> s) << (s + 1));
        dst[idx]     = sum;
        dst[idx + m] = cmulf(d, w);
        float2* tmp = src; src = dst; dst = tmp;
        __syncthreads();
    }
}

// forward untangle -> fp16 spectrum row
__device__ __forceinline__ void untangle_store_h(
    float2* Z, __half2* Srow, int t, const float2* __restrict__ wt) {
#pragma unroll
    for (int u = 0; u < 2; u++) {
        int k = t + 64 * u;
        float2 Zk = Z[k];
        float2 Zm = Z[(128 - k) & 127];
        float2 Ze = make_float2(0.5f * (Zk.x + Zm.x), 0.5f * (Zk.y - Zm.y));
        float2 d  = make_float2(Zk.x - Zm.x, Zk.y + Zm.y);
        float2 Zo = make_float2(0.5f * d.y, -0.5f * d.x);
        float2 W  = wt[k];
        float2 H  = make_float2(Ze.x + W.x * Zo.x - W.y * Zo.y,
                                Ze.y + W.x * Zo.y + W.y * Zo.x);
        Srow[k] = __float22half2_rn(H);
    }
    if (t == 0) {
        float2 Z0 = Z[0];
        Srow[128] = __float22half2_rn(make_float2(Z0.x - Z0.y, 0.f));
    }
}

// ------------------------- gather + forward rfft (fused) ---------------------
__global__ __launch_bounds__(256)
void gather_fft_kernel(const int* __restrict__ x, const float* __restrict__ emb,
                       float* __restrict__ h, __half2* __restrict__ hH,
                       __half2* __restrict__ SH,
                       const float2* __restrict__ tw, const float2* __restrict__ wt) {
    __shared__ float2 buf[4][2][128];
    int g = threadIdx.x >> 6, t = threadIdx.x & 63;
    int row = (blockIdx.x << 2) + g;
    float4 v = reinterpret_cast<const float4*>(emb + (size_t)x[row] * DIM)[t];
    reinterpret_cast<float4*>(h + (size_t)row * DIM)[t] = v;
    __half2 p0 = __float22half2_rn(make_float2(v.x, v.y));
    __half2 p1 = __float22half2_rn(make_float2(v.z, v.w));
    *reinterpret_cast<uint2*>(hH + (size_t)row * HROW2 + 2 * t) =
        make_uint2(*reinterpret_cast<uint32_t*>(&p0), *reinterpret_cast<uint32_t*>(&p1));
    buf[g][0][2 * t]     = make_float2(v.x, v.y);
    buf[g][0][2 * t + 1] = make_float2(v.z, v.w);
    __syncthreads();
    fft128(buf[g][0], buf[g][1], t, -1.f, tw);
    untangle_store_h(buf[g][1], SH + (size_t)row * SROW2, t, wt);
}

// --------------- rel tables fft -> fp16 copies (both layers) -----------------
__global__ __launch_bounds__(256)
void rel_fft2_kernel(const float* __restrict__ rel1, const float* __restrict__ rel2,
                     __half2* __restrict__ rH1,  __half2* __restrict__ RSH1,
                     __half2* __restrict__ rH2,  __half2* __restrict__ RSH2,
                     const float2* __restrict__ tw, const float2* __restrict__ wt) {
    __shared__ float2 buf[4][2][128];
    int g = threadIdx.x >> 6, t = threadIdx.x & 63;
    int row = (blockIdx.x << 2) + g;
    const float* rel = (row < NRELS) ? rel1 : rel2;
    __half2* rH  = (row < NRELS) ? rH1  : rH2;
    __half2* RSH = (row < NRELS) ? RSH1 : RSH2;
    int r = (row < NRELS) ? row : row - NRELS;
    float4 v = reinterpret_cast<const float4*>(rel + (size_t)r * DIM)[t];
    __half2 p0 = __float22half2_rn(make_float2(v.x, v.y));
    __half2 p1 = __float22half2_rn(make_float2(v.z, v.w));
    *reinterpret_cast<uint2*>(rH + (size_t)r * HROW2 + 2 * t) =
        make_uint2(*reinterpret_cast<uint32_t*>(&p0), *reinterpret_cast<uint32_t*>(&p1));
    buf[g][0][2 * t]     = make_float2(v.x, v.y);
    buf[g][0][2 * t + 1] = make_float2(v.z, v.w);
    __syncthreads();
    fft128(buf[g][0], buf[g][1], t, -1.f, tw);
    untangle_store_h(buf[g][1], RSH + (size_t)r * SROW2, t, wt);
}

// --------------- aggregation + inverse rfft (WARP per node) ------------------
__global__ __launch_bounds__(256, 3)
void agg_inv_kernel(const int2* __restrict__ edges, const int* __restrict__ off,
                    const int* __restrict__ perm,
                    const __half2* __restrict__ hH,  const __half2* __restrict__ HSH,
                    const __half2* __restrict__ rH, const __half2* __restrict__ RSH,
                    const float* __restrict__ w, int wofs,
                    __nv_bfloat16* __restrict__ HChi,
                    __nv_bfloat16* __restrict__ HClo,
                    const float2* __restrict__ tw, const float2* __restrict__ wi) {
    __shared__ float2 buf[8][2][132];
    int wl = threadIdx.x >> 5, t = threadIdx.x & 31;
    int v = perm[(blockIdx.x << 3) + wl];
    float w0 = w[wofs + 0], w1 = w[wofs + 1], w2 = w[wofs + 2];

    const uint4* hH4 = reinterpret_cast<const uint4*>(hH);
    const uint4* rH4 = reinterpret_cast<const uint4*>(rH);
    const uint4* HS4 = reinterpret_cast<const uint4*>(HSH);
    const uint4* RS4 = reinterpret_cast<const uint4*>(RSH);

    float T[8], Rs[8], F[8];
    float hv[8], rv[8], av[8], bv[8];

    cvt8(hH4[(size_t)v * 32 + t], hv);
    cvt8(rH4[t], rv);
#pragma unroll
    for (int i = 0; i < 8; i++) {
        Rs[i] = rv[i];
        T[i]  = hv[i] * fmaf(w0, rv[i], w1);
    }
    cvt8(HS4[(size_t)v * SROW4 + t], av);
    cvt8(RS4[t], bv);
#pragma unroll
    for (int i = 0; i < 4; i++) {
        F[2 * i]     = av[2 * i] * bv[2 * i] + av[2 * i + 1] * bv[2 * i + 1];
        F[2 * i + 1] = av[2 * i + 1] * bv[2 * i] - av[2 * i] * bv[2 * i + 1];
    }
    float2 Ft = make_float2(0.f, 0.f);
    if (t == 0) {
        float2 a = __half22float2(HSH[(size_t)v * SROW2 + 128]);
        float2 b = __half22float2(RSH[128]);
        Ft = make_float2(a.x * b.x + a.y * b.y, a.y * b.x - a.x * b.y);
    }

    int e = off[v], e1 = off[v + 1];
    for (; e + 1 < e1; e += 2) {
        int2 ea = edges[e];
        int2 eb = edges[e + 1];
        uint4 ha = hH4[(size_t)ea.x * 32 + t];
        uint4 ra = rH4[(size_t)ea.y * 32 + t];
        uint4 sa = HS4[(size_t)ea.x * SROW4 + t];
        uint4 ta = RS4[(size_t)ea.y * SROW4 + t];
        uint4 hb = hH4[(size_t)eb.x * 32 + t];
        uint4 rb = rH4[(size_t)eb.y * 32 + t];
        uint4 sb = HS4[(size_t)eb.x * SROW4 + t];
        uint4 tb = RS4[(size_t)eb.y * SROW4 + t];
        cvt8(ha, hv); cvt8(ra, rv);
#pragma unroll
        for (int i = 0; i < 8; i++) {
            Rs[i] += rv[i];
            T[i] = fmaf(hv[i], fmaf(w0, rv[i], w1), T[i]);
        }
        cvt8(sa, av); cvt8(ta, bv);
#pragma unroll
        for (int i = 0; i < 4; i++) {
            F[2 * i]     += av[2 * i] * bv[2 * i] + av[2 * i + 1] * bv[2 * i + 1];
            F[2 * i + 1] += av[2 * i + 1] * bv[2 * i] - av[2 * i] * bv[2 * i + 1];
        }
        cvt8(hb, hv); cvt8(rb, rv);
#pragma unroll
        for (int i = 0; i < 8; i++) {
            Rs[i] += rv[i];
            T[i] = fmaf(hv[i], fmaf(w0, rv[i], w1), T[i]);
        }
        cvt8(sb, av); cvt8(tb, bv);
#pragma unroll
        for (int i = 0; i < 4; i++) {
            F[2 * i]     += av[2 * i] * bv[2 * i] + av[2 * i + 1] * bv[2 * i + 1];
            F[2 * i + 1] += av[2 * i + 1] * bv[2 * i] - av[2 * i] * bv[2 * i + 1];
        }
        if (t == 0) {
            float2 a0 = __half22float2(HSH[(size_t)ea.x * SROW2 + 128]);
            float2 b0 = __half22float2(RSH[(size_t)ea.y * SROW2 + 128]);
            float2 a1 = __half22float2(HSH[(size_t)eb.x * SROW2 + 128]);
            float2 b1 = __half22float2(RSH[(size_t)eb.y * SROW2 + 128]);
            Ft.x += a0.x * b0.x + a0.y * b0.y + a1.x * b1.x + a1.y * b1.y;
            Ft.y += a0.y * b0.x - a0.x * b0.y + a1.y * b1.x - a1.x * b1.y;
        }
    }
    if (e < e1) {
        int2 ed = edges[e];
        uint4 ha = hH4[(size_t)ed.x * 32 + t];
        uint4 ra = rH4[(size_t)ed.y * 32 + t];
        uint4 sa = HS4[(size_t)ed.x * SROW4 + t];
        uint4 ta = RS4[(size_t)ed.y * SROW4 + t];
        cvt8(ha, hv); cvt8(ra, rv);
#pragma unroll
        for (int i = 0; i < 8; i++) {
            Rs[i] += rv[i];
            T[i] = fmaf(hv[i], fmaf(w0, rv[i], w1), T[i]);
        }
        cvt8(sa, av); cvt8(ta, bv);
#pragma unroll
        for (int i = 0; i < 4; i++) {
            F[2 * i]     += av[2 * i] * bv[2 * i] + av[2 * i + 1] * bv[2 * i + 1];
            F[2 * i + 1] += av[2 * i + 1] * bv[2 * i] - av[2 * i] * bv[2 * i + 1];
        }
        if (t == 0) {
            float2 a = __half22float2(HSH[(size_t)ed.x * SROW2 + 128]);
            float2 b = __half22float2(RSH[(size_t)ed.y * SROW2 + 128]);
            Ft.x += a.x * b.x + a.y * b.y;
            Ft.y += a.y * b.x - a.x * b.y;
        }
    }

    float2* sA = buf[wl][1];
#pragma unroll
    for (int i = 0; i < 4; i++)
        sA[4 * t + i] = make_float2(w2 * F[2 * i], w2 * F[2 * i + 1]);
    if (t == 0) sA[128] = make_float2(w2 * Ft.x, w2 * Ft.y);
    __syncwarp();

    float2* pk = buf[wl][0];
#pragma unroll
    for (int u = 0; u < 4; u++) {
        int k = t + 32 * u;
        float2 Ak = sA[k], Am = sA[128 - k];
        float2 Ze = make_float2(0.5f * (Ak.x + Am.x), 0.5f * (Ak.y - Am.y));
        float2 hd = make_float2(0.5f * (Ak.x - Am.x), 0.5f * (Ak.y + Am.y));
        float2 Zo = cmulf(wi[k], hd);
        pk[k] = make_float2(Ze.x - Zo.y, Ze.y + Zo.x);
    }
    __syncwarp();

    float2* src = buf[wl][0];
    float2* dst = buf[wl][1];
#pragma unroll
    for (int s = 0; s < 7; s++) {
        int m = 1 << s;
#pragma unroll
        for (int u = 0; u < 2; u++) {
            int tt = t + 32 * u;
            float2 wv = tw[(s << 6) + (tt >> s)];
            float2 c0 = src[tt];
            float2 c1 = src[tt + 64];
            float2 sum = make_float2(c0.x + c1.x, c0.y + c1.y);
            float2 d   = make_float2(c0.x - c1.x, c0.y - c1.y);
            int idx = (tt & (m - 1)) | ((tt >> s) << (s + 1));
            dst[idx]     = sum;
            dst[idx + m] = cmulf(d, wv);
        }
        float2* tmp = src; src = dst; dst = tmp;
        __syncwarp();
    }

    const float inv = 1.f / 128.f;
    float o[8];
#pragma unroll
    for (int i = 0; i < 4; i++) {
        float2 z = src[4 * t + i];
        o[2 * i]     = fmaf(w1, Rs[2 * i],     T[2 * i])     + z.x * inv;
        o[2 * i + 1] = fmaf(w1, Rs[2 * i + 1], T[2 * i + 1]) + z.y * inv;
    }
    __nv_bfloat16 hi8[8], lo8[8];
#pragma unroll
    for (int j = 0; j < 8; j++) {
        hi8[j] = __float2bfloat16(o[j]);
        lo8[j] = __float2bfloat16(o[j] - __bfloat162float(hi8[j]));
    }
    reinterpret_cast<uint4*>(HChi + (size_t)v * DIM)[t] = *reinterpret_cast<uint4*>(hi8);
    reinterpret_cast<uint4*>(HClo + (size_t)v * DIM)[t] = *reinterpret_cast<uint4*>(lo8);
}

// --------- LN + ReLU (input Z already = gemm+bias+resid), optional fft -------
template<bool DO_FFT>
__global__ __launch_bounds__(256)
void epilogue_fft_kernel(const float* __restrict__ Z,
                         const float* __restrict__ gamma,
                         const float* __restrict__ beta,
                         float* __restrict__ h_out,
                         __half2* __restrict__ hH,
                         __half2* __restrict__ SH,
                         const float2* __restrict__ tw,
                         const float2* __restrict__ wt) {
    __shared__ float2 buf[4][2][128];
    __shared__ float sred[4][2];
    int g = threadIdx.x >> 6, t = threadIdx.x & 63;
    int wsub = t >> 5;
    int v = (blockIdx.x << 2) + g;

    float4 z = reinterpret_cast<const float4*>(Z + (size_t)v * DIM)[t];
    float s = z.x + z.y + z.z + z.w;
#pragma unroll
    for (int ofs = 16; ofs; ofs >>= 1) s += __shfl_xor_sync(0xffffffffu, s, ofs);
    if ((t & 31) == 0) sred[g][wsub] = s;
    __syncthreads();
    float mu = (sred[g][0] + sred[g][1]) * (1.f / DIM);
    __syncthreads();
    float4 zc = make_float4(z.x - mu, z.y - mu, z.z - mu, z.w - mu);
    float vv = zc.x * zc.x + zc.y * zc.y + zc.z * zc.z + zc.w * zc.w;
#pragma unroll
    for (int ofs = 16; ofs; ofs >>= 1) vv += __shfl_xor_sync(0xffffffffu, vv, ofs);
    if ((t & 31) == 0) sred[g][wsub] = vv;
    __syncthreads();
    float rstd = rsqrtf((sred[g][0] + sred[g][1]) * (1.f / DIM) + LN_EPS);
    float4 gm = reinterpret_cast<const float4*>(gamma)[t];
    float4 bt = reinterpret_cast<const float4*>(beta)[t];
    float4 y = make_float4(fmaxf(zc.x * rstd * gm.x + bt.x, 0.f),
                           fmaxf(zc.y * rstd * gm.y + bt.y, 0.f),
                           fmaxf(zc.z * rstd * gm.z + bt.z, 0.f),
                           fmaxf(zc.w * rstd * gm.w + bt.w, 0.f));
    reinterpret_cast<float4*>(h_out + (size_t)v * DIM)[t] = y;
    if (DO_FFT) {
        __half2 p0 = __float22half2_rn(make_float2(y.x, y.y));
        __half2 p1 = __float22half2_rn(make_float2(y.z, y.w));
        *reinterpret_cast<uint2*>(hH + (size_t)v * HROW2 + 2 * t) =
            make_uint2(*reinterpret_cast<uint32_t*>(&p0), *reinterpret_cast<uint32_t*>(&p1));
        buf[g][0][2 * t]     = make_float2(y.x, y.y);
        buf[g][0][2 * t + 1] = make_float2(y.z, y.w);
        __syncthreads();
        fft128(buf[g][0], buf[g][1], t, -1.f, tw);
        untangle_store_h(buf[g][1], SH + (size_t)v * SROW2, t, wt);
    }
}

// ------------------------- bf16x3 GEMM with pre-split operands ---------------
#define GBK 32
#define GPAD 8
#define GLDW (GBK + GPAD)

__device__ __forceinline__ void mma_bf16(float* d,
    uint32_t a0, uint32_t a1, uint32_t a2, uint32_t a3,
    uint32_t b0, uint32_t b1) {
    asm volatile(
        "mma.sync.aligned.m16n8k16.row.col.f32.bf16.bf16.f32 "
        "{%0,%1,%2,%3}, {%4,%5,%6,%7}, {%8,%9}, {%0,%1,%2,%3};"
        : "+f"(d[0]), "+f"(d[1]), "+f"(d[2]), "+f"(d[3])
        : "r"(a0), "r"(a1), "r"(a2), "r"(a3), "r"(b0), "r"(b1));
}

template<bool BIAS, bool RESID>
__global__ __launch_bounds__(256)
void bf16s_gemm(const __nv_bfloat16* __restrict__ Ahi,
                const __nv_bfloat16* __restrict__ Alo,
                const __nv_bfloat16* __restrict__ Bhi,
                const __nv_bfloat16* __restrict__ Blo,
                float* __restrict__ C, const float* __restrict__ bias,
                const float* __restrict__ Hres,
                int M, int N, int K) {
    __shared__ __align__(16) __nv_bfloat16 Ah[128 * GLDW];
    __shared__ __align__(16) __nv_bfloat16 Al[128 * GLDW];
    __shared__ __align__(16) __nv_bfloat16 Bh[128 * GLDW];
    __shared__ __align__(16) __nv_bfloat16 Bl[128 * GLDW];

    int tid = threadIdx.x;
    int lane = tid & 31, wid = tid >> 5;
    int wm = wid & 1, wn = wid >> 1;
    int r = lane >> 2, cq = lane & 3;
    int bm = blockIdx.y * 128, bn = blockIdx.x * 128;

    float acc[4][4][4];
#pragma unroll
    for (int a = 0; a < 4; a++)
#pragma unroll
        for (int b = 0; b < 4; b++)
#pragma unroll
            for (int c = 0; c < 4; c++) acc[a][b][c] = 0.f;

    int lrow[2], lcol[2];
#pragma unroll
    for (int j = 0; j < 2; j++) {
        int idx = tid + 256 * j;
        lrow[j] = idx >> 2; lcol[j] = (idx & 3) << 3;
    }

    uint4 rah[2], ral[2], rbh[2], rbl[2];
    const uint4 z4 = make_uint4(0, 0, 0, 0);

    auto load_tile = [&](int k0) {
#pragma unroll
        for (int j = 0; j < 2; j++) {
            size_t ao = (size_t)(bm + lrow[j]) * K + k0 + lcol[j];
            size_t bo = (size_t)(bn + lrow[j]) * K + k0 + lcol[j];
            bool av = (bm + lrow[j] < M), bv = (bn + lrow[j] < N);
            rah[j] = av ? *reinterpret_cast<const uint4*>(Ahi + ao) : z4;
            ral[j] = av ? *reinterpret_cast<const uint4*>(Alo + ao) : z4;
            rbh[j] = bv ? *reinterpret_cast<const uint4*>(Bhi + bo) : z4;
            rbl[j] = bv ? *reinterpret_cast<const uint4*>(Blo + bo) : z4;
        }
    };
    auto stage_tile = [&]() {
#pragma unroll
        for (int j = 0; j < 2; j++) {
            int so = lrow[j] * GLDW + lcol[j];
            *reinterpret_cast<uint4*>(&Ah[so]) = rah[j];
            *reinterpret_cast<uint4*>(&Al[so]) = ral[j];
            *reinterpret_cast<uint4*>(&Bh[so]) = rbh[j];
            *reinterpret_cast<uint4*>(&Bl[so]) = rbl[j];
        }
    };

    load_tile(0);
    for (int k0 = 0; k0 < K; k0 += GBK) {
        stage_tile();
        __syncthreads();
        if (k0 + GBK < K) load_tile(k0 + GBK);

#pragma unroll
        for (int ks = 0; ks < 2; ks++) {
            int kb = ks * 16 + cq * 2;
            uint32_t bhf[4][2], blf[4][2];
#pragma unroll
            for (int nf = 0; nf < 4; nf++) {
                int col = wn * 32 + nf * 8 + r;
                bhf[nf][0] = *reinterpret_cast<const uint32_t*>(&Bh[col * GLDW + kb]);
                bhf[nf][1] = *reinterpret_cast<const uint32_t*>(&Bh[col * GLDW + kb + 8]);
                blf[nf][0] = *reinterpret_cast<const uint32_t*>(&Bl[col * GLDW + kb]);
                blf[nf][1] = *reinterpret_cast<const uint32_t*>(&Bl[col * GLDW + kb + 8]);
            }
#pragma unroll
            for (int mf = 0; mf < 4; mf++) {
                int row = wm * 64 + mf * 16 + r;
                uint32_t a0 = *reinterpret_cast<const uint32_t*>(&Ah[row * GLDW + kb]);
                uint32_t a1 = *reinterpret_cast<const uint32_t*>(&Ah[(row + 8) * GLDW + kb]);
                uint32_t a2 = *reinterpret_cast<const uint32_t*>(&Ah[row * GLDW + kb + 8]);
                uint32_t a3 = *reinterpret_cast<const uint32_t*>(&Ah[(row + 8) * GLDW + kb + 8]);
                uint32_t l0 = *reinterpret_cast<const uint32_t*>(&Al[row * GLDW + kb]);
                uint32_t l1 = *reinterpret_cast<const uint32_t*>(&Al[(row + 8) * GLDW + kb]);
                uint32_t l2 = *reinterpret_cast<const uint32_t*>(&Al[row * GLDW + kb + 8]);
                uint32_t l3 = *reinterpret_cast<const uint32_t*>(&Al[(row + 8) * GLDW + kb + 8]);
#pragma unroll
                for (int nf = 0; nf < 4; nf++) {
                    mma_bf16(acc[mf][nf], a0, a1, a2, a3, bhf[nf][0], bhf[nf][1]);
                    mma_bf16(acc[mf][nf], a0, a1, a2, a3, blf[nf][0], blf[nf][1]);
                    mma_bf16(acc[mf][nf], l0, l1, l2, l3, bhf[nf][0], bhf[nf][1]);
                }
            }
        }
        __syncthreads();
    }

#pragma unroll
    for (int mf = 0; mf < 4; mf++) {
        int row0 = bm + wm * 64 + mf * 16 + r;
#pragma unroll
        for (int nf = 0; nf < 4; nf++) {
            int col = bn + wn * 32 + nf * 8 + cq * 2;
            float bx = 0.f, by = 0.f;
            if (BIAS) { bx = bias[col]; by = bias[col + 1]; }
            if (row0 < M) {
                float rx = bx, ry = by;
                if (RESID) {
                    float2 hv = *reinterpret_cast<const float2*>(
                        Hres + (size_t)row0 * N + col);
                    rx += hv.x; ry += hv.y;
                }
                *reinterpret_cast<float2*>(C + (size_t)row0 * N + col) =
                    make_float2(acc[mf][nf][0] + rx, acc[mf][nf][1] + ry);
            }
            if (row0 + 8 < M) {
                float rx = bx, ry = by;
                if (RESID) {
                    float2 hv = *reinterpret_cast<const float2*>(
                        Hres + (size_t)(row0 + 8) * N + col);
                    rx += hv.x; ry += hv.y;
                }
                *reinterpret_cast<float2*>(C + (size_t)(row0 + 8) * N + col) =
                    make_float2(acc[mf][nf][2] + rx, acc[mf][nf][3] + ry);
            }
        }
    }
}

// ------------------------- launch --------------------------------------------
extern "C" void kernel_launch(void* const* d_in, const int* in_sizes, int n_in,
                              void* d_out, int out_size) {
    (void)in_sizes; (void)n_in; (void)out_size;
    const int*   x    = (const int*)  d_in[0];
    const int*   eidx = (const int*)  d_in[1];
    const int*   et   = (const int*)  d_in[2];
    const float* emb  = (const float*)d_in[3];
    const float* rel1 = (const float*)d_in[4];
    const float* Wn1  = (const float*)d_in[7];
    const float* bn1  = (const float*)d_in[8];
    const float* cw1  = (const float*)d_in[9];
    const float* gm1  = (const float*)d_in[10];
    const float* bt1  = (const float*)d_in[11];
    const float* rel2 = (const float*)d_in[12];
    const float* Wr2  = (const float*)d_in[13];
    const float* br2  = (const float*)d_in[14];
    const float* Wn2  = (const float*)d_in[15];
    const float* bn2  = (const float*)d_in[16];
    const float* cw2  = (const float*)d_in[17];
    const float* gm2  = (const float*)d_in[18];
    const float* bt2  = (const float*)d_in[19];

    float* out_h    = (float*)d_out;
    float* out_rels = out_h + (size_t)N_NODES * DIM;
    const int* src = eidx;
    const int* dst = eidx + N_EDGES;

    float *pH, *pZ, *pTw, *pWt, *pWi, *pW;
    __nv_bfloat16 *pHChi, *pHClo, *pWhi, *pWlo, *pR2hi, *pR2lo;
    __half2 *pHH, *pHSH, *pRH, *pRSH;
    int *pDeg, *pOff, *pPos, *pDh, *pPerm;
    int2* pEdges;
    cudaGetSymbolAddress((void**)&pH,    g_h);
    cudaGetSymbolAddress((void**)&pZ,    g_Z);
    cudaGetSymbolAddress((void**)&pHChi, g_HChi);
    cudaGetSymbolAddress((void**)&pHClo, g_HClo);
    cudaGetSymbolAddress((void**)&pWhi,  g_Whi);
    cudaGetSymbolAddress((void**)&pWlo,  g_Wlo);
    cudaGetSymbolAddress((void**)&pR2hi, g_R2hi);
    cudaGetSymbolAddress((void**)&pR2lo, g_R2lo);
    cudaGetSymbolAddress((void**)&pHH,   g_hH);
    cudaGetSymbolAddress((void**)&pHSH,  g_HSH);
    cudaGetSymbolAddress((void**)&pRH,   g_rH);
    cudaGetSymbolAddress((void**)&pRSH,  g_RSH);
    cudaGetSymbolAddress((void**)&pTw,   g_tw);
    cudaGetSymbolAddress((void**)&pWt,   g_wt);
    cudaGetSymbolAddress((void**)&pWi,   g_wi);
    cudaGetSymbolAddress((void**)&pW,    g_w);
    cudaGetSymbolAddress((void**)&pDeg,  g_deg);
    cudaGetSymbolAddress((void**)&pOff,  g_off);
    cudaGetSymbolAddress((void**)&pPos,  g_pos);
    cudaGetSymbolAddress((void**)&pDh,   g_dh);
    cudaGetSymbolAddress((void**)&pPerm, g_perm);
    cudaGetSymbolAddress((void**)&pEdges, g_edges);

    const float2* tw = (const float2*)pTw;
    const float2* wt = (const float2*)pWt;
    const float2* wi = (const float2*)pWi;
    __half2* pRH1  = pRH;
    __half2* pRH2  = pRH  + (size_t)NRELS * HROW2;
    __half2* pRSH1 = pRSH;
    __half2* pRSH2 = pRSH + (size_t)NRELS * SROW2;

    // ---- handle lifecycle: destroy previous call's handles, create fresh
    // ones, so the capture call is net-zero in device memory while every
    // call launches identical work. ----
    static cudaStream_t s1 = nullptr, s2 = nullptr;
    static cudaEvent_t evSetup = nullptr, evSort = nullptr,
                       evRel = nullptr, evTail = nullptr;
    if (s1)      cudaStreamDestroy(s1);
    if (s2)      cudaStreamDestroy(s2);
    if (evSetup) cudaEventDestroy(evSetup);
    if (evSort)  cudaEventDestroy(evSort);
    if (evRel)   cudaEventDestroy(evRel);
    if (evTail)  cudaEventDestroy(evTail);
    cudaStreamCreateWithFlags(&s1, cudaStreamNonBlocking);
    cudaStreamCreateWithFlags(&s2, cudaStreamNonBlocking);
    cudaEventCreateWithFlags(&evSetup, cudaEventDisableTiming);
    cudaEventCreateWithFlags(&evSort,  cudaEventDisableTiming);
    cudaEventCreateWithFlags(&evRel,   cudaEventDisableTiming);
    cudaEventCreateWithFlags(&evTail,  cudaEventDisableTiming);

    // s0: setup (twiddles, softmax, deg=0); fork point for s1/s2
    setup_kernel<<<(N_NODES + 255) / 256, 256>>>(pTw, pWt, pWi, cw1, cw2, pW, pDeg);
    cudaEventRecord(evSetup, 0);

    // s1: edge sort chain (forked AFTER the capture-origin event -> captured)
    cudaStreamWaitEvent(s1, evSetup, 0);
    hist_kernel<<<(N_EDGES + 255) / 256, 256, 0, s1>>>(dst, pDeg);
    scan_kernel<<<1, 1024, 0, s1>>>(pDeg, pOff, pPos, pDh);
    scatter_perm_kernel<<<(N_EDGES + 255) / 256, 256, 0, s1>>>(
        src, dst, et, pDeg, pPos, pDh, pEdges, pPerm);
    cudaEventRecord(evSort, s1);

    // s2: MUST fork from the capture-origin stream BEFORE its first launch,
    // otherwise its work is not captured into the graph (R13 bug).
    cudaStreamWaitEvent(s2, evSetup, 0);
    const int SPLIT_N = 3 * (DIM * DIM / 4) + NRELS * DIM / 4;
    split_all_kernel<<<(SPLIT_N + 255) / 256, 256, 0, s2>>>(
        Wn1, Wn2, Wr2, rel2, pWhi, pWlo, pR2hi, pR2lo);
    bf16s_gemm<true, false><<<dim3(2, (NRELS + 127) / 128), 256, 0, s2>>>(
        pR2hi, pR2lo, pWhi + 2 * DIM * DIM, pWlo + 2 * DIM * DIM,
        out_rels, br2, nullptr, NRELS, DIM, DIM);
    rel_fft2_kernel<<<2 * NRELS / 4, 256, 0, s2>>>(
        rel1, rel2, pRH1, pRSH1, pRH2, pRSH2, tw, wt);
    cudaEventRecord(evRel, s2);
    cudaEventRecord(evTail, s2);

    // s0: node gather + forward fft
    gather_fft_kernel<<<N_NODES / 4, 256>>>(x, emb, pH, pHH, pHSH, tw, wt);

    // join: main chain needs sort outputs + rel tables
    cudaStreamWaitEvent(0, evSort, 0);
    cudaStreamWaitEvent(0, evRel, 0);

    for (int L = 0; L < 2; L++) {
        const float* bn = (L == 0) ? bn1 : bn2;
        const float* gm = (L == 0) ? gm1 : gm2;
        const float* bt = (L == 0) ? bt1 : bt2;
        __half2* rH  = (L == 0) ? pRH1  : pRH2;
        __half2* RSH = (L == 0) ? pRSH1 : pRSH2;
        const __nv_bfloat16* Whi = pWhi + (size_t)L * DIM * DIM;
        const __nv_bfloat16* Wlo = pWlo + (size_t)L * DIM * DIM;

        agg_inv_kernel<<<N_NODES / 8, 256>>>(pEdges, pOff, pPerm, pHH, pHSH,
                                             rH, RSH, pW, 3 * L, pHChi, pHClo,
                                             tw, wi);
        bf16s_gemm<true, true><<<dim3(2, (N_NODES + 127) / 128), 256>>>(
            pHChi, pHClo, Whi, Wlo, pZ, bn, pH, N_NODES, DIM, DIM);
        if (L == 0) {
            epilogue_fft_kernel<true><<<N_NODES / 4, 256>>>(
                pZ, gm, bt, pH, pHH, pHSH, tw, wt);
        } else {
            epilogue_fft_kernel<false><<<N_NODES / 4, 256>>>(
                pZ, gm, bt, out_h, nullptr, nullptr, tw, wt);
        }
    }

    // ensure the s2 chain (incl. rels GEMM) completes within the graph
    cudaStreamWaitEvent(0, evTail, 0);
}

// round 15
// speedup vs baseline: 1.1953x; 1.0390x over previous
#include <cuda_runtime.h>
#include <cuda_bf16.h>
#include <cuda_fp16.h>
#include <math.h>
#include <stdint.h>

#define N_NODES 50000
#define N_EDGES 250000
#define DIM     256
#define NRELS   400
#define HROW2   128     // h row: 128 half2 (256 vals) = 512 B
#define SROW2   132     // spec row: 129 bins as half2 + 3 pad = 528 B (16B-aligned)
#define SROW4   33      // spec row in uint4
#define LN_EPS  1e-5f
#define DBINS   64
#define ROWS_A  25088                 // chunk-A rows (perm order), 128|ROWS_A, 8|ROWS_A
#define AGG_BLKS_A (ROWS_A / 8)       // 3136
#define AGG_BLKS_B ((N_NODES - ROWS_A) / 8 + (((N_NODES - ROWS_A) % 8) ? 1 : 0)) // 3114
#define EPI_BLKS_A (ROWS_A / 4)       // 6272
#define EPI_BLKS_B ((N_NODES - ROWS_A) / 4)  // 6228 (24912 % 4 == 0)

// ------------------------- scratch (device globals) --------------------------
__device__ float   g_h  [(size_t)N_NODES * DIM];
__device__ float   g_Z  [(size_t)N_NODES * DIM];           // perm-order rows
__device__ __nv_bfloat16 g_HChi[(size_t)N_NODES * DIM];    // perm-order rows
__device__ __nv_bfloat16 g_HClo[(size_t)N_NODES * DIM];
__device__ __nv_bfloat16 g_Whi [3 * DIM * DIM];
__device__ __nv_bfloat16 g_Wlo [3 * DIM * DIM];
__device__ __nv_bfloat16 g_R2hi[NRELS * DIM];
__device__ __nv_bfloat16 g_R2lo[NRELS * DIM];
__device__ __half2 g_hH [(size_t)N_NODES * HROW2];
__device__ __half2 g_HSH[(size_t)N_NODES * SROW2];
__device__ __half2 g_rH [2][(size_t)NRELS * HROW2];
__device__ __half2 g_RSH[2][(size_t)NRELS * SROW2];
__device__ float   g_tw [7 * 64 * 2];
__device__ float   g_wt [129 * 2];
__device__ float   g_wi [129 * 2];
__device__ float   g_w  [6];
__device__ int     g_deg[N_NODES];
__device__ int     g_off[N_NODES + 1];
__device__ int     g_pos[N_NODES];
__device__ int     g_dh [DBINS];
__device__ int     g_perm[N_NODES];
__device__ int2    g_edges[N_EDGES];

// ------------------------- small helpers -------------------------------------
__device__ __forceinline__ float2 cmulf(float2 a, float2 b) {
    return make_float2(a.x * b.x - a.y * b.y, a.x * b.y + a.y * b.x);
}
__device__ __forceinline__ void cvt8(uint4 u, float* f) {
    __half2* p = reinterpret_cast<__half2*>(&u);
#pragma unroll
    for (int i = 0; i < 4; i++) {
        float2 x = __half22float2(p[i]);
        f[2 * i] = x.x; f[2 * i + 1] = x.y;
    }
}

// ------------------------- fused setup kernel --------------------------------
__global__ void setup_kernel(float* tw, float* wt, float* wi,
                             const float* __restrict__ cw1,
                             const float* __restrict__ cw2, float* w,
                             int* deg) {
    int i = blockIdx.x * blockDim.x + threadIdx.x;
    if (i < 7 * 64) {
        int s = i >> 6, j = i & 63;
        int l = 64 >> s;
        float2 v = make_float2(0.f, 0.f);
        if (j < l) {
            double a = (double)j / (double)l;
            v = make_float2((float)cospi(a), (float)sinpi(a));
        }
        reinterpret_cast<float2*>(tw)[i] = v;
    }
    if (i < 129) {
        double a = (double)i / 128.0;
        reinterpret_cast<float2*>(wt)[i] = make_float2((float)cospi(a), (float)(-sinpi(a)));
        reinterpret_cast<float2*>(wi)[i] = make_float2((float)cospi(a), (float)( sinpi(a)));
    }
    if (i == 0) {
        for (int L = 0; L < 2; L++) {
            const float* c = (L == 0) ? cw1 : cw2;
            float m = fmaxf(c[0], fmaxf(c[1], c[2]));
            float e0 = expf(c[0] - m), e1 = expf(c[1] - m), e2 = expf(c[2] - m);
            float s = e0 + e1 + e2;
            w[L * 3 + 0] = e0 / s; w[L * 3 + 1] = e1 / s; w[L * 3 + 2] = e2 / s;
        }
    }
    if (i < N_NODES) deg[i] = 0;
}

// ------------------------- fp32 -> bf16 hi/lo split --------------------------
__global__ void split_all_kernel(const float* __restrict__ Wn1,
                                 const float* __restrict__ Wn2,
                                 const float* __restrict__ Wr2,
                                 const float* __restrict__ rel2,
                                 __nv_bfloat16* __restrict__ Whi,
                                 __nv_bfloat16* __restrict__ Wlo,
                                 __nv_bfloat16* __restrict__ R2hi,
                                 __nv_bfloat16* __restrict__ R2lo) {
    const int W4 = DIM * DIM / 4;
    const int R4 = NRELS * DIM / 4;
    int i = blockIdx.x * blockDim.x + threadIdx.x;
    const float* src; __nv_bfloat16 *hi, *lo; int idx;
    if (i < W4)            { src = Wn1;  hi = Whi;                 lo = Wlo;                 idx = i; }
    else if (i < 2 * W4)   { src = Wn2;  hi = Whi + DIM * DIM;     lo = Wlo + DIM * DIM;     idx = i - W4; }
    else if (i < 3 * W4)   { src = Wr2;  hi = Whi + 2 * DIM * DIM; lo = Wlo + 2 * DIM * DIM; idx = i - 2 * W4; }
    else if (i < 3 * W4 + R4) { src = rel2; hi = R2hi;             lo = R2lo;                idx = i - 3 * W4; }
    else return;
    float4 v = reinterpret_cast<const float4*>(src)[idx];
    float f[4] = {v.x, v.y, v.z, v.w};
    __nv_bfloat16 h[4], l[4];
#pragma unroll
    for (int j = 0; j < 4; j++) {
        h[j] = __float2bfloat16(f[j]);
        l[j] = __float2bfloat16(f[j] - __bfloat162float(h[j]));
    }
    reinterpret_cast<uint2*>(hi)[idx] = *reinterpret_cast<uint2*>(h);
    reinterpret_cast<uint2*>(lo)[idx] = *reinterpret_cast<uint2*>(l);
}

// ------------------------- edge sorting --------------------------------------
__global__ void hist_kernel(const int* __restrict__ dst, int* deg) {
    int e = blockIdx.x * blockDim.x + threadIdx.x;
    if (e < N_EDGES) atomicAdd(&deg[dst[e]], 1);
}
__global__ __launch_bounds__(1024)
void scan_kernel(const int* __restrict__ deg, int* off, int* pos, int* dh) {
    __shared__ int ps[1024];
    __shared__ int dsh[DBINS];
    int t = threadIdx.x;
    if (t < DBINS) dsh[t] = 0;
    __syncthreads();
    const int CH = (N_NODES + 1023) / 1024;
    int b0 = t * CH, b1 = min(b0 + CH, N_NODES);
    int s = 0;
    for (int i = b0; i < b1; i++) {
        int d = deg[i];
        s += d;
        atomicAdd(&dsh[min(d, DBINS - 1)], 1);
    }
    ps[t] = s;
    __syncthreads();
    for (int o = 1; o < 1024; o <<= 1) {
        int u = (t >= o) ? ps[t - o] : 0;
        __syncthreads();
        ps[t] += u;
        __syncthreads();
    }
    int run = ps[t] - s;
    for (int i = b0; i < b1; i++) {
        off[i] = run; pos[i] = run; run += deg[i];
    }
    if (t == 1023) off[N_NODES] = ps[1023];
    if (t == 0) {
        int acc = 0;
        for (int b = 0; b < DBINS; b++) { int c = dsh[b]; dh[b] = acc; acc += c; }
    }
}
__global__ void scatter_perm_kernel(const int* __restrict__ src,
                                    const int* __restrict__ dst,
                                    const int* __restrict__ et,
                                    const int* __restrict__ deg,
                                    int* pos, int* dh,
                                    int2* edges, int* perm) {
    int e = blockIdx.x * blockDim.x + threadIdx.x;
    if (e < N_EDGES) {
        int p = atomicAdd(&pos[dst[e]], 1);
        edges[p] = make_int2(src[e], et[e]);
    }
    if (e < N_NODES) {
        int p = atomicAdd(&dh[min(deg[e], DBINS - 1)], 1);
        perm[p] = e;
    }
}

// ------------------------- 128-pt Stockham FFT (64 threads/row) --------------
__device__ __forceinline__ void fft128(float2* b0, float2* b1, int t, float sgn,
                                       const float2* __restrict__ tw) {
    float2* src = b0;
    float2* dst = b1;
#pragma unroll
    for (int s = 0; s < 7; s++) {
        int m = 1 << s;
        int j = t >> s;
        float2 w = tw[(s << 6) + j];
        w.y *= sgn;
        float2 c0 = src[t];
        float2 c1 = src[t + 64];
        float2 sum = make_float2(c0.x + c1.x, c0.y + c1.y);
        float2 d   = make_float2(c0.x - c1.x, c0.y - c1.y);
        int idx = (t & (m - 1)) | ((t >> s) << (s + 1));
        dst[idx]     = sum;
        dst[idx + m] = cmulf(d, w);
        float2* tmp = src; src = dst; dst = tmp;
        __syncthreads();
    }
}

// forward untangle -> fp16 spectrum row
__device__ __forceinline__ void untangle_store_h(
    float2* Z, __half2* Srow, int t, const float2* __restrict__ wt) {
#pragma unroll
    for (int u = 0; u < 2; u++) {
        int k = t + 64 * u;
        float2 Zk = Z[k];
        float2 Zm = Z[(128 - k) & 127];
        float2 Ze = make_float2(0.5f * (Zk.x + Zm.x), 0.5f * (Zk.y - Zm.y));
        float2 d  = make_float2(Zk.x - Zm.x, Zk.y + Zm.y);
        float2 Zo = make_float2(0.5f * d.y, -0.5f * d.x);
        float2 W  = wt[k];
        float2 H  = make_float2(Ze.x + W.x * Zo.x - W.y * Zo.y,
                                Ze.y + W.x * Zo.y + W.y * Zo.x);
        Srow[k] = __float22half2_rn(H);
    }
    if (t == 0) {
        float2 Z0 = Z[0];
        Srow[128] = __float22half2_rn(make_float2(Z0.x - Z0.y, 0.f));
    }
}

// ------------------------- gather + forward rfft (fused) ---------------------
__global__ __launch_bounds__(256)
void gather_fft_kernel(const int* __restrict__ x, const float* __restrict__ emb,
                       float* __restrict__ h, __half2* __restrict__ hH,
                       __half2* __restrict__ SH,
                       const float2* __restrict__ tw, const float2* __restrict__ wt) {
    __shared__ float2 buf[4][2][128];
    int g = threadIdx.x >> 6, t = threadIdx.x & 63;
    int row = (blockIdx.x << 2) + g;
    float4 v = reinterpret_cast<const float4*>(emb + (size_t)x[row] * DIM)[t];
    reinterpret_cast<float4*>(h + (size_t)row * DIM)[t] = v;
    __half2 p0 = __float22half2_rn(make_float2(v.x, v.y));
    __half2 p1 = __float22half2_rn(make_float2(v.z, v.w));
    *reinterpret_cast<uint2*>(hH + (size_t)row * HROW2 + 2 * t) =
        make_uint2(*reinterpret_cast<uint32_t*>(&p0), *reinterpret_cast<uint32_t*>(&p1));
    buf[g][0][2 * t]     = make_float2(v.x, v.y);
    buf[g][0][2 * t + 1] = make_float2(v.z, v.w);
    __syncthreads();
    fft128(buf[g][0], buf[g][1], t, -1.f, tw);
    untangle_store_h(buf[g][1], SH + (size_t)row * SROW2, t, wt);
}

// --------------- rel tables fft -> fp16 copies (both layers) -----------------
__global__ __launch_bounds__(256)
void rel_fft2_kernel(const float* __restrict__ rel1, const float* __restrict__ rel2,
                     __half2* __restrict__ rH1,  __half2* __restrict__ RSH1,
                     __half2* __restrict__ rH2,  __half2* __restrict__ RSH2,
                     const float2* __restrict__ tw, const float2* __restrict__ wt) {
    __shared__ float2 buf[4][2][128];
    int g = threadIdx.x >> 6, t = threadIdx.x & 63;
    int row = (blockIdx.x << 2) + g;
    const float* rel = (row < NRELS) ? rel1 : rel2;
    __half2* rH  = (row < NRELS) ? rH1  : rH2;
    __half2* RSH = (row < NRELS) ? RSH1 : RSH2;
    int r = (row < NRELS) ? row : row - NRELS;
    float4 v = reinterpret_cast<const float4*>(rel + (size_t)r * DIM)[t];
    __half2 p0 = __float22half2_rn(make_float2(v.x, v.y));
    __half2 p1 = __float22half2_rn(make_float2(v.z, v.w));
    *reinterpret_cast<uint2*>(rH + (size_t)r * HROW2 + 2 * t) =
        make_uint2(*reinterpret_cast<uint32_t*>(&p0), *reinterpret_cast<uint32_t*>(&p1));
    buf[g][0][2 * t]     = make_float2(v.x, v.y);
    buf[g][0][2 * t + 1] = make_float2(v.z, v.w);
    __syncthreads();
    fft128(buf[g][0], buf[g][1], t, -1.f, tw);
    untangle_store_h(buf[g][1], RSH + (size_t)r * SROW2, t, wt);
}

// --------------- aggregation + inverse rfft (WARP per node, perm rows) -------
// Writes HChi/HClo at PERM row p (contiguous per block range) for pipelining.
__global__ __launch_bounds__(256, 3)
void agg_inv_kernel(int blk0,
                    const int2* __restrict__ edges, const int* __restrict__ off,
                    const int* __restrict__ perm,
                    const __half2* __restrict__ hH,  const __half2* __restrict__ HSH,
                    const __half2* __restrict__ rH, const __half2* __restrict__ RSH,
                    const float* __restrict__ w, int wofs,
                    __nv_bfloat16* __restrict__ HChi,
                    __nv_bfloat16* __restrict__ HClo,
                    const float2* __restrict__ tw, const float2* __restrict__ wi) {
    __shared__ float2 buf[8][2][132];
    int wl = threadIdx.x >> 5, t = threadIdx.x & 31;
    int p = (((blk0 + blockIdx.x) << 3) + wl);
    if (p >= N_NODES) return;
    int v = perm[p];
    float w0 = w[wofs + 0], w1 = w[wofs + 1], w2 = w[wofs + 2];

    const uint4* hH4 = reinterpret_cast<const uint4*>(hH);
    const uint4* rH4 = reinterpret_cast<const uint4*>(rH);
    const uint4* HS4 = reinterpret_cast<const uint4*>(HSH);
    const uint4* RS4 = reinterpret_cast<const uint4*>(RSH);

    float T[8], Rs[8], F[8];
    float hv[8], rv[8], av[8], bv[8];

    cvt8(hH4[(size_t)v * 32 + t], hv);
    cvt8(rH4[t], rv);
#pragma unroll
    for (int i = 0; i < 8; i++) {
        Rs[i] = rv[i];
        T[i]  = hv[i] * fmaf(w0, rv[i], w1);
    }
    cvt8(HS4[(size_t)v * SROW4 + t], av);
    cvt8(RS4[t], bv);
#pragma unroll
    for (int i = 0; i < 4; i++) {
        F[2 * i]     = av[2 * i] * bv[2 * i] + av[2 * i + 1] * bv[2 * i + 1];
        F[2 * i + 1] = av[2 * i + 1] * bv[2 * i] - av[2 * i] * bv[2 * i + 1];
    }
    float2 Ft = make_float2(0.f, 0.f);
    if (t == 0) {
        float2 a = __half22float2(HSH[(size_t)v * SROW2 + 128]);
        float2 b = __half22float2(RSH[128]);
        Ft = make_float2(a.x * b.x + a.y * b.y, a.y * b.x - a.x * b.y);
    }

    int e = off[v], e1 = off[v + 1];
    for (; e + 1 < e1; e += 2) {
        int2 ea = edges[e];
        int2 eb = edges[e + 1];
        uint4 ha = hH4[(size_t)ea.x * 32 + t];
        uint4 ra = rH4[(size_t)ea.y * 32 + t];
        uint4 sa = HS4[(size_t)ea.x * SROW4 + t];
        uint4 ta = RS4[(size_t)ea.y * SROW4 + t];
        uint4 hb = hH4[(size_t)eb.x * 32 + t];
        uint4 rb = rH4[(size_t)eb.y * 32 + t];
        uint4 sb = HS4[(size_t)eb.x * SROW4 + t];
        uint4 tb = RS4[(size_t)eb.y * SROW4 + t];
        cvt8(ha, hv); cvt8(ra, rv);
#pragma unroll
        for (int i = 0; i < 8; i++) {
            Rs[i] += rv[i];
            T[i] = fmaf(hv[i], fmaf(w0, rv[i], w1), T[i]);
        }
        cvt8(sa, av); cvt8(ta, bv);
#pragma unroll
        for (int i = 0; i < 4; i++) {
            F[2 * i]     += av[2 * i] * bv[2 * i] + av[2 * i + 1] * bv[2 * i + 1];
            F[2 * i + 1] += av[2 * i + 1] * bv[2 * i] - av[2 * i] * bv[2 * i + 1];
        }
        cvt8(hb, hv); cvt8(rb, rv);
#pragma unroll
        for (int i = 0; i < 8; i++) {
            Rs[i] += rv[i];
            T[i] = fmaf(hv[i], fmaf(w0, rv[i], w1), T[i]);
        }
        cvt8(sb, av); cvt8(tb, bv);
#pragma unroll
        for (int i = 0; i < 4; i++) {
            F[2 * i]     += av[2 * i] * bv[2 * i] + av[2 * i + 1] * bv[2 * i + 1];
            F[2 * i + 1] += av[2 * i + 1] * bv[2 * i] - av[2 * i] * bv[2 * i + 1];
        }
        if (t == 0) {
            float2 a0 = __half22float2(HSH[(size_t)ea.x * SROW2 + 128]);
            float2 b0 = __half22float2(RSH[(size_t)ea.y * SROW2 + 128]);
            float2 a1 = __half22float2(HSH[(size_t)eb.x * SROW2 + 128]);
            float2 b1 = __half22float2(RSH[(size_t)eb.y * SROW2 + 128]);
            Ft.x += a0.x * b0.x + a0.y * b0.y + a1.x * b1.x + a1.y * b1.y;
            Ft.y += a0.y * b0.x - a0.x * b0.y + a1.y * b1.x - a1.x * b1.y;
        }
    }
    if (e < e1) {
        int2 ed = edges[e];
        uint4 ha = hH4[(size_t)ed.x * 32 + t];
        uint4 ra = rH4[(size_t)ed.y * 32 + t];
        uint4 sa = HS4[(size_t)ed.x * SROW4 + t];
        uint4 ta = RS4[(size_t)ed.y * SROW4 + t];
        cvt8(ha, hv); cvt8(ra, rv);
#pragma unroll
        for (int i = 0; i < 8; i++) {
            Rs[i] += rv[i];
            T[i] = fmaf(hv[i], fmaf(w0, rv[i], w1), T[i]);
        }
        cvt8(sa, av); cvt8(ta, bv);
#pragma unroll
        for (int i = 0; i < 4; i++) {
            F[2 * i]     += av[2 * i] * bv[2 * i] + av[2 * i + 1] * bv[2 * i + 1];
            F[2 * i + 1] += av[2 * i + 1] * bv[2 * i] - av[2 * i] * bv[2 * i + 1];
        }
        if (t == 0) {
            float2 a = __half22float2(HSH[(size_t)ed.x * SROW2 + 128]);
            float2 b = __half22float2(RSH[(size_t)ed.y * SROW2 + 128]);
            Ft.x += a.x * b.x + a.y * b.y;
            Ft.y += a.y * b.x - a.x * b.y;
        }
    }

    float2* sA = buf[wl][1];
#pragma unroll
    for (int i = 0; i < 4; i++)
        sA[4 * t + i] = make_float2(w2 * F[2 * i], w2 * F[2 * i + 1]);
    if (t == 0) sA[128] = make_float2(w2 * Ft.x, w2 * Ft.y);
    __syncwarp();

    float2* pk = buf[wl][0];
#pragma unroll
    for (int u = 0; u < 4; u++) {
        int k = t + 32 * u;
        float2 Ak = sA[k], Am = sA[128 - k];
        float2 Ze = make_float2(0.5f * (Ak.x + Am.x), 0.5f * (Ak.y - Am.y));
        float2 hd = make_float2(0.5f * (Ak.x - Am.x), 0.5f * (Ak.y + Am.y));
        float2 Zo = cmulf(wi[k], hd);
        pk[k] = make_float2(Ze.x - Zo.y, Ze.y + Zo.x);
    }
    __syncwarp();

    float2* src = buf[wl][0];
    float2* dst = buf[wl][1];
#pragma unroll
    for (int s = 0; s < 7; s++) {
        int m = 1 << s;
#pragma unroll
        for (int u = 0; u < 2; u++) {
            int tt = t + 32 * u;
            float2 wv = tw[(s << 6) + (tt >> s)];
            float2 c0 = src[tt];
            float2 c1 = src[tt + 64];
            float2 sum = make_float2(c0.x + c1.x, c0.y + c1.y);
            float2 d   = make_float2(c0.x - c1.x, c0.y - c1.y);
            int idx = (tt & (m - 1)) | ((tt >> s) << (s + 1));
            dst[idx]     = sum;
            dst[idx + m] = cmulf(d, wv);
        }
        float2* tmp = src; src = dst; dst = tmp;
        __syncwarp();
    }

    const float inv = 1.f / 128.f;
    float o[8];
#pragma unroll
    for (int i = 0; i < 4; i++) {
        float2 z = src[4 * t + i];
        o[2 * i]     = fmaf(w1, Rs[2 * i],     T[2 * i])     + z.x * inv;
        o[2 * i + 1] = fmaf(w1, Rs[2 * i + 1], T[2 * i + 1]) + z.y * inv;
    }
    __nv_bfloat16 hi8[8], lo8[8];
#pragma unroll
    for (int j = 0; j < 8; j++) {
        hi8[j] = __float2bfloat16(o[j]);
        lo8[j] = __float2bfloat16(o[j] - __bfloat162float(hi8[j]));
    }
    reinterpret_cast<uint4*>(HChi + (size_t)p * DIM)[t] = *reinterpret_cast<uint4*>(hi8);
    reinterpret_cast<uint4*>(HClo + (size_t)p * DIM)[t] = *reinterpret_cast<uint4*>(lo8);
}

// --------- LN + ReLU on perm-order Z rows; un-permutes on output -------------
template<bool DO_FFT>
__global__ __launch_bounds__(256)
void epilogue_fft_kernel(int row_base,
                         const float* __restrict__ Z,
                         const int* __restrict__ perm,
                         const float* __restrict__ gamma,
                         const float* __restrict__ beta,
                         float* __restrict__ h_out,
                         __half2* __restrict__ hH,
                         __half2* __restrict__ SH,
                         const float2* __restrict__ tw,
                         const float2* __restrict__ wt) {
    __shared__ float2 buf[4][2][128];
    __shared__ float sred[4][2];
    int g = threadIdx.x >> 6, t = threadIdx.x & 63;
    int wsub = t >> 5;
    int p = row_base + (blockIdx.x << 2) + g;
    int v = perm[p];

    float4 z = reinterpret_cast<const float4*>(Z + (size_t)p * DIM)[t];
    float s = z.x + z.y + z.z + z.w;
#pragma unroll
    for (int ofs = 16; ofs; ofs >>= 1) s += __shfl_xor_sync(0xffffffffu, s, ofs);
    if ((t & 31) == 0) sred[g][wsub] = s;
    __syncthreads();
    float mu = (sred[g][0] + sred[g][1]) * (1.f / DIM);
    __syncthreads();
    float4 zc = make_float4(z.x - mu, z.y - mu, z.z - mu, z.w - mu);
    float vv = zc.x * zc.x + zc.y * zc.y + zc.z * zc.z + zc.w * zc.w;
#pragma unroll
    for (int ofs = 16; ofs; ofs >>= 1) vv += __shfl_xor_sync(0xffffffffu, vv, ofs);
    if ((t & 31) == 0) sred[g][wsub] = vv;
    __syncthreads();
    float rstd = rsqrtf((sred[g][0] + sred[g][1]) * (1.f / DIM) + LN_EPS);
    float4 gm = reinterpret_cast<const float4*>(gamma)[t];
    float4 bt = reinterpret_cast<const float4*>(beta)[t];
    float4 y = make_float4(fmaxf(zc.x * rstd * gm.x + bt.x, 0.f),
                           fmaxf(zc.y * rstd * gm.y + bt.y, 0.f),
                           fmaxf(zc.z * rstd * gm.z + bt.z, 0.f),
                           fmaxf(zc.w * rstd * gm.w + bt.w, 0.f));
    reinterpret_cast<float4*>(h_out + (size_t)v * DIM)[t] = y;
    if (DO_FFT) {
        __half2 p0 = __float22half2_rn(make_float2(y.x, y.y));
        __half2 p1 = __float22half2_rn(make_float2(y.z, y.w));
        *reinterpret_cast<uint2*>(hH + (size_t)v * HROW2 + 2 * t) =
            make_uint2(*reinterpret_cast<uint32_t*>(&p0), *reinterpret_cast<uint32_t*>(&p1));
        buf[g][0][2 * t]     = make_float2(y.x, y.y);
        buf[g][0][2 * t + 1] = make_float2(y.z, y.w);
        __syncthreads();
        fft128(buf[g][0], buf[g][1], t, -1.f, tw);
        untangle_store_h(buf[g][1], SH + (size_t)v * SROW2, t, wt);
    }
}

// ------------------------- bf16x3 GEMM with pre-split operands ---------------
// RESID: residual gathered via perm (A rows are perm-ordered).
#define GBK 32
#define GPAD 8
#define GLDW (GBK + GPAD)

__device__ __forceinline__ void mma_bf16(float* d,
    uint32_t a0, uint32_t a1, uint32_t a2, uint32_t a3,
    uint32_t b0, uint32_t b1) {
    asm volatile(
        "mma.sync.aligned.m16n8k16.row.col.f32.bf16.bf16.f32 "
        "{%0,%1,%2,%3}, {%4,%5,%6,%7}, {%8,%9}, {%0,%1,%2,%3};"
        : "+f"(d[0]), "+f"(d[1]), "+f"(d[2]), "+f"(d[3])
        : "r"(a0), "r"(a1), "r"(a2), "r"(a3), "r"(b0), "r"(b1));
}

template<bool BIAS, bool RESID>
__global__ __launch_bounds__(256)
void bf16s_gemm(int row_off,
                const __nv_bfloat16* __restrict__ Ahi,
                const __nv_bfloat16* __restrict__ Alo,
                const __nv_bfloat16* __restrict__ Bhi,
                const __nv_bfloat16* __restrict__ Blo,
                float* __restrict__ C, const float* __restrict__ bias,
                const float* __restrict__ Hres, const int* __restrict__ perm,
                int M, int N, int K) {
    __shared__ __align__(16) __nv_bfloat16 Ah[128 * GLDW];
    __shared__ __align__(16) __nv_bfloat16 Al[128 * GLDW];
    __shared__ __align__(16) __nv_bfloat16 Bh[128 * GLDW];
    __shared__ __align__(16) __nv_bfloat16 Bl[128 * GLDW];

    int tid = threadIdx.x;
    int lane = tid & 31, wid = tid >> 5;
    int wm = wid & 1, wn = wid >> 1;
    int r = lane >> 2, cq = lane & 3;
    int bm = blockIdx.y * 128 + row_off, bn = blockIdx.x * 128;

    float acc[4][4][4];
#pragma unroll
    for (int a = 0; a < 4; a++)
#pragma unroll
        for (int b = 0; b < 4; b++)
#pragma unroll
            for (int c = 0; c < 4; c++) acc[a][b][c] = 0.f;

    int lrow[2], lcol[2];
#pragma unroll
    for (int j = 0; j < 2; j++) {
        int idx = tid + 256 * j;
        lrow[j] = idx >> 2; lcol[j] = (idx & 3) << 3;
    }

    uint4 rah[2], ral[2], rbh[2], rbl[2];
    const uint4 z4 = make_uint4(0, 0, 0, 0);

    auto load_tile = [&](int k0) {
#pragma unroll
        for (int j = 0; j < 2; j++) {
            size_t ao = (size_t)(bm + lrow[j]) * K + k0 + lcol[j];
            size_t bo = (size_t)(bn + lrow[j]) * K + k0 + lcol[j];
            bool av = (bm + lrow[j] < M), bv = (bn + lrow[j] < N);
            rah[j] = av ? *reinterpret_cast<const uint4*>(Ahi + ao) : z4;
            ral[j] = av ? *reinterpret_cast<const uint4*>(Alo + ao) : z4;
            rbh[j] = bv ? *reinterpret_cast<const uint4*>(Bhi + bo) : z4;
            rbl[j] = bv ? *reinterpret_cast<const uint4*>(Blo + bo) : z4;
        }
    };
    auto stage_tile = [&]() {
#pragma unroll
        for (int j = 0; j < 2; j++) {
            int so = lrow[j] * GLDW + lcol[j];
            *reinterpret_cast<uint4*>(&Ah[so]) = rah[j];
            *reinterpret_cast<uint4*>(&Al[so]) = ral[j];
            *reinterpret_cast<uint4*>(&Bh[so]) = rbh[j];
            *reinterpret_cast<uint4*>(&Bl[so]) = rbl[j];
        }
    };

    load_tile(0);
    for (int k0 = 0; k0 < K; k0 += GBK) {
        stage_tile();
        __syncthreads();
        if (k0 + GBK < K) load_tile(k0 + GBK);

#pragma unroll
        for (int ks = 0; ks < 2; ks++) {
            int kb = ks * 16 + cq * 2;
            uint32_t bhf[4][2], blf[4][2];
#pragma unroll
            for (int nf = 0; nf < 4; nf++) {
                int col = wn * 32 + nf * 8 + r;
                bhf[nf][0] = *reinterpret_cast<const uint32_t*>(&Bh[col * GLDW + kb]);
                bhf[nf][1] = *reinterpret_cast<const uint32_t*>(&Bh[col * GLDW + kb + 8]);
                blf[nf][0] = *reinterpret_cast<const uint32_t*>(&Bl[col * GLDW + kb]);
                blf[nf][1] = *reinterpret_cast<const uint32_t*>(&Bl[col * GLDW + kb + 8]);
            }
#pragma unroll
            for (int mf = 0; mf < 4; mf++) {
                int row = wm * 64 + mf * 16 + r;
                uint32_t a0 = *reinterpret_cast<const uint32_t*>(&Ah[row * GLDW + kb]);
                uint32_t a1 = *reinterpret_cast<const uint32_t*>(&Ah[(row + 8) * GLDW + kb]);
                uint32_t a2 = *reinterpret_cast<const uint32_t*>(&Ah[row * GLDW + kb + 8]);
                uint32_t a3 = *reinterpret_cast<const uint32_t*>(&Ah[(row + 8) * GLDW + kb + 8]);
                uint32_t l0 = *reinterpret_cast<const uint32_t*>(&Al[row * GLDW + kb]);
                uint32_t l1 = *reinterpret_cast<const uint32_t*>(&Al[(row + 8) * GLDW + kb]);
                uint32_t l2 = *reinterpret_cast<const uint32_t*>(&Al[row * GLDW + kb + 8]);
                uint32_t l3 = *reinterpret_cast<const uint32_t*>(&Al[(row + 8) * GLDW + kb + 8]);
#pragma unroll
                for (int nf = 0; nf < 4; nf++) {
                    mma_bf16(acc[mf][nf], a0, a1, a2, a3, bhf[nf][0], bhf[nf][1]);
                    mma_bf16(acc[mf][nf], a0, a1, a2, a3, blf[nf][0], blf[nf][1]);
                    mma_bf16(acc[mf][nf], l0, l1, l2, l3, bhf[nf][0], bhf[nf][1]);
                }
            }
        }
        __syncthreads();
    }

#pragma unroll
    for (int mf = 0; mf < 4; mf++) {
        int row0 = bm + wm * 64 + mf * 16 + r;
#pragma unroll
        for (int nf = 0; nf < 4; nf++) {
            int col = bn + wn * 32 + nf * 8 + cq * 2;
            float bx = 0.f, by = 0.f;
            if (BIAS) { bx = bias[col]; by = bias[col + 1]; }
            if (row0 < M) {
                float rx = bx, ry = by;
                if (RESID) {
                    int vres = perm[row0];
                    float2 hv = *reinterpret_cast<const float2*>(
                        Hres + (size_t)vres * N + col);
                    rx += hv.x; ry += hv.y;
                }
                *reinterpret_cast<float2*>(C + (size_t)row0 * N + col) =
                    make_float2(acc[mf][nf][0] + rx, acc[mf][nf][1] + ry);
            }
            if (row0 + 8 < M) {
                float rx = bx, ry = by;
                if (RESID) {
                    int vres = perm[row0 + 8];
                    float2 hv = *reinterpret_cast<const float2*>(
                        Hres + (size_t)vres * N + col);
                    rx += hv.x; ry += hv.y;
                }
                *reinterpret_cast<float2*>(C + (size_t)(row0 + 8) * N + col) =
                    make_float2(acc[mf][nf][2] + rx, acc[mf][nf][3] + ry);
            }
        }
    }
}

// ------------------------- launch --------------------------------------------
extern "C" void kernel_launch(void* const* d_in, const int* in_sizes, int n_in,
                              void* d_out, int out_size) {
    (void)in_sizes; (void)n_in; (void)out_size;
    const int*   x    = (const int*)  d_in[0];
    const int*   eidx = (const int*)  d_in[1];
    const int*   et   = (const int*)  d_in[2];
    const float* emb  = (const float*)d_in[3];
    const float* rel1 = (const float*)d_in[4];
    const float* Wn1  = (const float*)d_in[7];
    const float* bn1  = (const float*)d_in[8];
    const float* cw1  = (const float*)d_in[9];
    const float* gm1  = (const float*)d_in[10];
    const float* bt1  = (const float*)d_in[11];
    const float* rel2 = (const float*)d_in[12];
    const float* Wr2  = (const float*)d_in[13];
    const float* br2  = (const float*)d_in[14];
    const float* Wn2  = (const float*)d_in[15];
    const float* bn2  = (const float*)d_in[16];
    const float* cw2  = (const float*)d_in[17];
    const float* gm2  = (const float*)d_in[18];
    const float* bt2  = (const float*)d_in[19];

    float* out_h    = (float*)d_out;
    float* out_rels = out_h + (size_t)N_NODES * DIM;
    const int* src = eidx;
    const int* dst = eidx + N_EDGES;

    float *pH, *pZ, *pTw, *pWt, *pWi, *pW;
    __nv_bfloat16 *pHChi, *pHClo, *pWhi, *pWlo, *pR2hi, *pR2lo;
    __half2 *pHH, *pHSH, *pRH, *pRSH;
    int *pDeg, *pOff, *pPos, *pDh, *pPerm;
    int2* pEdges;
    cudaGetSymbolAddress((void**)&pH,    g_h);
    cudaGetSymbolAddress((void**)&pZ,    g_Z);
    cudaGetSymbolAddress((void**)&pHChi, g_HChi);
    cudaGetSymbolAddress((void**)&pHClo, g_HClo);
    cudaGetSymbolAddress((void**)&pWhi,  g_Whi);
    cudaGetSymbolAddress((void**)&pWlo,  g_Wlo);
    cudaGetSymbolAddress((void**)&pR2hi, g_R2hi);
    cudaGetSymbolAddress((void**)&pR2lo, g_R2lo);
    cudaGetSymbolAddress((void**)&pHH,   g_hH);
    cudaGetSymbolAddress((void**)&pHSH,  g_HSH);
    cudaGetSymbolAddress((void**)&pRH,   g_rH);
    cudaGetSymbolAddress((void**)&pRSH,  g_RSH);
    cudaGetSymbolAddress((void**)&pTw,   g_tw);
    cudaGetSymbolAddress((void**)&pWt,   g_wt);
    cudaGetSymbolAddress((void**)&pWi,   g_wi);
    cudaGetSymbolAddress((void**)&pW,    g_w);
    cudaGetSymbolAddress((void**)&pDeg,  g_deg);
    cudaGetSymbolAddress((void**)&pOff,  g_off);
    cudaGetSymbolAddress((void**)&pPos,  g_pos);
    cudaGetSymbolAddress((void**)&pDh,   g_dh);
    cudaGetSymbolAddress((void**)&pPerm, g_perm);
    cudaGetSymbolAddress((void**)&pEdges, g_edges);

    const float2* tw = (const float2*)pTw;
    const float2* wt = (const float2*)pWt;
    const float2* wi = (const float2*)pWi;
    __half2* pRH1  = pRH;
    __half2* pRH2  = pRH  + (size_t)NRELS * HROW2;
    __half2* pRSH1 = pRSH;
    __half2* pRSH2 = pRSH + (size_t)NRELS * SROW2;

    // handle lifecycle (net-zero on the capture call; work identical per call)
    static cudaStream_t s1 = nullptr, s2 = nullptr;
    static cudaEvent_t evSetup = nullptr, evSort = nullptr, evRel = nullptr,
                       evTail = nullptr, evAggA[2] = {nullptr, nullptr},
                       evChunkA[2] = {nullptr, nullptr};
    if (s1) cudaStreamDestroy(s1);
    if (s2) cudaStreamDestroy(s2);
    if (evSetup) cudaEventDestroy(evSetup);
    if (evSort)  cudaEventDestroy(evSort);
    if (evRel)   cudaEventDestroy(evRel);
    if (evTail)  cudaEventDestroy(evTail);
    for (int L = 0; L < 2; L++) {
        if (evAggA[L])   cudaEventDestroy(evAggA[L]);
        if (evChunkA[L]) cudaEventDestroy(evChunkA[L]);
    }
    cudaStreamCreateWithFlags(&s1, cudaStreamNonBlocking);
    cudaStreamCreateWithFlags(&s2, cudaStreamNonBlocking);
    cudaEventCreateWithFlags(&evSetup, cudaEventDisableTiming);
    cudaEventCreateWithFlags(&evSort,  cudaEventDisableTiming);
    cudaEventCreateWithFlags(&evRel,   cudaEventDisableTiming);
    cudaEventCreateWithFlags(&evTail,  cudaEventDisableTiming);
    for (int L = 0; L < 2; L++) {
        cudaEventCreateWithFlags(&evAggA[L],   cudaEventDisableTiming);
        cudaEventCreateWithFlags(&evChunkA[L], cudaEventDisableTiming);
    }

    // s0: setup; fork point
    setup_kernel<<<(N_NODES + 255) / 256, 256>>>(pTw, pWt, pWi, cw1, cw2, pW, pDeg);
    cudaEventRecord(evSetup, 0);

    // s1: edge sort chain
    cudaStreamWaitEvent(s1, evSetup, 0);
    hist_kernel<<<(N_EDGES + 255) / 256, 256, 0, s1>>>(dst, pDeg);
    scan_kernel<<<1, 1024, 0, s1>>>(pDeg, pOff, pPos, pDh);
    scatter_perm_kernel<<<(N_EDGES + 255) / 256, 256, 0, s1>>>(
        src, dst, et, pDeg, pPos, pDh, pEdges, pPerm);
    cudaEventRecord(evSort, s1);

    // s2: splits -> rels GEMM -> rel FFTs (forked before first launch)
    cudaStreamWaitEvent(s2, evSetup, 0);
    const int SPLIT_N = 3 * (DIM * DIM / 4) + NRELS * DIM / 4;
    split_all_kernel<<<(SPLIT_N + 255) / 256, 256, 0, s2>>>(
        Wn1, Wn2, Wr2, rel2, pWhi, pWlo, pR2hi, pR2lo);
    bf16s_gemm<true, false><<<dim3(2, (NRELS + 127) / 128), 256, 0, s2>>>(
        0, pR2hi, pR2lo, pWhi + 2 * DIM * DIM, pWlo + 2 * DIM * DIM,
        out_rels, br2, nullptr, nullptr, NRELS, DIM, DIM);
    rel_fft2_kernel<<<2 * NRELS / 4, 256, 0, s2>>>(
        rel1, rel2, pRH1, pRSH1, pRH2, pRSH2, tw, wt);
    cudaEventRecord(evRel, s2);
    cudaEventRecord(evTail, s2);

    // s0: node gather + forward fft
    gather_fft_kernel<<<N_NODES / 4, 256>>>(x, emb, pH, pHH, pHSH, tw, wt);

    // join
    cudaStreamWaitEvent(0, evSort, 0);
    cudaStreamWaitEvent(0, evRel, 0);

    for (int L = 0; L < 2; L++) {
        const float* bn = (L == 0) ? bn1 : bn2;
        const float* gm = (L == 0) ? gm1 : gm2;
        const float* bt = (L == 0) ? bt1 : bt2;
        __half2* rH  = (L == 0) ? pRH1  : pRH2;
        __half2* RSH = (L == 0) ? pRSH1 : pRSH2;
        const __nv_bfloat16* Whi = pWhi + (size_t)L * DIM * DIM;
        const __nv_bfloat16* Wlo = pWlo + (size_t)L * DIM * DIM;
        float* hout = (L == 0) ? pH : out_h;

        // s0: agg chunk A, then chunk B
        agg_inv_kernel<<<AGG_BLKS_A, 256>>>(0, pEdges, pOff, pPerm, pHH, pHSH,
                                            rH, RSH, pW, 3 * L, pHChi, pHClo,
                                            tw, wi);
        cudaEventRecord(evAggA[L], 0);
        agg_inv_kernel<<<AGG_BLKS_B, 256>>>(AGG_BLKS_A, pEdges, pOff, pPerm,
                                            pHH, pHSH, rH, RSH, pW, 3 * L,
                                            pHChi, pHClo, tw, wi);

        // s1: chunk A gemm+epilogue, overlapped with agg chunk B
        cudaStreamWaitEvent(s1, evAggA[L], 0);
        bf16s_gemm<true, true><<<dim3(2, ROWS_A / 128), 256, 0, s1>>>(
            0, pHChi, pHClo, Whi, Wlo, pZ, bn, pH, pPerm, N_NODES, DIM, DIM);
        if (L == 0)
            epilogue_fft_kernel<true><<<EPI_BLKS_A, 256, 0, s1>>>(
                0, pZ, pPerm, gm, bt, hout, pHH, pHSH, tw, wt);
        else
            epilogue_fft_kernel<false><<<EPI_BLKS_A, 256, 0, s1>>>(
                0, pZ, pPerm, gm, bt, hout, nullptr, nullptr, tw, wt);
        cudaEventRecord(evChunkA[L], s1);

        // s0: chunk B gemm+epilogue
        bf16s_gemm<true, true><<<dim3(2, (N_NODES - ROWS_A + 127) / 128), 256>>>(
            ROWS_A, pHChi, pHClo, Whi, Wlo, pZ, bn, pH, pPerm, N_NODES, DIM, DIM);
        if (L == 0)
            epilogue_fft_kernel<true><<<EPI_BLKS_B, 256>>>(
                ROWS_A, pZ, pPerm, gm, bt, hout, pHH, pHSH, tw, wt);
        else
            epilogue_fft_kernel<false><<<EPI_BLKS_B, 256>>>(
                ROWS_A, pZ, pPerm, gm, bt, hout, nullptr, nullptr, tw, wt);

        // layer barrier: next layer's agg (or graph end) needs chunk A done
        cudaStreamWaitEvent(0, evChunkA[L], 0);
    }

    // ensure the s2 chain (incl. rels GEMM) completes within the graph
    cudaStreamWaitEvent(0, evTail, 0);
}